// round 1
// baseline (speedup 1.0000x reference)
#include <cuda_runtime.h>
#include <cuda_bf16.h>
#include <math.h>

#define Ndim 1024
#define Mdim 4096
#define D0 1024
#define D1 512
#define Hdim 512
#define Edim 64

// ---------------- scratch (device globals; no allocation allowed) ----------------
__device__ float g_h_tar[Ndim*Hdim];
__device__ float g_h_mask[Ndim*Hdim];
__device__ float g_h_nei0[Mdim*Hdim];
__device__ float g_h_nei1[Mdim*Hdim];
__device__ float g_h_agg[Ndim*Hdim];
__device__ float g_t[Ndim*Hdim];
__device__ float g_views0[Ndim*Hdim];
__device__ float g_views1[Ndim*Hdim];
__device__ float g_masks0[Ndim*Hdim];
__device__ float g_masks1[Ndim*Hdim];
__device__ float g_mean_adj[Ndim*Ndim];
__device__ float g_xw[Ndim*Edim];
__device__ float g_h1[Ndim*Edim];
__device__ float g_hw[Ndim*Edim];
__device__ float g_zcoarse[Ndim*Edim];
__device__ float g_hs[4*Ndim*Edim];
__device__ float g_epart[16];
__device__ float g_beta[4];
__device__ float g_zfine[Ndim*Edim];
__device__ float g_zc[Ndim*Edim];
__device__ float g_zf[Ndim*Edim];
__device__ float g_Uf[Ndim*16];
__device__ float g_Uc[Ndim*16];
__device__ float g_diag[Ndim];
__device__ float g_part[64*Ndim];   // per j-tile partial denoms

__device__ __forceinline__ float eluf(float x){ return x > 0.f ? x : expm1f(x); }
__device__ __forceinline__ float fast_tanh(float x){
    x = fminf(fmaxf(x, -20.f), 20.f);
    float e = __expf(2.f*x);
    return (e - 1.f) / (e + 1.f);
}

// ---------------- dense GEMM: C = act(A[M,K] @ B[K,N] + bias) ----------------
// 64x64 block tile, BK=16, 256 threads, 4x4 per thread. Requires M%64==0, N%64==0, K%16==0.
__global__ __launch_bounds__(256) void gemm_act_kernel(
    const float* __restrict__ A, const float* __restrict__ B,
    const float* __restrict__ bias, float* __restrict__ C,
    int Md, int Nd, int Kd, int act)
{
    __shared__ float As[16][68];
    __shared__ float Bs[16][68];
    const int tid = threadIdx.x;
    const int bm = blockIdx.y * 64;
    const int bn = blockIdx.x * 64;
    const int tr = tid >> 4;
    const int tc = tid & 15;
    const int ar = tid >> 2;
    const int ac = (tid & 3) << 2;
    const int br = tid >> 4;
    const int bc = (tid & 15) << 2;
    float acc[4][4] = {};
    const float* Aptr = A + (size_t)(bm + ar) * Kd + ac;
    const float* Bptr = B + (size_t)br * Nd + bn + bc;
    for (int k0 = 0; k0 < Kd; k0 += 16) {
        float4 av = *(const float4*)(Aptr + k0);
        As[ac+0][ar] = av.x; As[ac+1][ar] = av.y;
        As[ac+2][ar] = av.z; As[ac+3][ar] = av.w;
        float4 bv = *(const float4*)(Bptr + (size_t)k0 * Nd);
        *(float4*)&Bs[br][bc] = bv;
        __syncthreads();
        #pragma unroll
        for (int kk = 0; kk < 16; kk++) {
            float a0 = As[kk][tr*4+0], a1 = As[kk][tr*4+1];
            float a2 = As[kk][tr*4+2], a3 = As[kk][tr*4+3];
            float b0 = Bs[kk][tc*4+0], b1 = Bs[kk][tc*4+1];
            float b2 = Bs[kk][tc*4+2], b3 = Bs[kk][tc*4+3];
            acc[0][0] += a0*b0; acc[0][1] += a0*b1; acc[0][2] += a0*b2; acc[0][3] += a0*b3;
            acc[1][0] += a1*b0; acc[1][1] += a1*b1; acc[1][2] += a1*b2; acc[1][3] += a1*b3;
            acc[2][0] += a2*b0; acc[2][1] += a2*b1; acc[2][2] += a2*b2; acc[2][3] += a2*b3;
            acc[3][0] += a3*b0; acc[3][1] += a3*b1; acc[3][2] += a3*b2; acc[3][3] += a3*b3;
        }
        __syncthreads();
    }
    #pragma unroll
    for (int i = 0; i < 4; i++) {
        int row = bm + tr*4 + i;
        #pragma unroll
        for (int j = 0; j < 4; j++) {
            int col = bn + tc*4 + j;
            float v = acc[i][j];
            if (bias) v += bias[col];
            if (act == 1) v = eluf(v);
            else if (act == 2) v = fmaxf(v, 0.f);
            else if (act == 3) v = tanhf(v);
            C[(size_t)row * Nd + col] = v;
        }
    }
}

// ---------------- sparse row-scan SpMM: Y[row,:] = act( norm * sum_j A[row,j]*X[j,:] + bias ) ----
// One block per row. Deterministic compaction via per-thread chunk + serial prefix.
__global__ void spmm_scan_kernel(
    const float* __restrict__ A, const float* __restrict__ X,
    const float* __restrict__ bias, float* __restrict__ Y,
    int K, int E, int act, int norm)
{
    __shared__ int   s_idx[512];
    __shared__ float s_val[512];
    __shared__ int   s_cnt[257];
    const int row = blockIdx.x;
    const int tid = threadIdx.x;
    const int nt  = blockDim.x;
    const int chunk = K / nt;
    const float* arow = A + (size_t)row * K;
    const int c0 = tid * chunk;
    int cnt = 0;
    for (int j = 0; j < chunk; j++) if (arow[c0 + j] != 0.f) cnt++;
    s_cnt[tid] = cnt;
    __syncthreads();
    if (tid == 0) {
        int run = 0;
        for (int t = 0; t < nt; t++) { int c = s_cnt[t]; s_cnt[t] = run; run += c; }
        s_cnt[nt] = run;
    }
    __syncthreads();
    int off = s_cnt[tid];
    for (int j = 0; j < chunk; j++) {
        float a = arow[c0 + j];
        if (a != 0.f) { if (off < 512) { s_idx[off] = c0 + j; s_val[off] = a; } off++; }
    }
    __syncthreads();
    const int total = min(s_cnt[nt], 512);
    float inv = 1.f;
    if (norm) inv = 1.f / fmaxf((float)s_cnt[nt], 1.f);
    for (int e = tid; e < E; e += nt) {
        float acc = 0.f;
        for (int t = 0; t < total; t++) acc += s_val[t] * X[(size_t)s_idx[t] * E + e];
        acc *= inv;
        if (bias) acc += bias[e];
        if (act == 2) acc = fmaxf(acc, 0.f);
        Y[(size_t)row * E + e] = acc;
    }
}

// ---------------- elementwise helpers ----------------
__global__ void mean_adj_kernel(const float* __restrict__ a0, const float* __restrict__ a1,
                                float* __restrict__ out, int n)
{
    int i = blockIdx.x * blockDim.x + threadIdx.x;
    if (i < n) out[i] = 0.5f * (a0[i] + a1[i]);
}

__global__ void vm_kernel(const float* __restrict__ h_tar, const float* __restrict__ h_mask,
                          const float* __restrict__ t,
                          float* __restrict__ views, float* __restrict__ masks, int n)
{
    int i = blockIdx.x * blockDim.x + threadIdx.x;
    if (i < n) {
        float tv = t[i];
        views[i] = eluf(h_tar[i] + tv);
        masks[i] = eluf(h_mask[i] + tv);
    }
}

// warp-per-row L2 normalize for [rows, 64]
__global__ void l2norm_kernel(float* __restrict__ X, int rows)
{
    int w = (blockIdx.x * blockDim.x + threadIdx.x) >> 5;
    int lane = threadIdx.x & 31;
    if (w >= rows) return;
    float* r = X + (size_t)w * 64;
    float a = r[lane], b = r[lane + 32];
    float s = a*a + b*b;
    #pragma unroll
    for (int off = 16; off > 0; off >>= 1) s += __shfl_xor_sync(0xffffffffu, s, off);
    float nrm = fmaxf(sqrtf(s), 1e-12f);
    r[lane] = a / nrm; r[lane + 32] = b / nrm;
}

// semantic attention partials: grid (4 chunks, 4 views), block 256, one n per thread
__global__ __launch_bounds__(256) void att_kernel(
    const float* __restrict__ hs, const float* __restrict__ att_w,
    const float* __restrict__ att_b, const float* __restrict__ att_vec,
    float* __restrict__ epart)
{
    __shared__ float w_s[64*64];
    __shared__ float b_s[64];
    __shared__ float v_s[64];
    __shared__ float red[256];
    const int tid = threadIdx.x;
    for (int i = tid; i < 64*64; i += 256) w_s[i] = att_w[i];
    if (tid < 64) { b_s[tid] = att_b[tid]; v_s[tid] = att_vec[tid]; }
    __syncthreads();
    const int v = blockIdx.y;
    const int n = blockIdx.x * 256 + tid;
    const float* row = hs + ((size_t)v * Ndim + n) * 64;
    float r[64];
    #pragma unroll
    for (int f = 0; f < 64; f++) r[f] = row[f];
    float s = 0.f;
    for (int e = 0; e < 64; e++) {
        float acc = b_s[e];
        #pragma unroll
        for (int f = 0; f < 64; f++) acc += r[f] * w_s[f*64 + e];
        s += v_s[e] * tanhf(acc);
    }
    red[tid] = s;
    __syncthreads();
    for (int st = 128; st > 0; st >>= 1) {
        if (tid < st) red[tid] += red[tid + st];
        __syncthreads();
    }
    if (tid == 0) epart[v*4 + blockIdx.x] = red[0];
}

__global__ void beta_kernel(const float* __restrict__ epart, float* __restrict__ beta)
{
    float e[4];
    float m = -1e30f;
    for (int v = 0; v < 4; v++) {
        e[v] = (epart[v*4+0] + epart[v*4+1] + epart[v*4+2] + epart[v*4+3]) / (float)Ndim;
        m = fmaxf(m, e[v]);
    }
    float s = 0.f;
    for (int v = 0; v < 4; v++) { float b = expf(e[v] - m); beta[v] = b; s += b; }
    for (int v = 0; v < 4; v++) beta[v] /= s;
}

__global__ void zfine_kernel(const float* __restrict__ hs, const float* __restrict__ beta,
                             float* __restrict__ zfine, int n)
{
    int i = blockIdx.x * blockDim.x + threadIdx.x;
    if (i < n) {
        float s = beta[0]*hs[i] + beta[1]*hs[(size_t)Ndim*Edim + i]
                + beta[2]*hs[(size_t)2*Ndim*Edim + i] + beta[3]*hs[(size_t)3*Ndim*Edim + i];
        zfine[i] = s;
    }
}

// Uf = zf@mlp1 + b1 ; Uc = zc@mlp1    (grid N/16, block 256 = 16n x 16k)
__global__ __launch_bounds__(256) void u_kernel(
    const float* __restrict__ zf, const float* __restrict__ zc,
    const float* __restrict__ mlp1_w, const float* __restrict__ mlp1_b,
    float* __restrict__ Uf, float* __restrict__ Uc)
{
    __shared__ float w_s[64*16];
    const int tid = threadIdx.x;
    for (int i = tid; i < 64*16; i += 256) w_s[i] = mlp1_w[i];
    __syncthreads();
    const int n = blockIdx.x * 16 + (tid >> 4);
    const int k = tid & 15;
    const float* zfr = zf + (size_t)n * 64;
    const float* zcr = zc + (size_t)n * 64;
    float af = 0.f, acr = 0.f;
    #pragma unroll
    for (int e = 0; e < 64; e++) {
        float w = w_s[e*16 + k];
        af  += zfr[e] * w;
        acr += zcr[e] * w;
    }
    Uf[(size_t)n*16 + k] = af + mlp1_b[k];
    Uc[(size_t)n*16 + k] = acr;
}

__global__ void diag_kernel(const float* __restrict__ zf, const float* __restrict__ zc,
                            float* __restrict__ diag)
{
    int w = (blockIdx.x * blockDim.x + threadIdx.x) >> 5;
    int lane = threadIdx.x & 31;
    if (w >= Ndim) return;
    const float* a = zf + (size_t)w * 64;
    const float* b = zc + (size_t)w * 64;
    float s = a[lane]*b[lane] + a[lane+32]*b[lane+32];
    #pragma unroll
    for (int off = 16; off > 0; off >>= 1) s += __shfl_xor_sync(0xffffffffu, s, off);
    if (lane == 0) diag[w] = 2.f * s;   // logits = dot / TAU, TAU = 0.5
}

// pair kernel: grid (64 j-tiles, 64 i-tiles), block 256 = 16i x 16j.
// part[bj][i] = sum over tile-j of exp(2*dot(zf_i,zc_j)) * sigmoid(sum_k tanh(Uf_i+Uc_j)*m2 + b2)
__global__ __launch_bounds__(256) void pair_kernel(
    const float* __restrict__ zf, const float* __restrict__ zc,
    const float* __restrict__ Uf, const float* __restrict__ Uc,
    const float* __restrict__ mlp2_w, const float* __restrict__ mlp2_b,
    float* __restrict__ part)
{
    __shared__ float zf_s[16][68];
    __shared__ float zc_s[16][68];
    __shared__ float uc_s[16][17];
    __shared__ float m2_s[16];
    const int tid = threadIdx.x;
    const int bi = blockIdx.y * 16;
    const int bj = blockIdx.x * 16;
    const int lr = tid >> 4, lc = (tid & 15) << 2;
    *(float4*)&zf_s[lr][lc] = *(const float4*)(zf + (size_t)(bi + lr) * 64 + lc);
    *(float4*)&zc_s[lr][lc] = *(const float4*)(zc + (size_t)(bj + lr) * 64 + lc);
    uc_s[tid >> 4][tid & 15] = Uc[(size_t)(bj + (tid >> 4)) * 16 + (tid & 15)];
    if (tid < 16) m2_s[tid] = mlp2_w[tid];
    __syncthreads();
    const int ti = tid >> 4, tj = tid & 15;
    const int i = bi + ti;
    float uf[16];
    #pragma unroll
    for (int k = 0; k < 16; k++) uf[k] = Uf[(size_t)i*16 + k];
    float dot = 0.f;
    #pragma unroll
    for (int e = 0; e < 64; e++) dot += zf_s[ti][e] * zc_s[tj][e];
    float sacc = mlp2_b[0];
    #pragma unroll
    for (int k = 0; k < 16; k++) sacc += m2_s[k] * fast_tanh(uf[k] + uc_s[tj][k]);
    float w = 1.f / (1.f + __expf(-fminf(fmaxf(sacc, -30.f), 30.f)));
    float contrib = __expf(2.f * dot) * w;
    #pragma unroll
    for (int off = 8; off > 0; off >>= 1)
        contrib += __shfl_down_sync(0xffffffffu, contrib, off, 16);
    if (tj == 0) part[(size_t)blockIdx.x * Ndim + i] = contrib;
}

__global__ void loss_kernel(const float* __restrict__ part, const float* __restrict__ diag,
                            float* __restrict__ out)
{
    __shared__ float red[256];
    const int tid = threadIdx.x;
    float s = 0.f;
    for (int i = tid; i < Ndim; i += 256) {
        float d = 0.f;
        for (int b = 0; b < 64; b++) d += part[(size_t)b * Ndim + i];
        s += logf(d) - diag[i];
    }
    red[tid] = s;
    __syncthreads();
    for (int st = 128; st > 0; st >>= 1) {
        if (tid < st) red[tid] += red[tid + st];
        __syncthreads();
    }
    if (tid == 0) out[0] = red[0] / (float)Ndim;
}

// ---------------- host ----------------
static float* devptr(const void* sym) {
    void* p = nullptr;
    cudaGetSymbolAddress(&p, sym);
    return (float*)p;
}

static void run_gemm(const float* A, const float* B, const float* bias, float* C,
                     int Md, int Nd, int Kd, int act)
{
    dim3 grid(Nd / 64, Md / 64);
    gemm_act_kernel<<<grid, 256>>>(A, B, bias, C, Md, Nd, Kd, act);
}

static void run_gcn(const float* x, const float* adj, float* out,
                    const float* w1, const float* b1, const float* w2, const float* b2,
                    float* xw, float* h1, float* hw)
{
    run_gemm(x, w1, nullptr, xw, Ndim, Edim, Hdim, 0);
    spmm_scan_kernel<<<Ndim, 64>>>(adj, xw, b1, h1, Ndim, Edim, 2, 0);
    run_gemm(h1, w2, nullptr, hw, Ndim, Edim, Edim, 0);
    spmm_scan_kernel<<<Ndim, 64>>>(adj, hw, b2, out, Ndim, Edim, 0, 0);
}

extern "C" void kernel_launch(void* const* d_in, const int* in_sizes, int n_in,
                              void* d_out, int out_size)
{
    const float* feat0     = (const float*)d_in[0];
    const float* feat1     = (const float*)d_in[1];
    const float* feat2     = (const float*)d_in[2];
    const float* mask_feat = (const float*)d_in[3];
    const float* nei0      = (const float*)d_in[4];
    const float* nei1      = (const float*)d_in[5];
    const float* adj0      = (const float*)d_in[6];
    const float* adj1      = (const float*)d_in[7];
    const float* madj0     = (const float*)d_in[8];
    const float* madj1     = (const float*)d_in[9];
    const float* fc0_w     = (const float*)d_in[10];
    const float* fc0_b     = (const float*)d_in[11];
    const float* fc1_w     = (const float*)d_in[12];
    const float* fc1_b     = (const float*)d_in[13];
    const float* fc2_w     = (const float*)d_in[14];
    const float* fc2_b     = (const float*)d_in[15];
    const float* agg0_w    = (const float*)d_in[16];
    const float* agg1_w    = (const float*)d_in[17];
    const float* gcn_w1    = (const float*)d_in[18];
    const float* gcn_b1    = (const float*)d_in[19];
    const float* gcn_w2    = (const float*)d_in[20];
    const float* gcn_b2    = (const float*)d_in[21];
    const float* att_w     = (const float*)d_in[22];
    const float* att_b     = (const float*)d_in[23];
    const float* att_vec   = (const float*)d_in[24];
    const float* proj_w    = (const float*)d_in[25];
    const float* proj_b    = (const float*)d_in[26];
    const float* mlp1_w    = (const float*)d_in[27];
    const float* mlp1_b    = (const float*)d_in[28];
    const float* mlp2_w    = (const float*)d_in[29];
    const float* mlp2_b    = (const float*)d_in[30];

    float* h_tar  = devptr(g_h_tar);
    float* h_mask = devptr(g_h_mask);
    float* h_nei0 = devptr(g_h_nei0);
    float* h_nei1 = devptr(g_h_nei1);
    float* h_agg  = devptr(g_h_agg);
    float* tbuf   = devptr(g_t);
    float* views0 = devptr(g_views0);
    float* views1 = devptr(g_views1);
    float* masks0 = devptr(g_masks0);
    float* masks1 = devptr(g_masks1);
    float* meanA  = devptr(g_mean_adj);
    float* xw     = devptr(g_xw);
    float* h1buf  = devptr(g_h1);
    float* hwbuf  = devptr(g_hw);
    float* zco    = devptr(g_zcoarse);
    float* hs     = devptr(g_hs);
    float* epart  = devptr(g_epart);
    float* beta   = devptr(g_beta);
    float* zfine  = devptr(g_zfine);
    float* zc     = devptr(g_zc);
    float* zf     = devptr(g_zf);
    float* Uf     = devptr(g_Uf);
    float* Uc     = devptr(g_Uc);
    float* diag   = devptr(g_diag);
    float* part   = devptr(g_part);

    // ---- feature encoders ----
    run_gemm(feat0,     fc0_w, fc0_b, h_tar,  Ndim, Hdim, D0, 1);
    run_gemm(mask_feat, fc0_w, fc0_b, h_mask, Ndim, Hdim, D0, 1);
    run_gemm(feat1,     fc1_w, fc1_b, h_nei0, Mdim, Hdim, D1, 1);
    run_gemm(feat2,     fc2_w, fc2_b, h_nei1, Mdim, Hdim, D1, 1);

    // ---- neighbor aggregation + views/masks ----
    const int nh = Ndim * Hdim;
    spmm_scan_kernel<<<Ndim, 256>>>(nei0, h_nei0, nullptr, h_agg, Mdim, Hdim, 0, 1);
    run_gemm(h_agg, agg0_w, nullptr, tbuf, Ndim, Hdim, Hdim, 0);
    vm_kernel<<<(nh + 255)/256, 256>>>(h_tar, h_mask, tbuf, views0, masks0, nh);

    spmm_scan_kernel<<<Ndim, 256>>>(nei1, h_nei1, nullptr, h_agg, Mdim, Hdim, 0, 1);
    run_gemm(h_agg, agg1_w, nullptr, tbuf, Ndim, Hdim, Hdim, 0);
    vm_kernel<<<(nh + 255)/256, 256>>>(h_tar, h_mask, tbuf, views1, masks1, nh);

    // ---- GCNs ----
    mean_adj_kernel<<<(Ndim*Ndim + 255)/256, 256>>>(adj0, adj1, meanA, Ndim*Ndim);
    run_gcn(h_tar,  meanA, zco,                 gcn_w1, gcn_b1, gcn_w2, gcn_b2, xw, h1buf, hwbuf);
    run_gcn(views0, adj0,  hs + 0*Ndim*Edim,    gcn_w1, gcn_b1, gcn_w2, gcn_b2, xw, h1buf, hwbuf);
    run_gcn(masks0, madj0, hs + 1*Ndim*Edim,    gcn_w1, gcn_b1, gcn_w2, gcn_b2, xw, h1buf, hwbuf);
    run_gcn(views1, adj1,  hs + 2*Ndim*Edim,    gcn_w1, gcn_b1, gcn_w2, gcn_b2, xw, h1buf, hwbuf);
    run_gcn(masks1, madj1, hs + 3*Ndim*Edim,    gcn_w1, gcn_b1, gcn_w2, gcn_b2, xw, h1buf, hwbuf);

    // ---- l2norm views, semantic attention, z_fine ----
    l2norm_kernel<<<(4*Ndim)/8, 256>>>(hs, 4*Ndim);
    att_kernel<<<dim3(4,4), 256>>>(hs, att_w, att_b, att_vec, epart);
    beta_kernel<<<1, 1>>>(epart, beta);
    zfine_kernel<<<(Ndim*Edim + 255)/256, 256>>>(hs, beta, zfine, Ndim*Edim);

    // ---- projections ----
    run_gemm(zco,   proj_w, proj_b, zc, Ndim, Edim, Edim, 3);
    l2norm_kernel<<<Ndim/8, 256>>>(zc, Ndim);
    run_gemm(zfine, proj_w, proj_b, zf, Ndim, Edim, Edim, 3);
    l2norm_kernel<<<Ndim/8, 256>>>(zf, Ndim);

    // ---- weighted InfoNCE ----
    u_kernel<<<Ndim/16, 256>>>(zf, zc, mlp1_w, mlp1_b, Uf, Uc);
    diag_kernel<<<Ndim/8, 256>>>(zf, zc, diag);
    pair_kernel<<<dim3(64, 64), 256>>>(zf, zc, Uf, Uc, mlp2_w, mlp2_b, part);
    loss_kernel<<<1, 256>>>(part, diag, (float*)d_out);
}

// round 3
// speedup vs baseline: 1.5089x; 1.5089x over previous
#include <cuda_runtime.h>
#include <cuda_bf16.h>
#include <math.h>

#define Ndim 1024
#define Mdim 4096
#define D0 1024
#define D1 512
#define Hdim 512
#define Edim 64

typedef unsigned long long ull;

// ---------------- scratch (device globals; no allocation allowed) ----------------
__device__ float g_h_tar[Ndim*Hdim];
__device__ float g_h_mask[Ndim*Hdim];
__device__ float g_h_nei0[Mdim*Hdim];
__device__ float g_h_nei1[Mdim*Hdim];
__device__ float g_h_agg0[Ndim*Hdim];
__device__ float g_h_agg1[Ndim*Hdim];
__device__ float g_views0[Ndim*Hdim];
__device__ float g_views1[Ndim*Hdim];
__device__ float g_masks0[Ndim*Hdim];
__device__ float g_masks1[Ndim*Hdim];
__device__ float g_mean_adj[Ndim*Ndim];
__device__ float g_xw_all[5*Ndim*Edim];
__device__ float g_h1_all[5*Ndim*Edim];
__device__ float g_hw_all[5*Ndim*Edim];
__device__ float g_z_all[5*Ndim*Edim];   // slice0 = z_coarse, slices 1..4 = hs (l2norm'd in place)
__device__ float g_epart[16];
__device__ float g_beta[4];
__device__ float g_zfine[Ndim*Edim];
__device__ float g_z2[2*Ndim*Edim];      // slice0 = zc, slice1 = zf
__device__ float g_Uf[Ndim*16];
__device__ float g_Uc[Ndim*16];
__device__ float g_diag[Ndim];
__device__ float g_part[64*Ndim];

__device__ __forceinline__ float eluf(float x){ return x > 0.f ? x : expm1f(x); }
__device__ __forceinline__ float fast_tanh(float x){
    x = fminf(fmaxf(x, -20.f), 20.f);
    float e = __expf(2.f*x);
    return (e - 1.f) / (e + 1.f);
}
__device__ __forceinline__ ull dup2(float x){
    ull r; asm("mov.b64 %0, {%1, %1};" : "=l"(r) : "f"(x)); return r;
}
__device__ __forceinline__ ull fma2(ull a, ull b, ull c){
    ull d; asm("fma.rn.f32x2 %0, %1, %2, %3;" : "=l"(d) : "l"(a), "l"(b), "l"(c)); return d;
}
__device__ __forceinline__ void unpack2(ull v, float& lo, float& hi){
    asm("mov.b64 {%0, %1}, %2;" : "=f"(lo), "=f"(hi) : "l"(v));
}

// ================= big GEMM: segmented, f32x2, double-buffered =================
// BM = 16*TM, BN = 128, BK = 8, 256 threads, thread tile TM x 8.
// EPI: 1 = elu(v + bias); 2 = vm-fuse: C=elu(aux0+v), C2=elu(aux1+v); 3 = tanh(v+bias); 0 = raw.
struct Seg { const float* A; const float* W; const float* bias; float* C; float* C2; int K; int tileEnd; };
struct Segs { Seg s[4]; int nseg; };

template<int TM, int EPI>
__global__ __launch_bounds__(256) void gemm_big(
    Segs segs, int Nd, const float* __restrict__ aux0, const float* __restrict__ aux1)
{
    constexpr int BM = 16 * TM;
    __shared__ __align__(16) float As[2][8][BM];
    __shared__ __align__(16) float Bs[2][8][128];
    const int tid = threadIdx.x;
    const int by  = blockIdx.y;

    int si = 0, tileStart = 0;
    #pragma unroll
    for (int i = 0; i < 3; i++) {
        if (i < segs.nseg && by >= segs.s[i].tileEnd) { si = i + 1; tileStart = segs.s[i].tileEnd; }
    }
    const Seg sg = segs.s[si];
    const int K  = sg.K;
    const int bm = (by - tileStart) * BM;
    const int bn = blockIdx.x * 128;

    const int tx = tid & 15;        // 16 col groups of 8
    const int ty = tid >> 4;        // 16 row groups of TM

    // A loader indices
    int ar, akc;
    if (TM == 8) { ar = tid >> 1; akc = (tid & 1) * 4; }
    else         { ar = tid >> 2; akc = (tid & 3) * 2; }
    // B loader indices
    const int br = tid >> 5;               // 0..7
    const int bc = (tid & 31) * 4;         // 0..124

    const float* Ap = sg.A + (size_t)(bm + ar) * K + akc;
    const float* Bp = sg.W + (size_t)br * Nd + bn + bc;

    const int nk = K >> 3;

    // prologue: tile 0
    float4 aR4; float2 aR2; float4 bR;
    if (TM == 8) aR4 = *(const float4*)(Ap);
    else         aR2 = *(const float2*)(Ap);
    bR = *(const float4*)(Bp);
    if (TM == 8) {
        As[0][akc+0][ar] = aR4.x; As[0][akc+1][ar] = aR4.y;
        As[0][akc+2][ar] = aR4.z; As[0][akc+3][ar] = aR4.w;
    } else {
        As[0][akc+0][ar] = aR2.x; As[0][akc+1][ar] = aR2.y;
    }
    *(float4*)&Bs[0][br][bc] = bR;
    __syncthreads();

    ull acc[TM][4];
    #pragma unroll
    for (int i = 0; i < TM; i++)
        #pragma unroll
        for (int j = 0; j < 4; j++) acc[i][j] = 0ull;

    for (int t = 0; t < nk; t++) {
        const int cur = t & 1;
        const bool has = (t + 1 < nk);
        if (has) {
            const int k0 = (t + 1) * 8;
            if (TM == 8) aR4 = *(const float4*)(Ap + k0);
            else         aR2 = *(const float2*)(Ap + k0);
            bR = *(const float4*)(Bp + (size_t)k0 * Nd);
        }
        #pragma unroll
        for (int kk = 0; kk < 8; kk++) {
            ull a2[TM];
            if (TM == 8) {
                float4 av0 = *(const float4*)&As[cur][kk][ty*8];
                float4 av1 = *(const float4*)&As[cur][kk][ty*8+4];
                a2[0]=dup2(av0.x); a2[1]=dup2(av0.y); a2[2]=dup2(av0.z); a2[3]=dup2(av0.w);
                a2[4]=dup2(av1.x); a2[5]=dup2(av1.y); a2[6]=dup2(av1.z); a2[7]=dup2(av1.w);
            } else {
                float4 av0 = *(const float4*)&As[cur][kk][ty*4];
                a2[0]=dup2(av0.x); a2[1]=dup2(av0.y); a2[2]=dup2(av0.z); a2[3]=dup2(av0.w);
            }
            ulonglong2 bp0 = *(const ulonglong2*)&Bs[cur][kk][tx*8];
            ulonglong2 bp1 = *(const ulonglong2*)&Bs[cur][kk][tx*8+4];
            #pragma unroll
            for (int i = 0; i < TM; i++) {
                acc[i][0] = fma2(a2[i], bp0.x, acc[i][0]);
                acc[i][1] = fma2(a2[i], bp0.y, acc[i][1]);
                acc[i][2] = fma2(a2[i], bp1.x, acc[i][2]);
                acc[i][3] = fma2(a2[i], bp1.y, acc[i][3]);
            }
        }
        if (has) {
            const int nxt = cur ^ 1;
            if (TM == 8) {
                As[nxt][akc+0][ar] = aR4.x; As[nxt][akc+1][ar] = aR4.y;
                As[nxt][akc+2][ar] = aR4.z; As[nxt][akc+3][ar] = aR4.w;
            } else {
                As[nxt][akc+0][ar] = aR2.x; As[nxt][akc+1][ar] = aR2.y;
            }
            *(float4*)&Bs[nxt][br][bc] = bR;
            __syncthreads();
        }
    }

    // epilogue
    #pragma unroll
    for (int i = 0; i < TM; i++) {
        const int row = bm + ty * TM + i;
        const size_t base = (size_t)row * Nd + bn + tx * 8;
        #pragma unroll
        for (int j = 0; j < 4; j++) {
            float v0, v1; unpack2(acc[i][j], v0, v1);
            const int c = bn + tx * 8 + 2 * j;
            if (EPI == 1) {
                v0 = eluf(v0 + sg.bias[c]); v1 = eluf(v1 + sg.bias[c+1]);
                *(float2*)&sg.C[base + 2*j] = make_float2(v0, v1);
            } else if (EPI == 2) {
                float t0 = v0, t1 = v1;
                float2 w0 = make_float2(eluf(aux0[base+2*j] + t0), eluf(aux0[base+2*j+1] + t1));
                float2 m0 = make_float2(eluf(aux1[base+2*j] + t0), eluf(aux1[base+2*j+1] + t1));
                *(float2*)&sg.C[base + 2*j]  = w0;
                *(float2*)&sg.C2[base + 2*j] = m0;
            } else if (EPI == 3) {
                v0 = tanhf(v0 + sg.bias[c]); v1 = tanhf(v1 + sg.bias[c+1]);
                *(float2*)&sg.C[base + 2*j] = make_float2(v0, v1);
            } else {
                *(float2*)&sg.C[base + 2*j] = make_float2(v0, v1);
            }
        }
    }
}

// ================= small GEMM: N=64, batched over 5 inputs, f32x2 =================
// BM=32, BN=64, BK=16, 128 threads, thread tile 4x4. ACT: 0 none, 3 tanh. bias optional.
struct In5 { const float* p[5]; };

template<int ACT>
__global__ __launch_bounds__(128) void gemm_small(
    In5 ins, const float* __restrict__ W, const float* __restrict__ bias,
    float* __restrict__ out, int K, int tilesPer)
{
    __shared__ __align__(16) float As[16][32];
    __shared__ __align__(16) float Bs[16][64];
    const int tid = threadIdx.x;
    const int g  = blockIdx.x / tilesPer;
    const int tb = blockIdx.x % tilesPer;
    const float* A = ins.p[g] + (size_t)tb * 32 * K;
    float* C = out + ((size_t)g * tilesPer * 32 + tb * 32) * 64;

    const int tx = tid & 15;   // 16 col groups of 4
    const int ty = tid >> 4;   // 8 row groups of 4
    const int ar = tid >> 2, akc = (tid & 3) * 4;
    const int br = tid >> 4, bc = (tid & 15) * 4;

    ull acc[4][2];
    #pragma unroll
    for (int i = 0; i < 4; i++) { acc[i][0] = 0ull; acc[i][1] = 0ull; }

    for (int k0 = 0; k0 < K; k0 += 16) {
        float4 av  = *(const float4*)(A + (size_t)ar * K + k0 + akc);
        float4 bv0 = *(const float4*)(W + (size_t)(k0 + br) * 64 + bc);
        float4 bv1 = *(const float4*)(W + (size_t)(k0 + br + 8) * 64 + bc);
        __syncthreads();
        As[akc+0][ar] = av.x; As[akc+1][ar] = av.y; As[akc+2][ar] = av.z; As[akc+3][ar] = av.w;
        *(float4*)&Bs[br][bc]     = bv0;
        *(float4*)&Bs[br+8][bc]   = bv1;
        __syncthreads();
        #pragma unroll
        for (int kk = 0; kk < 16; kk++) {
            float4 av2 = *(const float4*)&As[kk][ty*4];
            ulonglong2 bp = *(const ulonglong2*)&Bs[kk][tx*4];
            ull a2[4] = {dup2(av2.x), dup2(av2.y), dup2(av2.z), dup2(av2.w)};
            #pragma unroll
            for (int i = 0; i < 4; i++) {
                acc[i][0] = fma2(a2[i], bp.x, acc[i][0]);
                acc[i][1] = fma2(a2[i], bp.y, acc[i][1]);
            }
        }
    }
    #pragma unroll
    for (int i = 0; i < 4; i++) {
        const int row = ty * 4 + i;
        #pragma unroll
        for (int j = 0; j < 2; j++) {
            float v0, v1; unpack2(acc[i][j], v0, v1);
            const int c = tx * 4 + 2 * j;
            if (bias) { v0 += bias[c]; v1 += bias[c+1]; }
            if (ACT == 3) { v0 = tanhf(v0); v1 = tanhf(v1); }
            *(float2*)&C[(size_t)row * 64 + c] = make_float2(v0, v1);
        }
    }
}

// ========== sparse row-scan SpMM for nei aggregation (mean over nnz) ==========
__global__ void spmm_scan_kernel(
    const float* __restrict__ A, const float* __restrict__ X,
    float* __restrict__ Y, int K, int E)
{
    __shared__ int   s_idx[512];
    __shared__ float s_val[512];
    __shared__ int   s_cnt[257];
    const int row = blockIdx.x;
    const int tid = threadIdx.x;
    const int nt  = blockDim.x;
    const int chunk = K / nt;
    const float* arow = A + (size_t)row * K;
    const int c0 = tid * chunk;
    int cnt = 0;
    for (int j = 0; j < chunk; j++) if (arow[c0 + j] != 0.f) cnt++;
    s_cnt[tid] = cnt;
    __syncthreads();
    if (tid == 0) {
        int run = 0;
        for (int t = 0; t < nt; t++) { int c = s_cnt[t]; s_cnt[t] = run; run += c; }
        s_cnt[nt] = run;
    }
    __syncthreads();
    int off = s_cnt[tid];
    for (int j = 0; j < chunk; j++) {
        float a = arow[c0 + j];
        if (a != 0.f) { if (off < 512) { s_idx[off] = c0 + j; s_val[off] = a; } off++; }
    }
    __syncthreads();
    const int total = min(s_cnt[nt], 512);
    const float inv = 1.f / fmaxf((float)s_cnt[nt], 1.f);
    for (int e = tid; e < E; e += nt) {
        float acc = 0.f;
        for (int t = 0; t < total; t++) acc += s_val[t] * X[(size_t)s_idx[t] * E + e];
        Y[(size_t)row * E + e] = acc * inv;
    }
}

// ========== batched GCN SpMM: grid (Ndim, 5), per-g adjacency ==========
struct Adj5 { const float* a[5]; };
__global__ void gcn_spmm_kernel(
    Adj5 adjs, const float* __restrict__ Xall, const float* __restrict__ bias,
    float* __restrict__ Yall, int relu)
{
    __shared__ int   s_idx[512];
    __shared__ float s_val[512];
    __shared__ int   s_cnt[65];
    const int g   = blockIdx.y;
    const int row = blockIdx.x;
    const int tid = threadIdx.x;
    const int nt  = 64;
    const float* A = adjs.a[g];
    const float* X = Xall + (size_t)g * Ndim * Edim;
    float* Y       = Yall + (size_t)g * Ndim * Edim;
    const int chunk = Ndim / nt;   // 16
    const float* arow = A + (size_t)row * Ndim;
    const int c0 = tid * chunk;
    int cnt = 0;
    for (int j = 0; j < chunk; j++) if (arow[c0 + j] != 0.f) cnt++;
    s_cnt[tid] = cnt;
    __syncthreads();
    if (tid == 0) {
        int run = 0;
        for (int t = 0; t < nt; t++) { int c = s_cnt[t]; s_cnt[t] = run; run += c; }
        s_cnt[nt] = run;
    }
    __syncthreads();
    int off = s_cnt[tid];
    for (int j = 0; j < chunk; j++) {
        float a = arow[c0 + j];
        if (a != 0.f) { if (off < 512) { s_idx[off] = c0 + j; s_val[off] = a; } off++; }
    }
    __syncthreads();
    const int total = min(s_cnt[nt], 512);
    const int e = tid;
    if (e < Edim) {
        float acc = 0.f;
        for (int t = 0; t < total; t++) acc += s_val[t] * X[(size_t)s_idx[t] * Edim + e];
        acc += bias[e];
        if (relu) acc = fmaxf(acc, 0.f);
        Y[(size_t)row * Edim + e] = acc;
    }
}

// ---------------- elementwise helpers ----------------
__global__ void mean_adj_kernel(const float* __restrict__ a0, const float* __restrict__ a1,
                                float* __restrict__ out, int n)
{
    int i = blockIdx.x * blockDim.x + threadIdx.x;
    if (i < n) out[i] = 0.5f * (a0[i] + a1[i]);
}

__global__ void l2norm_kernel(float* __restrict__ X, int rows)
{
    int w = (blockIdx.x * blockDim.x + threadIdx.x) >> 5;
    int lane = threadIdx.x & 31;
    if (w >= rows) return;
    float* r = X + (size_t)w * 64;
    float a = r[lane], b = r[lane + 32];
    float s = a*a + b*b;
    #pragma unroll
    for (int off = 16; off > 0; off >>= 1) s += __shfl_xor_sync(0xffffffffu, s, off);
    float nrm = fmaxf(sqrtf(s), 1e-12f);
    r[lane] = a / nrm; r[lane + 32] = b / nrm;
}

__global__ __launch_bounds__(256) void att_kernel(
    const float* __restrict__ hs, const float* __restrict__ att_w,
    const float* __restrict__ att_b, const float* __restrict__ att_vec,
    float* __restrict__ epart)
{
    __shared__ float w_s[64*64];
    __shared__ float b_s[64];
    __shared__ float v_s[64];
    __shared__ float red[256];
    const int tid = threadIdx.x;
    for (int i = tid; i < 64*64; i += 256) w_s[i] = att_w[i];
    if (tid < 64) { b_s[tid] = att_b[tid]; v_s[tid] = att_vec[tid]; }
    __syncthreads();
    const int v = blockIdx.y;
    const int n = blockIdx.x * 256 + tid;
    const float* row = hs + ((size_t)v * Ndim + n) * 64;
    float r[64];
    #pragma unroll
    for (int f = 0; f < 64; f++) r[f] = row[f];
    float s = 0.f;
    for (int e = 0; e < 64; e++) {
        float acc = b_s[e];
        #pragma unroll
        for (int f = 0; f < 64; f++) acc += r[f] * w_s[f*64 + e];
        s += v_s[e] * tanhf(acc);
    }
    red[tid] = s;
    __syncthreads();
    for (int st = 128; st > 0; st >>= 1) {
        if (tid < st) red[tid] += red[tid + st];
        __syncthreads();
    }
    if (tid == 0) epart[v*4 + blockIdx.x] = red[0];
}

__global__ void beta_kernel(const float* __restrict__ epart, float* __restrict__ beta)
{
    float e[4];
    float m = -1e30f;
    for (int v = 0; v < 4; v++) {
        e[v] = (epart[v*4+0] + epart[v*4+1] + epart[v*4+2] + epart[v*4+3]) / (float)Ndim;
        m = fmaxf(m, e[v]);
    }
    float s = 0.f;
    for (int v = 0; v < 4; v++) { float b = expf(e[v] - m); beta[v] = b; s += b; }
    for (int v = 0; v < 4; v++) beta[v] /= s;
}

__global__ void zfine_kernel(const float* __restrict__ hs, const float* __restrict__ beta,
                             float* __restrict__ zfine, int n)
{
    int i = blockIdx.x * blockDim.x + threadIdx.x;
    if (i < n) {
        float s = beta[0]*hs[i] + beta[1]*hs[(size_t)Ndim*Edim + i]
                + beta[2]*hs[(size_t)2*Ndim*Edim + i] + beta[3]*hs[(size_t)3*Ndim*Edim + i];
        zfine[i] = s;
    }
}

__global__ __launch_bounds__(256) void u_kernel(
    const float* __restrict__ zf, const float* __restrict__ zc,
    const float* __restrict__ mlp1_w, const float* __restrict__ mlp1_b,
    float* __restrict__ Uf, float* __restrict__ Uc)
{
    __shared__ float w_s[64*16];
    const int tid = threadIdx.x;
    for (int i = tid; i < 64*16; i += 256) w_s[i] = mlp1_w[i];
    __syncthreads();
    const int n = blockIdx.x * 16 + (tid >> 4);
    const int k = tid & 15;
    const float* zfr = zf + (size_t)n * 64;
    const float* zcr = zc + (size_t)n * 64;
    float af = 0.f, acr = 0.f;
    #pragma unroll
    for (int e = 0; e < 64; e++) {
        float w = w_s[e*16 + k];
        af  += zfr[e] * w;
        acr += zcr[e] * w;
    }
    Uf[(size_t)n*16 + k] = af + mlp1_b[k];
    Uc[(size_t)n*16 + k] = acr;
}

__global__ void diag_kernel(const float* __restrict__ zf, const float* __restrict__ zc,
                            float* __restrict__ diag)
{
    int w = (blockIdx.x * blockDim.x + threadIdx.x) >> 5;
    int lane = threadIdx.x & 31;
    if (w >= Ndim) return;
    const float* a = zf + (size_t)w * 64;
    const float* b = zc + (size_t)w * 64;
    float s = a[lane]*b[lane] + a[lane+32]*b[lane+32];
    #pragma unroll
    for (int off = 16; off > 0; off >>= 1) s += __shfl_xor_sync(0xffffffffu, s, off);
    if (lane == 0) diag[w] = 2.f * s;
}

__global__ __launch_bounds__(256) void pair_kernel(
    const float* __restrict__ zf, const float* __restrict__ zc,
    const float* __restrict__ Uf, const float* __restrict__ Uc,
    const float* __restrict__ mlp2_w, const float* __restrict__ mlp2_b,
    float* __restrict__ part)
{
    __shared__ float zf_s[16][68];
    __shared__ float zc_s[16][68];
    __shared__ float uc_s[16][17];
    __shared__ float m2_s[16];
    const int tid = threadIdx.x;
    const int bi = blockIdx.y * 16;
    const int bj = blockIdx.x * 16;
    const int lr = tid >> 4, lc = (tid & 15) << 2;
    *(float4*)&zf_s[lr][lc] = *(const float4*)(zf + (size_t)(bi + lr) * 64 + lc);
    *(float4*)&zc_s[lr][lc] = *(const float4*)(zc + (size_t)(bj + lr) * 64 + lc);
    uc_s[tid >> 4][tid & 15] = Uc[(size_t)(bj + (tid >> 4)) * 16 + (tid & 15)];
    if (tid < 16) m2_s[tid] = mlp2_w[tid];
    __syncthreads();
    const int ti = tid >> 4, tj = tid & 15;
    const int i = bi + ti;
    float uf[16];
    #pragma unroll
    for (int k = 0; k < 16; k++) uf[k] = Uf[(size_t)i*16 + k];
    float dot = 0.f;
    #pragma unroll
    for (int e = 0; e < 64; e++) dot += zf_s[ti][e] * zc_s[tj][e];
    float sacc = mlp2_b[0];
    #pragma unroll
    for (int k = 0; k < 16; k++) sacc += m2_s[k] * fast_tanh(uf[k] + uc_s[tj][k]);
    float w = 1.f / (1.f + __expf(-fminf(fmaxf(sacc, -30.f), 30.f)));
    float contrib = __expf(2.f * dot) * w;
    #pragma unroll
    for (int off = 8; off > 0; off >>= 1)
        contrib += __shfl_down_sync(0xffffffffu, contrib, off, 16);
    if (tj == 0) part[(size_t)blockIdx.x * Ndim + i] = contrib;
}

__global__ void loss_kernel(const float* __restrict__ part, const float* __restrict__ diag,
                            float* __restrict__ out)
{
    __shared__ float red[256];
    const int tid = threadIdx.x;
    float s = 0.f;
    for (int i = tid; i < Ndim; i += 256) {
        float d = 0.f;
        for (int b = 0; b < 64; b++) d += part[(size_t)b * Ndim + i];
        s += logf(d) - diag[i];
    }
    red[tid] = s;
    __syncthreads();
    for (int st = 128; st > 0; st >>= 1) {
        if (tid < st) red[tid] += red[tid + st];
        __syncthreads();
    }
    if (tid == 0) out[0] = red[0] / (float)Ndim;
}

// ---------------- host ----------------
static float* devptr(const void* sym) {
    void* p = nullptr;
    cudaGetSymbolAddress(&p, sym);
    return (float*)p;
}

extern "C" void kernel_launch(void* const* d_in, const int* in_sizes, int n_in,
                              void* d_out, int out_size)
{
    const float* feat0     = (const float*)d_in[0];
    const float* feat1     = (const float*)d_in[1];
    const float* feat2     = (const float*)d_in[2];
    const float* mask_feat = (const float*)d_in[3];
    const float* nei0      = (const float*)d_in[4];
    const float* nei1      = (const float*)d_in[5];
    const float* adj0      = (const float*)d_in[6];
    const float* adj1      = (const float*)d_in[7];
    const float* madj0     = (const float*)d_in[8];
    const float* madj1     = (const float*)d_in[9];
    const float* fc0_w     = (const float*)d_in[10];
    const float* fc0_b     = (const float*)d_in[11];
    const float* fc1_w     = (const float*)d_in[12];
    const float* fc1_b     = (const float*)d_in[13];
    const float* fc2_w     = (const float*)d_in[14];
    const float* fc2_b     = (const float*)d_in[15];
    const float* agg0_w    = (const float*)d_in[16];
    const float* agg1_w    = (const float*)d_in[17];
    const float* gcn_w1    = (const float*)d_in[18];
    const float* gcn_b1    = (const float*)d_in[19];
    const float* gcn_w2    = (const float*)d_in[20];
    const float* gcn_b2    = (const float*)d_in[21];
    const float* att_w     = (const float*)d_in[22];
    const float* att_b     = (const float*)d_in[23];
    const float* att_vec   = (const float*)d_in[24];
    const float* proj_w    = (const float*)d_in[25];
    const float* proj_b    = (const float*)d_in[26];
    const float* mlp1_w    = (const float*)d_in[27];
    const float* mlp1_b    = (const float*)d_in[28];
    const float* mlp2_w    = (const float*)d_in[29];
    const float* mlp2_b    = (const float*)d_in[30];

    float* h_tar  = devptr(g_h_tar);
    float* h_mask = devptr(g_h_mask);
    float* h_nei0 = devptr(g_h_nei0);
    float* h_nei1 = devptr(g_h_nei1);
    float* h_agg0 = devptr(g_h_agg0);
    float* h_agg1 = devptr(g_h_agg1);
    float* views0 = devptr(g_views0);
    float* views1 = devptr(g_views1);
    float* masks0 = devptr(g_masks0);
    float* masks1 = devptr(g_masks1);
    float* meanA  = devptr(g_mean_adj);
    float* xw_all = devptr(g_xw_all);
    float* h1_all = devptr(g_h1_all);
    float* hw_all = devptr(g_hw_all);
    float* z_all  = devptr(g_z_all);
    float* epart  = devptr(g_epart);
    float* beta   = devptr(g_beta);
    float* zfine  = devptr(g_zfine);
    float* z2     = devptr(g_z2);
    float* Uf     = devptr(g_Uf);
    float* Uc     = devptr(g_Uc);
    float* diag   = devptr(g_diag);
    float* part   = devptr(g_part);

    const int NE = Ndim * Edim;   // 65536

    // ---- encoders: one segmented launch (K=1024 segments first for balance) ----
    {
        Segs sgs;
        sgs.nseg = 4;
        sgs.s[0] = { feat0,     fc0_w, fc0_b, h_tar,  nullptr, D0, 8  };
        sgs.s[1] = { mask_feat, fc0_w, fc0_b, h_mask, nullptr, D0, 16 };
        sgs.s[2] = { feat1,     fc1_w, fc1_b, h_nei0, nullptr, D1, 48 };
        sgs.s[3] = { feat2,     fc2_w, fc2_b, h_nei1, nullptr, D1, 80 };
        gemm_big<8,1><<<dim3(Hdim/128, 80), 256>>>(sgs, Hdim, nullptr, nullptr);
    }

    // ---- neighbor mean aggregation ----
    spmm_scan_kernel<<<Ndim, 256>>>(nei0, h_nei0, h_agg0, Mdim, Hdim);
    spmm_scan_kernel<<<Ndim, 256>>>(nei1, h_nei1, h_agg1, Mdim, Hdim);
    mean_adj_kernel<<<(Ndim*Ndim + 255)/256, 256>>>(adj0, adj1, meanA, Ndim*Ndim);

    // ---- agg GEMMs with fused views/masks epilogue ----
    {
        Segs sgs;
        sgs.nseg = 2;
        sgs.s[0] = { h_agg0, agg0_w, nullptr, views0, masks0, Hdim, 16 };
        sgs.s[1] = { h_agg1, agg1_w, nullptr, views1, masks1, Hdim, 32 };
        sgs.s[2] = sgs.s[1]; sgs.s[3] = sgs.s[1];
        gemm_big<4,2><<<dim3(Hdim/128, 32), 256>>>(sgs, Hdim, h_tar, h_mask);
    }

    // ---- GCN stage A: xw = X @ gcn_w1 for 5 inputs ----
    {
        In5 ins = {{ h_tar, views0, masks0, views1, masks1 }};
        gemm_small<0><<<5*32, 128>>>(ins, gcn_w1, nullptr, xw_all, Hdim, 32);
    }
    // ---- GCN stage B: h1 = relu(adj @ xw + b1) ----
    {
        Adj5 adjs = {{ meanA, adj0, madj0, adj1, madj1 }};
        gcn_spmm_kernel<<<dim3(Ndim, 5), 64>>>(adjs, xw_all, gcn_b1, h1_all, 1);
    }
    // ---- GCN stage C: hw = h1 @ gcn_w2 ----
    {
        In5 ins = {{ h1_all, h1_all + NE, h1_all + 2*NE, h1_all + 3*NE, h1_all + 4*NE }};
        gemm_small<0><<<5*32, 128>>>(ins, gcn_w2, nullptr, hw_all, Edim, 32);
    }
    // ---- GCN stage D: z = adj @ hw + b2 ----
    {
        Adj5 adjs = {{ meanA, adj0, madj0, adj1, madj1 }};
        gcn_spmm_kernel<<<dim3(Ndim, 5), 64>>>(adjs, hw_all, gcn_b2, z_all, 0);
    }

    // ---- l2norm the 4 fine views (slices 1..4), attention, z_fine ----
    float* hs = z_all + NE;
    l2norm_kernel<<<(4*Ndim)/8, 256>>>(hs, 4*Ndim);
    att_kernel<<<dim3(4,4), 256>>>(hs, att_w, att_b, att_vec, epart);
    beta_kernel<<<1, 1>>>(epart, beta);
    zfine_kernel<<<(NE + 255)/256, 256>>>(hs, beta, zfine, NE);

    // ---- projections (batched): zc from z_coarse, zf from z_fine ----
    {
        In5 ins = {{ z_all, zfine, zfine, zfine, zfine }};
        gemm_small<3><<<2*32, 128>>>(ins, proj_w, proj_b, z2, Edim, 32);
    }
    l2norm_kernel<<<(2*Ndim)/8, 256>>>(z2, 2*Ndim);
    float* zc = z2;
    float* zf = z2 + NE;

    // ---- weighted InfoNCE ----
    u_kernel<<<Ndim/16, 256>>>(zf, zc, mlp1_w, mlp1_b, Uf, Uc);
    diag_kernel<<<Ndim/8, 256>>>(zf, zc, diag);
    pair_kernel<<<dim3(64, 64), 256>>>(zf, zc, Uf, Uc, mlp2_w, mlp2_b, part);
    loss_kernel<<<1, 256>>>(part, diag, (float*)d_out);
}

// round 7
// speedup vs baseline: 2.0898x; 1.3850x over previous
#include <cuda_runtime.h>
#include <cuda_bf16.h>
#include <math.h>
#include <stdint.h>
#include <stddef.h>

#define Ndim 1024
#define Mdim 4096
#define D0 1024
#define D1 512
#define Hdim 512
#define Edim 64

typedef unsigned long long ull;

// ---------------- scratch (device globals; no allocation allowed) ----------------
__device__ float g_h_tar[Ndim*Hdim];
__device__ float g_h_mask[Ndim*Hdim];
__device__ float g_h_nei0[Mdim*Hdim];
__device__ float g_h_nei1[Mdim*Hdim];
__device__ float g_views0[Ndim*Hdim];
__device__ float g_views1[Ndim*Hdim];
__device__ float g_masks0[Ndim*Hdim];
__device__ float g_masks1[Ndim*Hdim];
__device__ float g_xw_all[5*Ndim*Edim];
__device__ float g_h1_all[5*Ndim*Edim];
__device__ float g_hw_all[5*Ndim*Edim];
__device__ float g_z_all[5*Ndim*Edim];
__device__ float g_epart[16];
__device__ float g_beta[4];
__device__ float g_zfine[Ndim*Edim];
__device__ float g_z2[2*Ndim*Edim];
__device__ float g_Uf[Ndim*16];
__device__ float g_Uc[Ndim*16];
__device__ float g_diag[Ndim];
__device__ float g_part[64*Ndim];

// bf16 hi/lo planes
__device__ __nv_bfloat16 g_feat0_h[Ndim*D0],  g_feat0_l[Ndim*D0];
__device__ __nv_bfloat16 g_mask_h[Ndim*D0],   g_mask_l[Ndim*D0];
__device__ __nv_bfloat16 g_feat1_h[Mdim*D1],  g_feat1_l[Mdim*D1];
__device__ __nv_bfloat16 g_feat2_h[Mdim*D1],  g_feat2_l[Mdim*D1];
__device__ __nv_bfloat16 g_fc0w_h[D0*Hdim],   g_fc0w_l[D0*Hdim];
__device__ __nv_bfloat16 g_fc1w_h[D1*Hdim],   g_fc1w_l[D1*Hdim];
__device__ __nv_bfloat16 g_fc2w_h[D1*Hdim],   g_fc2w_l[D1*Hdim];
__device__ __nv_bfloat16 g_ag0w_h[Hdim*Hdim], g_ag0w_l[Hdim*Hdim];
__device__ __nv_bfloat16 g_ag1w_h[Hdim*Hdim], g_ag1w_l[Hdim*Hdim];
__device__ __nv_bfloat16 g_agg0_h[Ndim*Hdim], g_agg0_l[Ndim*Hdim];
__device__ __nv_bfloat16 g_agg1_h[Ndim*Hdim], g_agg1_l[Ndim*Hdim];

__device__ __forceinline__ float eluf(float x){ return x > 0.f ? x : expm1f(x); }
__device__ __forceinline__ float fast_tanh(float x){
    x = fminf(fmaxf(x, -20.f), 20.f);
    float e = __expf(2.f*x);
    return (e - 1.f) / (e + 1.f);
}
__device__ __forceinline__ ull dup2(float x){
    ull r; asm("mov.b64 %0, {%1, %1};" : "=l"(r) : "f"(x)); return r;
}
__device__ __forceinline__ ull fma2(ull a, ull b, ull c){
    ull d; asm("fma.rn.f32x2 %0, %1, %2, %3;" : "=l"(d) : "l"(a), "l"(b), "l"(c)); return d;
}
__device__ __forceinline__ void unpack2(ull v, float& lo, float& hi){
    asm("mov.b64 {%0, %1}, %2;" : "=f"(lo), "=f"(hi) : "l"(v));
}
__device__ __forceinline__ uint32_t smem_u32(const void* p){
    uint32_t r;
    asm("{ .reg .u64 t; cvta.to.shared.u64 t, %1; cvt.u32.u64 %0, t; }" : "=r"(r) : "l"(p));
    return r;
}
__device__ __forceinline__ void ldmA4(uint32_t* r, uint32_t addr){
    asm volatile("ldmatrix.sync.aligned.m8n8.x4.shared.b16 {%0,%1,%2,%3}, [%4];"
        : "=r"(r[0]),"=r"(r[1]),"=r"(r[2]),"=r"(r[3]) : "r"(addr));
}
__device__ __forceinline__ void ldmBT4(uint32_t* r, uint32_t addr){
    asm volatile("ldmatrix.sync.aligned.m8n8.x4.trans.shared.b16 {%0,%1,%2,%3}, [%4];"
        : "=r"(r[0]),"=r"(r[1]),"=r"(r[2]),"=r"(r[3]) : "r"(addr));
}
__device__ __forceinline__ void mma_bf16(float* d, const uint32_t* a, const uint32_t* b){
    asm volatile("mma.sync.aligned.m16n8k16.row.col.f32.bf16.bf16.f32 "
        "{%0,%1,%2,%3}, {%4,%5,%6,%7}, {%8,%9}, {%0,%1,%2,%3};"
        : "+f"(d[0]),"+f"(d[1]),"+f"(d[2]),"+f"(d[3])
        : "r"(a[0]),"r"(a[1]),"r"(a[2]),"r"(a[3]), "r"(b[0]),"r"(b[1]));
}

// ---------------- split: fp32 -> bf16 hi/lo planes ----------------
struct SJob { const float* s; __nv_bfloat16* h; __nv_bfloat16* l; int n4; };
struct SJobs { SJob j[9]; };

__global__ __launch_bounds__(256) void split_kernel(SJobs jobs)
{
    SJob jb = jobs.j[blockIdx.y];
    const int stride = gridDim.x * blockDim.x;
    for (int i = blockIdx.x * blockDim.x + threadIdx.x; i < jb.n4; i += stride) {
        float4 v = ((const float4*)jb.s)[i];
        __nv_bfloat16 h0 = __float2bfloat16(v.x);
        __nv_bfloat16 h1 = __float2bfloat16(v.y);
        __nv_bfloat16 h2 = __float2bfloat16(v.z);
        __nv_bfloat16 h3 = __float2bfloat16(v.w);
        __nv_bfloat16 l0 = __float2bfloat16(v.x - __bfloat162float(h0));
        __nv_bfloat16 l1 = __float2bfloat16(v.y - __bfloat162float(h1));
        __nv_bfloat16 l2 = __float2bfloat16(v.z - __bfloat162float(h2));
        __nv_bfloat16 l3 = __float2bfloat16(v.w - __bfloat162float(h3));
        ushort4 H, L;
        H.x = __bfloat16_as_ushort(h0); H.y = __bfloat16_as_ushort(h1);
        H.z = __bfloat16_as_ushort(h2); H.w = __bfloat16_as_ushort(h3);
        L.x = __bfloat16_as_ushort(l0); L.y = __bfloat16_as_ushort(l1);
        L.z = __bfloat16_as_ushort(l2); L.w = __bfloat16_as_ushort(l3);
        ((ushort4*)jb.h)[i] = H;
        ((ushort4*)jb.l)[i] = L;
    }
}

// ================= HMMA GEMM: C = act(A@W + ...), bf16-split 3-product =================
// BM=128, BN=128, BK=32, 256 threads (8 warps: 2m x 4n), warp tile 64x32.
// EPI: 1 = elu(v+bias) -> C ; 2 = C=elu(aux0+v), C2=elu(aux1+v) ; 0 = raw.
struct SegH { const __nv_bfloat16 *Ah, *Al, *Wh, *Wl; const float* bias;
              float* C; float* C2; int K; int tileEnd; };
struct SegsH { SegH s[4]; int nseg; };

template<int EPI>
__global__ __launch_bounds__(256) void hmma_gemm(
    SegsH segs, int Nd, const float* __restrict__ aux0, const float* __restrict__ aux1)
{
    __shared__ __align__(16) __nv_bfloat16 Ah_s[128][40];
    __shared__ __align__(16) __nv_bfloat16 Al_s[128][40];
    __shared__ __align__(16) __nv_bfloat16 Wh_s[32][136];
    __shared__ __align__(16) __nv_bfloat16 Wl_s[32][136];

    const int tid = threadIdx.x;
    const int by  = blockIdx.y;
    int si = 0, tileStart = 0;
    #pragma unroll
    for (int i = 0; i < 3; i++)
        if (i < segs.nseg && by >= segs.s[i].tileEnd) { si = i + 1; tileStart = segs.s[i].tileEnd; }
    const SegH sg = segs.s[si];
    const int K  = sg.K;
    const int bm = (by - tileStart) * 128;
    const int bn = blockIdx.x * 128;

    const int lane = tid & 31;
    const int w    = tid >> 5;
    const int wm   = w >> 2;      // 0..1
    const int wn   = w & 3;       // 0..3

    // loaders
    const int arow = tid >> 1;           // 0..127
    const int aseg = (tid & 1) * 16;     // 0 or 16
    const int krow = tid >> 3;           // 0..31
    const int nsg  = (tid & 7) * 16;     // 0..112

    const uint32_t aBaseH = smem_u32(&Ah_s[0][0]);
    const uint32_t aBaseL = smem_u32(&Al_s[0][0]);
    const uint32_t wBaseH = smem_u32(&Wh_s[0][0]);
    const uint32_t wBaseL = smem_u32(&Wl_s[0][0]);
    const uint32_t aoff = ((wm*64 + (lane & 15)) * 40 + (lane >> 4) * 8) * 2;
    const uint32_t boff = ((lane & 15) * 136 + wn*32 + (lane >> 4) * 8) * 2;

    float d[4][4][4];
    #pragma unroll
    for (int mt = 0; mt < 4; mt++)
        #pragma unroll
        for (int nt = 0; nt < 4; nt++)
            #pragma unroll
            for (int q = 0; q < 4; q++) d[mt][nt][q] = 0.f;

    const int nk = K >> 5;
    for (int t = 0; t < nk; t++) {
        const int k0 = t * 32;
        const __nv_bfloat16* Agh = sg.Ah + (size_t)(bm + arow) * K + k0 + aseg;
        const __nv_bfloat16* Agl = sg.Al + (size_t)(bm + arow) * K + k0 + aseg;
        const __nv_bfloat16* Wgh = sg.Wh + (size_t)(k0 + krow) * Nd + bn + nsg;
        const __nv_bfloat16* Wgl = sg.Wl + (size_t)(k0 + krow) * Nd + bn + nsg;
        uint4 ah0 = *(const uint4*)(Agh);     uint4 ah1 = *(const uint4*)(Agh + 8);
        uint4 al0 = *(const uint4*)(Agl);     uint4 al1 = *(const uint4*)(Agl + 8);
        uint4 wh0 = *(const uint4*)(Wgh);     uint4 wh1 = *(const uint4*)(Wgh + 8);
        uint4 wl0 = *(const uint4*)(Wgl);     uint4 wl1 = *(const uint4*)(Wgl + 8);
        __syncthreads();
        *(uint4*)&Ah_s[arow][aseg]     = ah0;  *(uint4*)&Ah_s[arow][aseg + 8] = ah1;
        *(uint4*)&Al_s[arow][aseg]     = al0;  *(uint4*)&Al_s[arow][aseg + 8] = al1;
        *(uint4*)&Wh_s[krow][nsg]      = wh0;  *(uint4*)&Wh_s[krow][nsg + 8]  = wh1;
        *(uint4*)&Wl_s[krow][nsg]      = wl0;  *(uint4*)&Wl_s[krow][nsg + 8]  = wl1;
        __syncthreads();
        #pragma unroll
        for (int ks = 0; ks < 2; ks++) {
            uint32_t ah[4][4], al[4][4];
            #pragma unroll
            for (int mt = 0; mt < 4; mt++) {
                const uint32_t o = aoff + (mt * 16 * 40 + ks * 16) * 2;
                ldmA4(ah[mt], aBaseH + o);
                ldmA4(al[mt], aBaseL + o);
            }
            uint32_t bh[2][4], bl[2][4];
            #pragma unroll
            for (int np = 0; np < 2; np++) {
                const uint32_t o = boff + (ks * 16 * 136 + np * 16) * 2;
                ldmBT4(bh[np], wBaseH + o);
                ldmBT4(bl[np], wBaseL + o);
            }
            #pragma unroll
            for (int mt = 0; mt < 4; mt++) {
                #pragma unroll
                for (int nt = 0; nt < 4; nt++) {
                    const uint32_t* bph = &bh[nt >> 1][(nt & 1) * 2];
                    const uint32_t* bpl = &bl[nt >> 1][(nt & 1) * 2];
                    mma_bf16(d[mt][nt], al[mt], bph);
                    mma_bf16(d[mt][nt], ah[mt], bpl);
                    mma_bf16(d[mt][nt], ah[mt], bph);
                }
            }
        }
    }

    // epilogue
    const int g  = lane >> 2;
    const int tq = lane & 3;
    #pragma unroll
    for (int mt = 0; mt < 4; mt++) {
        #pragma unroll
        for (int nt = 0; nt < 4; nt++) {
            const int r = bm + wm*64 + mt*16 + g;
            const int c = bn + wn*32 + nt*8 + tq*2;
            #pragma unroll
            for (int half = 0; half < 2; half++) {
                const int rr = r + half * 8;
                float v0 = d[mt][nt][half*2 + 0];
                float v1 = d[mt][nt][half*2 + 1];
                const size_t idx = (size_t)rr * Nd + c;
                if (EPI == 1) {
                    v0 = eluf(v0 + sg.bias[c]); v1 = eluf(v1 + sg.bias[c+1]);
                    *(float2*)&sg.C[idx] = make_float2(v0, v1);
                } else if (EPI == 2) {
                    float2 a0 = *(const float2*)&aux0[idx];
                    float2 a1 = *(const float2*)&aux1[idx];
                    *(float2*)&sg.C[idx]  = make_float2(eluf(a0.x + v0), eluf(a0.y + v1));
                    *(float2*)&sg.C2[idx] = make_float2(eluf(a1.x + v0), eluf(a1.y + v1));
                } else {
                    *(float2*)&sg.C[idx] = make_float2(v0, v1);
                }
            }
        }
    }
}

// ================= small GEMM: N=64, batched over 5 inputs, f32x2 =================
struct In5 { const float* p[5]; };

template<int ACT>
__global__ __launch_bounds__(128) void gemm_small(
    In5 ins, const float* __restrict__ W, const float* __restrict__ bias,
    float* __restrict__ out, int K, int tilesPer)
{
    __shared__ __align__(16) float As[16][32];
    __shared__ __align__(16) float Bs[16][64];
    const int tid = threadIdx.x;
    const int g  = blockIdx.x / tilesPer;
    const int tb = blockIdx.x % tilesPer;
    const float* A = ins.p[g] + (size_t)tb * 32 * K;
    float* C = out + ((size_t)g * tilesPer * 32 + tb * 32) * 64;

    const int tx = tid & 15;
    const int ty = tid >> 4;
    const int ar = tid >> 2, akc = (tid & 3) * 4;
    const int br = tid >> 4, bc = (tid & 15) * 4;

    ull acc[4][2];
    #pragma unroll
    for (int i = 0; i < 4; i++) { acc[i][0] = 0ull; acc[i][1] = 0ull; }

    for (int k0 = 0; k0 < K; k0 += 16) {
        float4 av  = *(const float4*)(A + (size_t)ar * K + k0 + akc);
        float4 bv0 = *(const float4*)(W + (size_t)(k0 + br) * 64 + bc);
        float4 bv1 = *(const float4*)(W + (size_t)(k0 + br + 8) * 64 + bc);
        __syncthreads();
        As[akc+0][ar] = av.x; As[akc+1][ar] = av.y; As[akc+2][ar] = av.z; As[akc+3][ar] = av.w;
        *(float4*)&Bs[br][bc]   = bv0;
        *(float4*)&Bs[br+8][bc] = bv1;
        __syncthreads();
        #pragma unroll
        for (int kk = 0; kk < 16; kk++) {
            float4 av2 = *(const float4*)&As[kk][ty*4];
            ulonglong2 bp = *(const ulonglong2*)&Bs[kk][tx*4];
            ull a2[4] = {dup2(av2.x), dup2(av2.y), dup2(av2.z), dup2(av2.w)};
            #pragma unroll
            for (int i = 0; i < 4; i++) {
                acc[i][0] = fma2(a2[i], bp.x, acc[i][0]);
                acc[i][1] = fma2(a2[i], bp.y, acc[i][1]);
            }
        }
    }
    #pragma unroll
    for (int i = 0; i < 4; i++) {
        const int row = ty * 4 + i;
        #pragma unroll
        for (int j = 0; j < 2; j++) {
            float v0, v1; unpack2(acc[i][j], v0, v1);
            const int c = tx * 4 + 2 * j;
            if (bias) { v0 += bias[c]; v1 += bias[c+1]; }
            if (ACT == 3) { v0 = tanhf(v0); v1 = tanhf(v1); }
            *(float2*)&C[(size_t)row * 64 + c] = make_float2(v0, v1);
        }
    }
}

// ========== nei SpMM (mean over nnz) -> bf16 hi/lo planes ==========
__global__ void spmm_scan_kernel(
    const float* __restrict__ A, const float* __restrict__ X,
    __nv_bfloat16* __restrict__ Yh, __nv_bfloat16* __restrict__ Yl, int K, int E)
{
    __shared__ int   s_idx[512];
    __shared__ float s_val[512];
    __shared__ int   s_cnt[257];
    const int row = blockIdx.x;
    const int tid = threadIdx.x;
    const int nt  = blockDim.x;
    const int chunk = K / nt;
    const float* arow = A + (size_t)row * K;
    const int c0 = tid * chunk;
    int cnt = 0;
    for (int j = 0; j < chunk; j++) if (arow[c0 + j] != 0.f) cnt++;
    s_cnt[tid] = cnt;
    __syncthreads();
    if (tid == 0) {
        int run = 0;
        for (int t = 0; t < nt; t++) { int c = s_cnt[t]; s_cnt[t] = run; run += c; }
        s_cnt[nt] = run;
    }
    __syncthreads();
    int off = s_cnt[tid];
    for (int j = 0; j < chunk; j++) {
        float a = arow[c0 + j];
        if (a != 0.f) { if (off < 512) { s_idx[off] = c0 + j; s_val[off] = a; } off++; }
    }
    __syncthreads();
    const int total = min(s_cnt[nt], 512);
    const float inv = 1.f / fmaxf((float)s_cnt[nt], 1.f);
    for (int e = tid; e < E; e += nt) {
        float acc = 0.f;
        for (int t = 0; t < total; t++) acc += s_val[t] * X[(size_t)s_idx[t] * E + e];
        float v = acc * inv;
        __nv_bfloat16 h = __float2bfloat16(v);
        Yh[(size_t)row * E + e] = h;
        Yl[(size_t)row * E + e] = __float2bfloat16(v - __bfloat162float(h));
    }
}

// ========== batched GCN SpMM; g==0 uses mean(adj0,adj1) on the fly ==========
struct Adj4 { const float* a[4]; };
__global__ void gcn_spmm_kernel(
    const float* __restrict__ adj0, const float* __restrict__ adj1, Adj4 others,
    const float* __restrict__ Xall, const float* __restrict__ bias,
    float* __restrict__ Yall, int relu, int donorm)
{
    __shared__ int   s_idx[512];
    __shared__ float s_val[512];
    __shared__ int   s_cnt[65];
    __shared__ float s_sq[2];
    const int g   = blockIdx.y;
    const int row = blockIdx.x;
    const int tid = threadIdx.x;
    const int nt  = 64;
    const float* X = Xall + (size_t)g * Ndim * Edim;
    float* Y       = Yall + (size_t)g * Ndim * Edim;
    const int chunk = Ndim / nt;   // 16
    const int c0 = tid * chunk;
    int cnt = 0;
    if (g == 0) {
        const float* r0 = adj0 + (size_t)row * Ndim;
        const float* r1 = adj1 + (size_t)row * Ndim;
        for (int j = 0; j < chunk; j++) if (r0[c0+j] + r1[c0+j] != 0.f) cnt++;
        s_cnt[tid] = cnt;
        __syncthreads();
        if (tid == 0) {
            int run = 0;
            for (int t = 0; t < nt; t++) { int c = s_cnt[t]; s_cnt[t] = run; run += c; }
            s_cnt[nt] = run;
        }
        __syncthreads();
        int off = s_cnt[tid];
        for (int j = 0; j < chunk; j++) {
            float a = r0[c0+j] + r1[c0+j];
            if (a != 0.f) { if (off < 512) { s_idx[off] = c0 + j; s_val[off] = 0.5f * a; } off++; }
        }
    } else {
        const float* arow = others.a[g-1] + (size_t)row * Ndim;
        for (int j = 0; j < chunk; j++) if (arow[c0 + j] != 0.f) cnt++;
        s_cnt[tid] = cnt;
        __syncthreads();
        if (tid == 0) {
            int run = 0;
            for (int t = 0; t < nt; t++) { int c = s_cnt[t]; s_cnt[t] = run; run += c; }
            s_cnt[nt] = run;
        }
        __syncthreads();
        int off = s_cnt[tid];
        for (int j = 0; j < chunk; j++) {
            float a = arow[c0 + j];
            if (a != 0.f) { if (off < 512) { s_idx[off] = c0 + j; s_val[off] = a; } off++; }
        }
    }
    __syncthreads();
    const int total = min(s_cnt[nt], 512);
    const int e = tid;
    float v = 0.f;
    for (int t = 0; t < total; t++) v += s_val[t] * X[(size_t)s_idx[t] * Edim + e];
    v += bias[e];
    if (relu) v = fmaxf(v, 0.f);
    if (donorm && g > 0) {
        float sq = v * v;
        #pragma unroll
        for (int o = 16; o > 0; o >>= 1) sq += __shfl_xor_sync(0xffffffffu, sq, o);
        if ((tid & 31) == 0) s_sq[tid >> 5] = sq;
        __syncthreads();
        const float nrm = fmaxf(sqrtf(s_sq[0] + s_sq[1]), 1e-12f);
        v /= nrm;
    }
    Y[(size_t)row * Edim + e] = v;
}

// ---------------- elementwise / tail kernels ----------------
__global__ void l2norm_kernel(float* __restrict__ X, int rows)
{
    int w = (blockIdx.x * blockDim.x + threadIdx.x) >> 5;
    int lane = threadIdx.x & 31;
    if (w >= rows) return;
    float* r = X + (size_t)w * 64;
    float a = r[lane], b = r[lane + 32];
    float s = a*a + b*b;
    #pragma unroll
    for (int off = 16; off > 0; off >>= 1) s += __shfl_xor_sync(0xffffffffu, s, off);
    float nrm = fmaxf(sqrtf(s), 1e-12f);
    r[lane] = a / nrm; r[lane + 32] = b / nrm;
}

__global__ __launch_bounds__(256) void att_kernel(
    const float* __restrict__ hs, const float* __restrict__ att_w,
    const float* __restrict__ att_b, const float* __restrict__ att_vec,
    float* __restrict__ epart)
{
    __shared__ float w_s[64*64];
    __shared__ float b_s[64];
    __shared__ float v_s[64];
    __shared__ float red[256];
    const int tid = threadIdx.x;
    for (int i = tid; i < 64*64; i += 256) w_s[i] = att_w[i];
    if (tid < 64) { b_s[tid] = att_b[tid]; v_s[tid] = att_vec[tid]; }
    __syncthreads();
    const int v = blockIdx.y;
    const int n = blockIdx.x * 256 + tid;
    const float* row = hs + ((size_t)v * Ndim + n) * 64;
    float r[64];
    #pragma unroll
    for (int f = 0; f < 64; f++) r[f] = row[f];
    float s = 0.f;
    for (int e = 0; e < 64; e++) {
        float acc = b_s[e];
        #pragma unroll
        for (int f = 0; f < 64; f++) acc += r[f] * w_s[f*64 + e];
        s += v_s[e] * tanhf(acc);
    }
    red[tid] = s;
    __syncthreads();
    for (int st = 128; st > 0; st >>= 1) {
        if (tid < st) red[tid] += red[tid + st];
        __syncthreads();
    }
    if (tid == 0) epart[v*4 + blockIdx.x] = red[0];
}

__global__ void beta_kernel(const float* __restrict__ epart, float* __restrict__ beta)
{
    float e[4];
    float m = -1e30f;
    for (int v = 0; v < 4; v++) {
        e[v] = (epart[v*4+0] + epart[v*4+1] + epart[v*4+2] + epart[v*4+3]) / (float)Ndim;
        m = fmaxf(m, e[v]);
    }
    float s = 0.f;
    for (int v = 0; v < 4; v++) { float b = expf(e[v] - m); beta[v] = b; s += b; }
    for (int v = 0; v < 4; v++) beta[v] /= s;
}

__global__ void zfine_kernel(const float* __restrict__ hs, const float* __restrict__ beta,
                             float* __restrict__ zfine, int n)
{
    int i = blockIdx.x * blockDim.x + threadIdx.x;
    if (i < n) {
        float s = beta[0]*hs[i] + beta[1]*hs[(size_t)Ndim*Edim + i]
                + beta[2]*hs[(size_t)2*Ndim*Edim + i] + beta[3]*hs[(size_t)3*Ndim*Edim + i];
        zfine[i] = s;
    }
}

__global__ __launch_bounds__(256) void u_diag_kernel(
    const float* __restrict__ zf, const float* __restrict__ zc,
    const float* __restrict__ mlp1_w, const float* __restrict__ mlp1_b,
    float* __restrict__ Uf, float* __restrict__ Uc, float* __restrict__ diag)
{
    __shared__ float w_s[64*16];
    const int tid = threadIdx.x;
    for (int i = tid; i < 64*16; i += 256) w_s[i] = mlp1_w[i];
    __syncthreads();
    const int n = blockIdx.x * 16 + (tid >> 4);
    const int k = tid & 15;
    const float* zfr = zf + (size_t)n * 64;
    const float* zcr = zc + (size_t)n * 64;
    float af = 0.f, acr = 0.f;
    #pragma unroll
    for (int e = 0; e < 64; e++) {
        float w = w_s[e*16 + k];
        af  += zfr[e] * w;
        acr += zcr[e] * w;
    }
    Uf[(size_t)n*16 + k] = af + mlp1_b[k];
    Uc[(size_t)n*16 + k] = acr;
    float p = 0.f;
    #pragma unroll
    for (int e = 0; e < 4; e++) p += zfr[4*k + e] * zcr[4*k + e];
    #pragma unroll
    for (int o = 8; o > 0; o >>= 1) p += __shfl_down_sync(0xffffffffu, p, o, 16);
    if (k == 0) diag[n] = 2.f * p;
}

__global__ __launch_bounds__(256) void pair_kernel(
    const float* __restrict__ zf, const float* __restrict__ zc,
    const float* __restrict__ Uf, const float* __restrict__ Uc,
    const float* __restrict__ mlp2_w, const float* __restrict__ mlp2_b,
    float* __restrict__ part)
{
    __shared__ float zf_s[16][68];
    __shared__ float zc_s[16][68];
    __shared__ float uc_s[16][17];
    __shared__ float m2_s[16];
    const int tid = threadIdx.x;
    const int bi = blockIdx.y * 16;
    const int bj = blockIdx.x * 16;
    const int lr = tid >> 4, lc = (tid & 15) << 2;
    *(float4*)&zf_s[lr][lc] = *(const float4*)(zf + (size_t)(bi + lr) * 64 + lc);
    *(float4*)&zc_s[lr][lc] = *(const float4*)(zc + (size_t)(bj + lr) * 64 + lc);
    uc_s[tid >> 4][tid & 15] = Uc[(size_t)(bj + (tid >> 4)) * 16 + (tid & 15)];
    if (tid < 16) m2_s[tid] = mlp2_w[tid];
    __syncthreads();
    const int ti = tid >> 4, tj = tid & 15;
    const int i = bi + ti;
    float uf[16];
    #pragma unroll
    for (int k = 0; k < 16; k++) uf[k] = Uf[(size_t)i*16 + k];
    float dot = 0.f;
    #pragma unroll
    for (int e = 0; e < 64; e++) dot += zf_s[ti][e] * zc_s[tj][e];
    float sacc = mlp2_b[0];
    #pragma unroll
    for (int k = 0; k < 16; k++) sacc += m2_s[k] * fast_tanh(uf[k] + uc_s[tj][k]);
    float w = 1.f / (1.f + __expf(-fminf(fmaxf(sacc, -30.f), 30.f)));
    float contrib = __expf(2.f * dot) * w;
    #pragma unroll
    for (int off = 8; off > 0; off >>= 1)
        contrib += __shfl_down_sync(0xffffffffu, contrib, off, 16);
    if (tj == 0) part[(size_t)blockIdx.x * Ndim + i] = contrib;
}

__global__ void loss_kernel(const float* __restrict__ part, const float* __restrict__ diag,
                            float* __restrict__ out)
{
    __shared__ float red[256];
    const int tid = threadIdx.x;
    float s = 0.f;
    for (int i = tid; i < Ndim; i += 256) {
        float d = 0.f;
        for (int b = 0; b < 64; b++) d += part[(size_t)b * Ndim + i];
        s += logf(d) - diag[i];
    }
    red[tid] = s;
    __syncthreads();
    for (int st = 128; st > 0; st >>= 1) {
        if (tid < st) red[tid] += red[tid + st];
        __syncthreads();
    }
    if (tid == 0) out[0] = red[0] / (float)Ndim;
}

// ---------------- host ----------------
static float* devptr(const void* sym) {
    void* p = nullptr;
    cudaGetSymbolAddress(&p, sym);
    return (float*)p;
}
static __nv_bfloat16* devptrb(const void* sym) {
    void* p = nullptr;
    cudaGetSymbolAddress(&p, sym);
    return (__nv_bfloat16*)p;
}

extern "C" void kernel_launch(void* const* d_in, const int* in_sizes, int n_in,
                              void* d_out, int out_size)
{
    const float* feat0     = (const float*)d_in[0];
    const float* feat1     = (const float*)d_in[1];
    const float* feat2     = (const float*)d_in[2];
    const float* mask_feat = (const float*)d_in[3];
    const float* nei0      = (const float*)d_in[4];
    const float* nei1      = (const float*)d_in[5];
    const float* adj0      = (const float*)d_in[6];
    const float* adj1      = (const float*)d_in[7];
    const float* madj0     = (const float*)d_in[8];
    const float* madj1     = (const float*)d_in[9];
    const float* fc0_w     = (const float*)d_in[10];
    const float* fc0_b     = (const float*)d_in[11];
    const float* fc1_w     = (const float*)d_in[12];
    const float* fc1_b     = (const float*)d_in[13];
    const float* fc2_w     = (const float*)d_in[14];
    const float* fc2_b     = (const float*)d_in[15];
    const float* agg0_w    = (const float*)d_in[16];
    const float* agg1_w    = (const float*)d_in[17];
    const float* gcn_w1    = (const float*)d_in[18];
    const float* gcn_b1    = (const float*)d_in[19];
    const float* gcn_w2    = (const float*)d_in[20];
    const float* gcn_b2    = (const float*)d_in[21];
    const float* att_w     = (const float*)d_in[22];
    const float* att_b     = (const float*)d_in[23];
    const float* att_vec   = (const float*)d_in[24];
    const float* proj_w    = (const float*)d_in[25];
    const float* proj_b    = (const float*)d_in[26];
    const float* mlp1_w    = (const float*)d_in[27];
    const float* mlp1_b    = (const float*)d_in[28];
    const float* mlp2_w    = (const float*)d_in[29];
    const float* mlp2_b    = (const float*)d_in[30];

    float* h_tar  = devptr(g_h_tar);
    float* h_mask = devptr(g_h_mask);
    float* h_nei0 = devptr(g_h_nei0);
    float* h_nei1 = devptr(g_h_nei1);
    float* views0 = devptr(g_views0);
    float* views1 = devptr(g_views1);
    float* masks0 = devptr(g_masks0);
    float* masks1 = devptr(g_masks1);
    float* xw_all = devptr(g_xw_all);
    float* h1_all = devptr(g_h1_all);
    float* hw_all = devptr(g_hw_all);
    float* z_all  = devptr(g_z_all);
    float* epart  = devptr(g_epart);
    float* beta   = devptr(g_beta);
    float* zfine  = devptr(g_zfine);
    float* z2     = devptr(g_z2);
    float* Uf     = devptr(g_Uf);
    float* Uc     = devptr(g_Uc);
    float* diag   = devptr(g_diag);
    float* part   = devptr(g_part);

    __nv_bfloat16 *f0h = devptrb(g_feat0_h), *f0l = devptrb(g_feat0_l);
    __nv_bfloat16 *mkh = devptrb(g_mask_h),  *mkl = devptrb(g_mask_l);
    __nv_bfloat16 *f1h = devptrb(g_feat1_h), *f1l = devptrb(g_feat1_l);
    __nv_bfloat16 *f2h = devptrb(g_feat2_h), *f2l = devptrb(g_feat2_l);
    __nv_bfloat16 *w0h = devptrb(g_fc0w_h),  *w0l = devptrb(g_fc0w_l);
    __nv_bfloat16 *w1h = devptrb(g_fc1w_h),  *w1l = devptrb(g_fc1w_l);
    __nv_bfloat16 *w2h = devptrb(g_fc2w_h),  *w2l = devptrb(g_fc2w_l);
    __nv_bfloat16 *a0h = devptrb(g_ag0w_h),  *a0l = devptrb(g_ag0w_l);
    __nv_bfloat16 *a1h = devptrb(g_ag1w_h),  *a1l = devptrb(g_ag1w_l);
    __nv_bfloat16 *g0h = devptrb(g_agg0_h),  *g0l = devptrb(g_agg0_l);
    __nv_bfloat16 *g1h = devptrb(g_agg1_h),  *g1l = devptrb(g_agg1_l);

    const int NE = Ndim * Edim;

    // ---- split all static fp32 operands into bf16 hi/lo planes ----
    {
        SJobs js;
        js.j[0] = { feat0,     f0h, f0l, (Ndim*D0)/4 };
        js.j[1] = { mask_feat, mkh, mkl, (Ndim*D0)/4 };
        js.j[2] = { feat1,     f1h, f1l, (Mdim*D1)/4 };
        js.j[3] = { feat2,     f2h, f2l, (Mdim*D1)/4 };
        js.j[4] = { fc0_w,     w0h, w0l, (D0*Hdim)/4 };
        js.j[5] = { fc1_w,     w1h, w1l, (D1*Hdim)/4 };
        js.j[6] = { fc2_w,     w2h, w2l, (D1*Hdim)/4 };
        js.j[7] = { agg0_w,    a0h, a0l, (Hdim*Hdim)/4 };
        js.j[8] = { agg1_w,    a1h, a1l, (Hdim*Hdim)/4 };
        split_kernel<<<dim3(256, 9), 256>>>(js);
    }

    // ---- encoders via HMMA (one segmented launch) ----
    {
        SegsH sgs;
        sgs.nseg = 4;
        sgs.s[0] = { f0h, f0l, w0h, w0l, fc0_b, h_tar,  nullptr, D0, 8  };
        sgs.s[1] = { mkh, mkl, w0h, w0l, fc0_b, h_mask, nullptr, D0, 16 };
        sgs.s[2] = { f1h, f1l, w1h, w1l, fc1_b, h_nei0, nullptr, D1, 48 };
        sgs.s[3] = { f2h, f2l, w2h, w2l, fc2_b, h_nei1, nullptr, D1, 80 };
        hmma_gemm<1><<<dim3(Hdim/128, 80), 256>>>(sgs, Hdim, nullptr, nullptr);
    }

    // ---- neighbor mean aggregation -> bf16 planes ----
    spmm_scan_kernel<<<Ndim, 256>>>(nei0, h_nei0, g0h, g0l, Mdim, Hdim);
    spmm_scan_kernel<<<Ndim, 256>>>(nei1, h_nei1, g1h, g1l, Mdim, Hdim);

    // ---- agg GEMMs (HMMA) with fused views/masks epilogue ----
    {
        SegsH sgs;
        sgs.nseg = 2;
        sgs.s[0] = { g0h, g0l, a0h, a0l, nullptr, views0, masks0, Hdim, 8  };
        sgs.s[1] = { g1h, g1l, a1h, a1l, nullptr, views1, masks1, Hdim, 16 };
        sgs.s[2] = sgs.s[1]; sgs.s[3] = sgs.s[1];
        hmma_gemm<2><<<dim3(Hdim/128, 16), 256>>>(sgs, Hdim, h_tar, h_mask);
    }

    // ---- GCN stage A: xw = X @ gcn_w1 ----
    {
        In5 ins = {{ h_tar, views0, masks0, views1, masks1 }};
        gemm_small<0><<<5*32, 128>>>(ins, gcn_w1, nullptr, xw_all, Hdim, 32);
    }
    // ---- GCN stage B: h1 = relu(adj @ xw + b1) ----
    {
        Adj4 oth = {{ adj0, madj0, adj1, madj1 }};
        gcn_spmm_kernel<<<dim3(Ndim, 5), 64>>>(adj0, adj1, oth, xw_all, gcn_b1, h1_all, 1, 0);
    }
    // ---- GCN stage C: hw = h1 @ gcn_w2 ----
    {
        In5 ins = {{ h1_all, h1_all + NE, h1_all + 2*NE, h1_all + 3*NE, h1_all + 4*NE }};
        gemm_small<0><<<5*32, 128>>>(ins, gcn_w2, nullptr, hw_all, Edim, 32);
    }
    // ---- GCN stage D: z = adj @ hw + b2, fused l2norm for views ----
    {
        Adj4 oth = {{ adj0, madj0, adj1, madj1 }};
        gcn_spmm_kernel<<<dim3(Ndim, 5), 64>>>(adj0, adj1, oth, hw_all, gcn_b2, z_all, 0, 1);
    }

    // ---- semantic attention over (already normalized) hs, z_fine ----
    float* hs = z_all + NE;
    att_kernel<<<dim3(4,4), 256>>>(hs, att_w, att_b, att_vec, epart);
    beta_kernel<<<1, 1>>>(epart, beta);
    zfine_kernel<<<(NE + 255)/256, 256>>>(hs, beta, zfine, NE);

    // ---- projections ----
    {
        In5 ins = {{ z_all, zfine, zfine, zfine, zfine }};
        gemm_small<3><<<2*32, 128>>>(ins, proj_w, proj_b, z2, Edim, 32);
    }
    l2norm_kernel<<<(2*Ndim)/8, 256>>>(z2, 2*Ndim);
    float* zc = z2;
    float* zf = z2 + NE;

    // ---- weighted InfoNCE ----
    u_diag_kernel<<<Ndim/16, 256>>>(zf, zc, mlp1_w, mlp1_b, Uf, Uc, diag);
    pair_kernel<<<dim3(64, 64), 256>>>(zf, zc, Uf, Uc, mlp2_w, mlp2_b, part);
    loss_kernel<<<1, 256>>>(part, diag, (float*)d_out);
}

// round 8
// speedup vs baseline: 2.7120x; 1.2977x over previous
#include <cuda_runtime.h>
#include <cuda_bf16.h>
#include <math.h>
#include <stdint.h>
#include <stddef.h>

#define Ndim 1024
#define Mdim 4096
#define D0 1024
#define D1 512
#define Hdim 512
#define Edim 64

typedef unsigned long long ull;
typedef __nv_bfloat16 bf16;

// ---------------- scratch (device globals; no allocation allowed) ----------------
__device__ float g_h_tar[Ndim*Hdim];
__device__ float g_h_mask[Ndim*Hdim];
__device__ float g_h_nei0[Mdim*Hdim];
__device__ float g_h_nei1[Mdim*Hdim];
__device__ float g_xw_all[5*Ndim*Edim];
__device__ float g_h1_all[5*Ndim*Edim];
__device__ float g_hw_all[5*Ndim*Edim];
__device__ float g_z_all[5*Ndim*Edim];
__device__ float g_epart[16];
__device__ float g_beta[4];
__device__ float g_zfine[Ndim*Edim];
__device__ float g_z2[2*Ndim*Edim];
__device__ float g_Uf[Ndim*16];
__device__ float g_Uc[Ndim*16];
__device__ float g_diag[Ndim];
__device__ float g_part[64*Ndim];

// bf16 hi/lo planes
__device__ bf16 g_feat0_h[Ndim*D0],  g_feat0_l[Ndim*D0];
__device__ bf16 g_mask_h[Ndim*D0],   g_mask_l[Ndim*D0];
__device__ bf16 g_feat1_h[Mdim*D1],  g_feat1_l[Mdim*D1];
__device__ bf16 g_feat2_h[Mdim*D1],  g_feat2_l[Mdim*D1];
__device__ bf16 g_fc0w_h[D0*Hdim],   g_fc0w_l[D0*Hdim];
__device__ bf16 g_fc1w_h[D1*Hdim],   g_fc1w_l[D1*Hdim];
__device__ bf16 g_fc2w_h[D1*Hdim],   g_fc2w_l[D1*Hdim];
__device__ bf16 g_ag0w_h[Hdim*Hdim], g_ag0w_l[Hdim*Hdim];
__device__ bf16 g_ag1w_h[Hdim*Hdim], g_ag1w_l[Hdim*Hdim];
__device__ bf16 g_w1_h[Hdim*Edim],   g_w1_l[Hdim*Edim];
__device__ bf16 g_agg0_h[Ndim*Hdim], g_agg0_l[Ndim*Hdim];
__device__ bf16 g_agg1_h[Ndim*Hdim], g_agg1_l[Ndim*Hdim];
// stacked GCN input planes: slice0=h_tar, 1=views0, 2=masks0, 3=views1, 4=masks1
__device__ bf16 g_X5h[5*Ndim*Hdim], g_X5l[5*Ndim*Hdim];

__device__ __forceinline__ float eluf(float x){ return x > 0.f ? x : expm1f(x); }
__device__ __forceinline__ float fast_tanh(float x){
    x = fminf(fmaxf(x, -20.f), 20.f);
    float e = __expf(2.f*x);
    return __fdividef(e - 1.f, e + 1.f);
}
__device__ __forceinline__ ull dup2(float x){
    ull r; asm("mov.b64 %0, {%1, %1};" : "=l"(r) : "f"(x)); return r;
}
__device__ __forceinline__ ull fma2(ull a, ull b, ull c){
    ull d; asm("fma.rn.f32x2 %0, %1, %2, %3;" : "=l"(d) : "l"(a), "l"(b), "l"(c)); return d;
}
__device__ __forceinline__ void unpack2(ull v, float& lo, float& hi){
    asm("mov.b64 {%0, %1}, %2;" : "=f"(lo), "=f"(hi) : "l"(v));
}
__device__ __forceinline__ uint32_t smem_u32(const void* p){
    uint32_t r;
    asm("{ .reg .u64 t; cvta.to.shared.u64 t, %1; cvt.u32.u64 %0, t; }" : "=r"(r) : "l"(p));
    return r;
}
__device__ __forceinline__ void ldmA4(uint32_t* r, uint32_t addr){
    asm volatile("ldmatrix.sync.aligned.m8n8.x4.shared.b16 {%0,%1,%2,%3}, [%4];"
        : "=r"(r[0]),"=r"(r[1]),"=r"(r[2]),"=r"(r[3]) : "r"(addr));
}
__device__ __forceinline__ void ldmBT4(uint32_t* r, uint32_t addr){
    asm volatile("ldmatrix.sync.aligned.m8n8.x4.trans.shared.b16 {%0,%1,%2,%3}, [%4];"
        : "=r"(r[0]),"=r"(r[1]),"=r"(r[2]),"=r"(r[3]) : "r"(addr));
}
__device__ __forceinline__ void mma_bf16(float* d, const uint32_t* a, const uint32_t* b){
    asm volatile("mma.sync.aligned.m16n8k16.row.col.f32.bf16.bf16.f32 "
        "{%0,%1,%2,%3}, {%4,%5,%6,%7}, {%8,%9}, {%0,%1,%2,%3};"
        : "+f"(d[0]),"+f"(d[1]),"+f"(d[2]),"+f"(d[3])
        : "r"(a[0]),"r"(a[1]),"r"(a[2]),"r"(a[3]), "r"(b[0]),"r"(b[1]));
}
__device__ __forceinline__ void store_split2(float v0, float v1, bf16* H, bf16* L, size_t idx){
    bf16 h0 = __float2bfloat16(v0), h1 = __float2bfloat16(v1);
    bf16 l0 = __float2bfloat16(v0 - __bfloat162float(h0));
    bf16 l1 = __float2bfloat16(v1 - __bfloat162float(h1));
    __nv_bfloat162 hh; hh.x = h0; hh.y = h1;
    __nv_bfloat162 ll; ll.x = l0; ll.y = l1;
    *(__nv_bfloat162*)&H[idx] = hh;
    *(__nv_bfloat162*)&L[idx] = ll;
}

// ---------------- split: fp32 -> bf16 hi/lo planes ----------------
struct SJob { const float* s; bf16* h; bf16* l; int n4; };
struct SJobs { SJob j[10]; };

__global__ __launch_bounds__(256) void split_kernel(SJobs jobs)
{
    SJob jb = jobs.j[blockIdx.y];
    const int stride = gridDim.x * blockDim.x;
    for (int i = blockIdx.x * blockDim.x + threadIdx.x; i < jb.n4; i += stride) {
        float4 v = ((const float4*)jb.s)[i];
        bf16 h0 = __float2bfloat16(v.x);
        bf16 h1 = __float2bfloat16(v.y);
        bf16 h2 = __float2bfloat16(v.z);
        bf16 h3 = __float2bfloat16(v.w);
        bf16 l0 = __float2bfloat16(v.x - __bfloat162float(h0));
        bf16 l1 = __float2bfloat16(v.y - __bfloat162float(h1));
        bf16 l2 = __float2bfloat16(v.z - __bfloat162float(h2));
        bf16 l3 = __float2bfloat16(v.w - __bfloat162float(h3));
        ushort4 H, L;
        H.x = __bfloat16_as_ushort(h0); H.y = __bfloat16_as_ushort(h1);
        H.z = __bfloat16_as_ushort(h2); H.w = __bfloat16_as_ushort(h3);
        L.x = __bfloat16_as_ushort(l0); L.y = __bfloat16_as_ushort(l1);
        L.z = __bfloat16_as_ushort(l2); L.w = __bfloat16_as_ushort(l3);
        ((ushort4*)jb.h)[i] = H;
        ((ushort4*)jb.l)[i] = L;
    }
}

// ================= HMMA GEMM: bf16-split 3-product, reg-prefetch =================
// BM=128, BN=128, BK=32, 256 threads (8 warps: 2m x 4n), warp tile 64x32.
// EPI 1: C=elu(v+bias) fp32, optional split planes Bh/Bl.
// EPI 2: planes Bh/Bl = split(elu(aux0+v)), B2h/B2l = split(elu(aux1+v)). No fp32 out.
struct SegH { const bf16 *Ah, *Al, *Wh, *Wl; const float* bias;
              float* C; bf16 *Bh, *Bl, *B2h, *B2l; int K; int tileEnd; };
struct SegsH { SegH s[4]; int nseg; };

template<int EPI>
__global__ __launch_bounds__(256) void hmma_gemm(
    SegsH segs, int Nd, const float* __restrict__ aux0, const float* __restrict__ aux1)
{
    __shared__ __align__(16) bf16 Ah_s[128][40];
    __shared__ __align__(16) bf16 Al_s[128][40];
    __shared__ __align__(16) bf16 Wh_s[32][136];
    __shared__ __align__(16) bf16 Wl_s[32][136];

    const int tid = threadIdx.x;
    const int by  = blockIdx.y;
    int si = 0, tileStart = 0;
    #pragma unroll
    for (int i = 0; i < 3; i++)
        if (i < segs.nseg && by >= segs.s[i].tileEnd) { si = i + 1; tileStart = segs.s[i].tileEnd; }
    const SegH sg = segs.s[si];
    const int K  = sg.K;
    const int bm = (by - tileStart) * 128;
    const int bn = blockIdx.x * 128;

    const int lane = tid & 31;
    const int w    = tid >> 5;
    const int wm   = w >> 2;
    const int wn   = w & 3;

    const int arow = tid >> 1;
    const int aseg = (tid & 1) * 16;
    const int krow = tid >> 3;
    const int nsg  = (tid & 7) * 16;

    const uint32_t aBaseH = smem_u32(&Ah_s[0][0]);
    const uint32_t aBaseL = smem_u32(&Al_s[0][0]);
    const uint32_t wBaseH = smem_u32(&Wh_s[0][0]);
    const uint32_t wBaseL = smem_u32(&Wl_s[0][0]);
    const uint32_t aoff = ((wm*64 + (lane & 15)) * 40 + (lane >> 4) * 8) * 2;
    const uint32_t boff = ((lane & 15) * 136 + wn*32 + (lane >> 4) * 8) * 2;

    const bf16* Agh = sg.Ah + (size_t)(bm + arow) * K + aseg;
    const bf16* Agl = sg.Al + (size_t)(bm + arow) * K + aseg;
    const bf16* Wgh = sg.Wh + (size_t)krow * Nd + bn + nsg;
    const bf16* Wgl = sg.Wl + (size_t)krow * Nd + bn + nsg;

    float d[4][4][4];
    #pragma unroll
    for (int mt = 0; mt < 4; mt++)
        #pragma unroll
        for (int nt = 0; nt < 4; nt++)
            #pragma unroll
            for (int q = 0; q < 4; q++) d[mt][nt][q] = 0.f;

    const int nk = K >> 5;

    // prologue: load tile 0 into regs, store to smem
    uint4 ah0 = *(const uint4*)(Agh);     uint4 ah1 = *(const uint4*)(Agh + 8);
    uint4 al0 = *(const uint4*)(Agl);     uint4 al1 = *(const uint4*)(Agl + 8);
    uint4 wh0 = *(const uint4*)(Wgh);     uint4 wh1 = *(const uint4*)(Wgh + 8);
    uint4 wl0 = *(const uint4*)(Wgl);     uint4 wl1 = *(const uint4*)(Wgl + 8);
    *(uint4*)&Ah_s[arow][aseg]   = ah0;  *(uint4*)&Ah_s[arow][aseg+8] = ah1;
    *(uint4*)&Al_s[arow][aseg]   = al0;  *(uint4*)&Al_s[arow][aseg+8] = al1;
    *(uint4*)&Wh_s[krow][nsg]    = wh0;  *(uint4*)&Wh_s[krow][nsg+8]  = wh1;
    *(uint4*)&Wl_s[krow][nsg]    = wl0;  *(uint4*)&Wl_s[krow][nsg+8]  = wl1;
    __syncthreads();

    for (int t = 0; t < nk; t++) {
        const bool has = (t + 1 < nk);
        if (has) {
            const int k0 = (t + 1) * 32;
            ah0 = *(const uint4*)(Agh + k0);     ah1 = *(const uint4*)(Agh + k0 + 8);
            al0 = *(const uint4*)(Agl + k0);     al1 = *(const uint4*)(Agl + k0 + 8);
            wh0 = *(const uint4*)(Wgh + (size_t)k0 * Nd);  wh1 = *(const uint4*)(Wgh + (size_t)k0 * Nd + 8);
            wl0 = *(const uint4*)(Wgl + (size_t)k0 * Nd);  wl1 = *(const uint4*)(Wgl + (size_t)k0 * Nd + 8);
        }
        #pragma unroll
        for (int ks = 0; ks < 2; ks++) {
            uint32_t ah[4][4], al[4][4];
            #pragma unroll
            for (int mt = 0; mt < 4; mt++) {
                const uint32_t o = aoff + (mt * 16 * 40 + ks * 16) * 2;
                ldmA4(ah[mt], aBaseH + o);
                ldmA4(al[mt], aBaseL + o);
            }
            uint32_t bh[2][4], bl[2][4];
            #pragma unroll
            for (int np = 0; np < 2; np++) {
                const uint32_t o = boff + (ks * 16 * 136 + np * 16) * 2;
                ldmBT4(bh[np], wBaseH + o);
                ldmBT4(bl[np], wBaseL + o);
            }
            #pragma unroll
            for (int mt = 0; mt < 4; mt++) {
                #pragma unroll
                for (int nt = 0; nt < 4; nt++) {
                    const uint32_t* bph = &bh[nt >> 1][(nt & 1) * 2];
                    const uint32_t* bpl = &bl[nt >> 1][(nt & 1) * 2];
                    mma_bf16(d[mt][nt], al[mt], bph);
                    mma_bf16(d[mt][nt], ah[mt], bpl);
                    mma_bf16(d[mt][nt], ah[mt], bph);
                }
            }
        }
        if (has) {
            __syncthreads();
            *(uint4*)&Ah_s[arow][aseg]   = ah0;  *(uint4*)&Ah_s[arow][aseg+8] = ah1;
            *(uint4*)&Al_s[arow][aseg]   = al0;  *(uint4*)&Al_s[arow][aseg+8] = al1;
            *(uint4*)&Wh_s[krow][nsg]    = wh0;  *(uint4*)&Wh_s[krow][nsg+8]  = wh1;
            *(uint4*)&Wl_s[krow][nsg]    = wl0;  *(uint4*)&Wl_s[krow][nsg+8]  = wl1;
            __syncthreads();
        }
    }

    // epilogue
    const int g  = lane >> 2;
    const int tq = lane & 3;
    #pragma unroll
    for (int mt = 0; mt < 4; mt++) {
        #pragma unroll
        for (int nt = 0; nt < 4; nt++) {
            const int r = bm + wm*64 + mt*16 + g;
            const int c = bn + wn*32 + nt*8 + tq*2;
            #pragma unroll
            for (int half = 0; half < 2; half++) {
                const int rr = r + half * 8;
                float v0 = d[mt][nt][half*2 + 0];
                float v1 = d[mt][nt][half*2 + 1];
                const size_t idx = (size_t)rr * Nd + c;
                if (EPI == 1) {
                    v0 = eluf(v0 + sg.bias[c]); v1 = eluf(v1 + sg.bias[c+1]);
                    *(float2*)&sg.C[idx] = make_float2(v0, v1);
                    if (sg.Bh) store_split2(v0, v1, sg.Bh, sg.Bl, idx);
                } else if (EPI == 2) {
                    float2 a0 = *(const float2*)&aux0[idx];
                    float2 a1 = *(const float2*)&aux1[idx];
                    store_split2(eluf(a0.x + v0), eluf(a0.y + v1), sg.Bh,  sg.Bl,  idx);
                    store_split2(eluf(a1.x + v0), eluf(a1.y + v1), sg.B2h, sg.B2l, idx);
                }
            }
        }
    }
}

// ================= hmma_gemm64: stacked GCN stage A, M=5120 N=64 K=512 ============
// BM=64, BN=64, BK=32, 256 threads (8 warps: 4m x 2n), warp tile 16x32.
__global__ __launch_bounds__(256) void hmma_gemm64(
    const bf16* __restrict__ Ah, const bf16* __restrict__ Al,
    const bf16* __restrict__ Wh, const bf16* __restrict__ Wl,
    float* __restrict__ out)
{
    __shared__ __align__(16) bf16 Ah_s[64][40];
    __shared__ __align__(16) bf16 Al_s[64][40];
    __shared__ __align__(16) bf16 Wh_s[32][72];
    __shared__ __align__(16) bf16 Wl_s[32][72];

    const int tid = threadIdx.x;
    const int bm = blockIdx.x * 64;
    const int lane = tid & 31;
    const int w    = tid >> 5;
    const int wm   = w >> 1;    // 0..3
    const int wn   = w & 1;     // 0..1

    const int arow = tid >> 2;          // 0..63
    const int acol = (tid & 3) * 8;     // 0..24
    const int krow = tid >> 3;          // 0..31
    const int ncol = (tid & 7) * 8;     // 0..56

    const uint32_t aBaseH = smem_u32(&Ah_s[0][0]);
    const uint32_t aBaseL = smem_u32(&Al_s[0][0]);
    const uint32_t wBaseH = smem_u32(&Wh_s[0][0]);
    const uint32_t wBaseL = smem_u32(&Wl_s[0][0]);
    const uint32_t aoff = ((wm*16 + (lane & 15)) * 40 + (lane >> 4) * 8) * 2;
    const uint32_t boff = ((lane & 15) * 72 + wn*32 + (lane >> 4) * 8) * 2;

    const bf16* Agh = Ah + (size_t)(bm + arow) * Hdim + acol;
    const bf16* Agl = Al + (size_t)(bm + arow) * Hdim + acol;
    const bf16* Wgh = Wh + (size_t)krow * Edim + ncol;
    const bf16* Wgl = Wl + (size_t)krow * Edim + ncol;

    float d[4][4];
    #pragma unroll
    for (int nt = 0; nt < 4; nt++)
        #pragma unroll
        for (int q = 0; q < 4; q++) d[nt][q] = 0.f;

    const int nk = Hdim >> 5;   // 16

    uint4 aH = *(const uint4*)(Agh);
    uint4 aL = *(const uint4*)(Agl);
    uint4 wH = *(const uint4*)(Wgh);
    uint4 wL = *(const uint4*)(Wgl);
    *(uint4*)&Ah_s[arow][acol] = aH;
    *(uint4*)&Al_s[arow][acol] = aL;
    *(uint4*)&Wh_s[krow][ncol] = wH;
    *(uint4*)&Wl_s[krow][ncol] = wL;
    __syncthreads();

    for (int t = 0; t < nk; t++) {
        const bool has = (t + 1 < nk);
        if (has) {
            const int k0 = (t + 1) * 32;
            aH = *(const uint4*)(Agh + k0);
            aL = *(const uint4*)(Agl + k0);
            wH = *(const uint4*)(Wgh + (size_t)k0 * Edim);
            wL = *(const uint4*)(Wgl + (size_t)k0 * Edim);
        }
        #pragma unroll
        for (int ks = 0; ks < 2; ks++) {
            uint32_t ah[4], al[4];
            {
                const uint32_t o = aoff + (ks * 16) * 2;
                ldmA4(ah, aBaseH + o);
                ldmA4(al, aBaseL + o);
            }
            uint32_t bh[2][4], bl[2][4];
            #pragma unroll
            for (int np = 0; np < 2; np++) {
                const uint32_t o = boff + (ks * 16 * 72 + np * 16) * 2;
                ldmBT4(bh[np], wBaseH + o);
                ldmBT4(bl[np], wBaseL + o);
            }
            #pragma unroll
            for (int nt = 0; nt < 4; nt++) {
                const uint32_t* bph = &bh[nt >> 1][(nt & 1) * 2];
                const uint32_t* bpl = &bl[nt >> 1][(nt & 1) * 2];
                mma_bf16(d[nt], al, bph);
                mma_bf16(d[nt], ah, bpl);
                mma_bf16(d[nt], ah, bph);
            }
        }
        if (has) {
            __syncthreads();
            *(uint4*)&Ah_s[arow][acol] = aH;
            *(uint4*)&Al_s[arow][acol] = aL;
            *(uint4*)&Wh_s[krow][ncol] = wH;
            *(uint4*)&Wl_s[krow][ncol] = wL;
            __syncthreads();
        }
    }

    const int g  = lane >> 2;
    const int tq = lane & 3;
    #pragma unroll
    for (int nt = 0; nt < 4; nt++) {
        #pragma unroll
        for (int half = 0; half < 2; half++) {
            const int rr = bm + wm*16 + g + half*8;
            const int c  = wn*32 + nt*8 + tq*2;
            *(float2*)&out[(size_t)rr * Edim + c] =
                make_float2(d[nt][half*2 + 0], d[nt][half*2 + 1]);
        }
    }
}

// ================= small GEMM: N=64, batched over 5 inputs, f32x2 =================
struct In5 { const float* p[5]; };

template<int ACT>
__global__ __launch_bounds__(128) void gemm_small(
    In5 ins, const float* __restrict__ W, const float* __restrict__ bias,
    float* __restrict__ out, int K, int tilesPer)
{
    __shared__ __align__(16) float As[16][32];
    __shared__ __align__(16) float Bs[16][64];
    const int tid = threadIdx.x;
    const int g  = blockIdx.x / tilesPer;
    const int tb = blockIdx.x % tilesPer;
    const float* A = ins.p[g] + (size_t)tb * 32 * K;
    float* C = out + ((size_t)g * tilesPer * 32 + tb * 32) * 64;

    const int tx = tid & 15;
    const int ty = tid >> 4;
    const int ar = tid >> 2, akc = (tid & 3) * 4;
    const int br = tid >> 4, bc = (tid & 15) * 4;

    ull acc[4][2];
    #pragma unroll
    for (int i = 0; i < 4; i++) { acc[i][0] = 0ull; acc[i][1] = 0ull; }

    for (int k0 = 0; k0 < K; k0 += 16) {
        float4 av  = *(const float4*)(A + (size_t)ar * K + k0 + akc);
        float4 bv0 = *(const float4*)(W + (size_t)(k0 + br) * 64 + bc);
        float4 bv1 = *(const float4*)(W + (size_t)(k0 + br + 8) * 64 + bc);
        __syncthreads();
        As[akc+0][ar] = av.x; As[akc+1][ar] = av.y; As[akc+2][ar] = av.z; As[akc+3][ar] = av.w;
        *(float4*)&Bs[br][bc]   = bv0;
        *(float4*)&Bs[br+8][bc] = bv1;
        __syncthreads();
        #pragma unroll
        for (int kk = 0; kk < 16; kk++) {
            float4 av2 = *(const float4*)&As[kk][ty*4];
            ulonglong2 bp = *(const ulonglong2*)&Bs[kk][tx*4];
            ull a2[4] = {dup2(av2.x), dup2(av2.y), dup2(av2.z), dup2(av2.w)};
            #pragma unroll
            for (int i = 0; i < 4; i++) {
                acc[i][0] = fma2(a2[i], bp.x, acc[i][0]);
                acc[i][1] = fma2(a2[i], bp.y, acc[i][1]);
            }
        }
    }
    #pragma unroll
    for (int i = 0; i < 4; i++) {
        const int row = ty * 4 + i;
        #pragma unroll
        for (int j = 0; j < 2; j++) {
            float v0, v1; unpack2(acc[i][j], v0, v1);
            const int c = tx * 4 + 2 * j;
            if (bias) { v0 += bias[c]; v1 += bias[c+1]; }
            if (ACT == 3) { v0 = tanhf(v0); v1 = tanhf(v1); }
            *(float2*)&C[(size_t)row * 64 + c] = make_float2(v0, v1);
        }
    }
}

// ========== nei SpMM (mean over nnz) -> bf16 hi/lo planes; ballot compaction ======
__global__ __launch_bounds__(256) void spmm2_kernel(
    const float* __restrict__ nei0, const float* __restrict__ nei1,
    const float* __restrict__ X0, const float* __restrict__ X1,
    bf16* __restrict__ Y0h, bf16* __restrict__ Y0l,
    bf16* __restrict__ Y1h, bf16* __restrict__ Y1l)
{
    __shared__ int   s_idx[512];
    __shared__ float s_val[512];
    __shared__ int   warpTot[8];
    __shared__ int   warpBase[8];
    __shared__ int   s_tot;
    const int row = blockIdx.x;
    const int which = blockIdx.y;
    const float* A = which ? nei1 : nei0;
    const float* X = which ? X1 : X0;
    bf16* Yh = which ? Y1h : Y0h;
    bf16* Yl = which ? Y1l : Y0l;
    const int tid = threadIdx.x;
    const int lane = tid & 31;
    const int wrp  = tid >> 5;

    const float4* arow = (const float4*)(A + (size_t)row * Mdim);
    int base = 0;
    #pragma unroll
    for (int chunk = 0; chunk < 4; chunk++) {
        float4 v = arow[chunk * 256 + tid];
        int m = (v.x != 0.f ? 1 : 0) | (v.y != 0.f ? 2 : 0)
              | (v.z != 0.f ? 4 : 0) | (v.w != 0.f ? 8 : 0);
        int c = __popc(m);
        int incl = c;
        #pragma unroll
        for (int o = 1; o < 32; o <<= 1) {
            int n = __shfl_up_sync(0xffffffffu, incl, o);
            if (lane >= o) incl += n;
        }
        if (lane == 31) warpTot[wrp] = incl;
        __syncthreads();
        if (tid == 0) {
            int r = 0;
            #pragma unroll
            for (int i = 0; i < 8; i++) { warpBase[i] = r; r += warpTot[i]; }
            s_tot = r;
        }
        __syncthreads();
        int off = base + warpBase[wrp] + incl - c;
        const int colbase = (chunk * 256 + tid) * 4;
        if (m & 1) { if (off < 512) { s_idx[off] = colbase;     s_val[off] = v.x; } off++; }
        if (m & 2) { if (off < 512) { s_idx[off] = colbase + 1; s_val[off] = v.y; } off++; }
        if (m & 4) { if (off < 512) { s_idx[off] = colbase + 2; s_val[off] = v.z; } off++; }
        if (m & 8) { if (off < 512) { s_idx[off] = colbase + 3; s_val[off] = v.w; } off++; }
        base += s_tot;
        __syncthreads();
    }
    const int total = min(base, 512);
    const float inv = 1.f / fmaxf((float)base, 1.f);
    // gather: 256 threads x float2 = 512 cols
    const float2* Xp = (const float2*)X + tid;
    float2 acc = make_float2(0.f, 0.f);
    int t = 0;
    for (; t + 4 <= total; t += 4) {
        int i0 = s_idx[t], i1 = s_idx[t+1], i2 = s_idx[t+2], i3 = s_idx[t+3];
        float w0 = s_val[t], w1 = s_val[t+1], w2 = s_val[t+2], w3 = s_val[t+3];
        float2 x0 = Xp[(size_t)i0 * 256];
        float2 x1 = Xp[(size_t)i1 * 256];
        float2 x2 = Xp[(size_t)i2 * 256];
        float2 x3 = Xp[(size_t)i3 * 256];
        acc.x += w0*x0.x + w1*x1.x + w2*x2.x + w3*x3.x;
        acc.y += w0*x0.y + w1*x1.y + w2*x2.y + w3*x3.y;
    }
    for (; t < total; t++) {
        int i0 = s_idx[t]; float w0 = s_val[t];
        float2 x0 = Xp[(size_t)i0 * 256];
        acc.x += w0 * x0.x; acc.y += w0 * x0.y;
    }
    store_split2(acc.x * inv, acc.y * inv, Yh, Yl, (size_t)row * Hdim + tid * 2);
}

// ========== batched GCN SpMM (ballot); g==0 uses mean(adj0,adj1) on the fly ======
struct Adj4 { const float* a[4]; };
__global__ __launch_bounds__(64) void gcn_spmm_kernel(
    const float* __restrict__ adj0, const float* __restrict__ adj1, Adj4 others,
    const float* __restrict__ Xall, const float* __restrict__ bias,
    float* __restrict__ Yall, int relu, int donorm)
{
    __shared__ int   s_idx[512];
    __shared__ float s_val[512];
    __shared__ int   warpTot[2];
    __shared__ int   warpBase[2];
    __shared__ int   s_tot;
    __shared__ float s_sq[2];
    const int g   = blockIdx.y;
    const int row = blockIdx.x;
    const int tid = threadIdx.x;
    const int lane = tid & 31;
    const int wrp  = tid >> 5;
    const float* X = Xall + (size_t)g * Ndim * Edim;
    float* Y       = Yall + (size_t)g * Ndim * Edim;

    const float4* r0 = (const float4*)((g == 0 ? adj0 : others.a[g-1]) + (size_t)row * Ndim);
    const float4* r1 = (const float4*)(adj1 + (size_t)row * Ndim);

    int base = 0;
    #pragma unroll
    for (int chunk = 0; chunk < 4; chunk++) {
        float4 v = r0[chunk * 64 + tid];
        if (g == 0) {
            float4 v1 = r1[chunk * 64 + tid];
            v.x = 0.5f * (v.x + v1.x); v.y = 0.5f * (v.y + v1.y);
            v.z = 0.5f * (v.z + v1.z); v.w = 0.5f * (v.w + v1.w);
        }
        int m = (v.x != 0.f ? 1 : 0) | (v.y != 0.f ? 2 : 0)
              | (v.z != 0.f ? 4 : 0) | (v.w != 0.f ? 8 : 0);
        int c = __popc(m);
        int incl = c;
        #pragma unroll
        for (int o = 1; o < 32; o <<= 1) {
            int n = __shfl_up_sync(0xffffffffu, incl, o);
            if (lane >= o) incl += n;
        }
        if (lane == 31) warpTot[wrp] = incl;
        __syncthreads();
        if (tid == 0) {
            warpBase[0] = 0; warpBase[1] = warpTot[0];
            s_tot = warpTot[0] + warpTot[1];
        }
        __syncthreads();
        int off = base + warpBase[wrp] + incl - c;
        const int colbase = (chunk * 64 + tid) * 4;
        if (m & 1) { if (off < 512) { s_idx[off] = colbase;     s_val[off] = v.x; } off++; }
        if (m & 2) { if (off < 512) { s_idx[off] = colbase + 1; s_val[off] = v.y; } off++; }
        if (m & 4) { if (off < 512) { s_idx[off] = colbase + 2; s_val[off] = v.z; } off++; }
        if (m & 8) { if (off < 512) { s_idx[off] = colbase + 3; s_val[off] = v.w; } off++; }
        base += s_tot;
        __syncthreads();
    }
    const int total = min(base, 512);
    const int e = tid;
    float v = 0.f;
    int t = 0;
    for (; t + 4 <= total; t += 4) {
        int i0 = s_idx[t], i1 = s_idx[t+1], i2 = s_idx[t+2], i3 = s_idx[t+3];
        float w0 = s_val[t], w1 = s_val[t+1], w2 = s_val[t+2], w3 = s_val[t+3];
        v += w0 * X[(size_t)i0 * Edim + e] + w1 * X[(size_t)i1 * Edim + e]
           + w2 * X[(size_t)i2 * Edim + e] + w3 * X[(size_t)i3 * Edim + e];
    }
    for (; t < total; t++) v += s_val[t] * X[(size_t)s_idx[t] * Edim + e];
    v += bias[e];
    if (relu) v = fmaxf(v, 0.f);
    if (donorm && g > 0) {
        float sq = v * v;
        #pragma unroll
        for (int o = 16; o > 0; o >>= 1) sq += __shfl_xor_sync(0xffffffffu, sq, o);
        if (lane == 0) s_sq[wrp] = sq;
        __syncthreads();
        const float nrm = fmaxf(sqrtf(s_sq[0] + s_sq[1]), 1e-12f);
        v /= nrm;
    }
    Y[(size_t)row * Edim + e] = v;
}

// ---------------- elementwise / tail kernels ----------------
__global__ void l2norm_kernel(float* __restrict__ X, int rows)
{
    int w = (blockIdx.x * blockDim.x + threadIdx.x) >> 5;
    int lane = threadIdx.x & 31;
    if (w >= rows) return;
    float* r = X + (size_t)w * 64;
    float a = r[lane], b = r[lane + 32];
    float s = a*a + b*b;
    #pragma unroll
    for (int off = 16; off > 0; off >>= 1) s += __shfl_xor_sync(0xffffffffu, s, off);
    float nrm = fmaxf(sqrtf(s), 1e-12f);
    r[lane] = a / nrm; r[lane + 32] = b / nrm;
}

__global__ __launch_bounds__(256) void att_kernel(
    const float* __restrict__ hs, const float* __restrict__ att_w,
    const float* __restrict__ att_b, const float* __restrict__ att_vec,
    float* __restrict__ epart)
{
    __shared__ float w_s[64*64];
    __shared__ float b_s[64];
    __shared__ float v_s[64];
    __shared__ float red[256];
    const int tid = threadIdx.x;
    for (int i = tid; i < 64*64; i += 256) w_s[i] = att_w[i];
    if (tid < 64) { b_s[tid] = att_b[tid]; v_s[tid] = att_vec[tid]; }
    __syncthreads();
    const int v = blockIdx.y;
    const int n = blockIdx.x * 256 + tid;
    const float* row = hs + ((size_t)v * Ndim + n) * 64;
    float r[64];
    #pragma unroll
    for (int f = 0; f < 64; f++) r[f] = row[f];
    float s = 0.f;
    for (int e = 0; e < 64; e++) {
        float acc = b_s[e];
        #pragma unroll
        for (int f = 0; f < 64; f++) acc += r[f] * w_s[f*64 + e];
        s += v_s[e] * tanhf(acc);
    }
    red[tid] = s;
    __syncthreads();
    for (int st = 128; st > 0; st >>= 1) {
        if (tid < st) red[tid] += red[tid + st];
        __syncthreads();
    }
    if (tid == 0) epart[v*4 + blockIdx.x] = red[0];
}

__global__ void beta_kernel(const float* __restrict__ epart, float* __restrict__ beta)
{
    float e[4];
    float m = -1e30f;
    for (int v = 0; v < 4; v++) {
        e[v] = (epart[v*4+0] + epart[v*4+1] + epart[v*4+2] + epart[v*4+3]) / (float)Ndim;
        m = fmaxf(m, e[v]);
    }
    float s = 0.f;
    for (int v = 0; v < 4; v++) { float b = expf(e[v] - m); beta[v] = b; s += b; }
    for (int v = 0; v < 4; v++) beta[v] /= s;
}

__global__ void zfine_kernel(const float* __restrict__ hs, const float* __restrict__ beta,
                             float* __restrict__ zfine, int n)
{
    int i = blockIdx.x * blockDim.x + threadIdx.x;
    if (i < n) {
        float s = beta[0]*hs[i] + beta[1]*hs[(size_t)Ndim*Edim + i]
                + beta[2]*hs[(size_t)2*Ndim*Edim + i] + beta[3]*hs[(size_t)3*Ndim*Edim + i];
        zfine[i] = s;
    }
}

__global__ __launch_bounds__(256) void u_diag_kernel(
    const float* __restrict__ zf, const float* __restrict__ zc,
    const float* __restrict__ mlp1_w, const float* __restrict__ mlp1_b,
    float* __restrict__ Uf, float* __restrict__ Uc, float* __restrict__ diag)
{
    __shared__ float w_s[64*16];
    const int tid = threadIdx.x;
    for (int i = tid; i < 64*16; i += 256) w_s[i] = mlp1_w[i];
    __syncthreads();
    const int n = blockIdx.x * 16 + (tid >> 4);
    const int k = tid & 15;
    const float* zfr = zf + (size_t)n * 64;
    const float* zcr = zc + (size_t)n * 64;
    float af = 0.f, acr = 0.f;
    #pragma unroll
    for (int e = 0; e < 64; e++) {
        float w = w_s[e*16 + k];
        af  += zfr[e] * w;
        acr += zcr[e] * w;
    }
    Uf[(size_t)n*16 + k] = af + mlp1_b[k];
    Uc[(size_t)n*16 + k] = acr;
    float p = 0.f;
    #pragma unroll
    for (int e = 0; e < 4; e++) p += zfr[4*k + e] * zcr[4*k + e];
    #pragma unroll
    for (int o = 8; o > 0; o >>= 1) p += __shfl_down_sync(0xffffffffu, p, o, 16);
    if (k == 0) diag[n] = 2.f * p;
}

__global__ __launch_bounds__(256) void pair_kernel(
    const float* __restrict__ zf, const float* __restrict__ zc,
    const float* __restrict__ Uf, const float* __restrict__ Uc,
    const float* __restrict__ mlp2_w, const float* __restrict__ mlp2_b,
    float* __restrict__ part)
{
    __shared__ float zf_s[16][68];
    __shared__ float zc_s[16][68];
    __shared__ float uc_s[16][17];
    __shared__ float m2_s[16];
    const int tid = threadIdx.x;
    const int bi = blockIdx.y * 16;
    const int bj = blockIdx.x * 16;
    const int lr = tid >> 4, lc = (tid & 15) << 2;
    *(float4*)&zf_s[lr][lc] = *(const float4*)(zf + (size_t)(bi + lr) * 64 + lc);
    *(float4*)&zc_s[lr][lc] = *(const float4*)(zc + (size_t)(bj + lr) * 64 + lc);
    uc_s[tid >> 4][tid & 15] = Uc[(size_t)(bj + (tid >> 4)) * 16 + (tid & 15)];
    if (tid < 16) m2_s[tid] = mlp2_w[tid];
    __syncthreads();
    const int ti = tid >> 4, tj = tid & 15;
    const int i = bi + ti;
    float uf[16];
    #pragma unroll
    for (int k = 0; k < 16; k++) uf[k] = Uf[(size_t)i*16 + k];
    float dot = 0.f;
    #pragma unroll
    for (int e = 0; e < 64; e++) dot += zf_s[ti][e] * zc_s[tj][e];
    float sacc = mlp2_b[0];
    #pragma unroll
    for (int k = 0; k < 16; k++) sacc += m2_s[k] * fast_tanh(uf[k] + uc_s[tj][k]);
    float w = 1.f / (1.f + __expf(-fminf(fmaxf(sacc, -30.f), 30.f)));
    float contrib = __expf(2.f * dot) * w;
    #pragma unroll
    for (int off = 8; off > 0; off >>= 1)
        contrib += __shfl_down_sync(0xffffffffu, contrib, off, 16);
    if (tj == 0) part[(size_t)blockIdx.x * Ndim + i] = contrib;
}

__global__ void loss_kernel(const float* __restrict__ part, const float* __restrict__ diag,
                            float* __restrict__ out)
{
    __shared__ float red[256];
    const int tid = threadIdx.x;
    float s = 0.f;
    for (int i = tid; i < Ndim; i += 256) {
        float d = 0.f;
        for (int b = 0; b < 64; b++) d += part[(size_t)b * Ndim + i];
        s += logf(d) - diag[i];
    }
    red[tid] = s;
    __syncthreads();
    for (int st = 128; st > 0; st >>= 1) {
        if (tid < st) red[tid] += red[tid + st];
        __syncthreads();
    }
    if (tid == 0) out[0] = red[0] / (float)Ndim;
}

// ---------------- host ----------------
static float* devptr(const void* sym) {
    void* p = nullptr;
    cudaGetSymbolAddress(&p, sym);
    return (float*)p;
}
static bf16* devptrb(const void* sym) {
    void* p = nullptr;
    cudaGetSymbolAddress(&p, sym);
    return (bf16*)p;
}

extern "C" void kernel_launch(void* const* d_in, const int* in_sizes, int n_in,
                              void* d_out, int out_size)
{
    const float* feat0     = (const float*)d_in[0];
    const float* feat1     = (const float*)d_in[1];
    const float* feat2     = (const float*)d_in[2];
    const float* mask_feat = (const float*)d_in[3];
    const float* nei0      = (const float*)d_in[4];
    const float* nei1      = (const float*)d_in[5];
    const float* adj0      = (const float*)d_in[6];
    const float* adj1      = (const float*)d_in[7];
    const float* madj0     = (const float*)d_in[8];
    const float* madj1     = (const float*)d_in[9];
    const float* fc0_w     = (const float*)d_in[10];
    const float* fc0_b     = (const float*)d_in[11];
    const float* fc1_w     = (const float*)d_in[12];
    const float* fc1_b     = (const float*)d_in[13];
    const float* fc2_w     = (const float*)d_in[14];
    const float* fc2_b     = (const float*)d_in[15];
    const float* agg0_w    = (const float*)d_in[16];
    const float* agg1_w    = (const float*)d_in[17];
    const float* gcn_w1    = (const float*)d_in[18];
    const float* gcn_b1    = (const float*)d_in[19];
    const float* gcn_w2    = (const float*)d_in[20];
    const float* gcn_b2    = (const float*)d_in[21];
    const float* att_w     = (const float*)d_in[22];
    const float* att_b     = (const float*)d_in[23];
    const float* att_vec   = (const float*)d_in[24];
    const float* proj_w    = (const float*)d_in[25];
    const float* proj_b    = (const float*)d_in[26];
    const float* mlp1_w    = (const float*)d_in[27];
    const float* mlp1_b    = (const float*)d_in[28];
    const float* mlp2_w    = (const float*)d_in[29];
    const float* mlp2_b    = (const float*)d_in[30];

    float* h_tar  = devptr(g_h_tar);
    float* h_mask = devptr(g_h_mask);
    float* h_nei0 = devptr(g_h_nei0);
    float* h_nei1 = devptr(g_h_nei1);
    float* xw_all = devptr(g_xw_all);
    float* h1_all = devptr(g_h1_all);
    float* hw_all = devptr(g_hw_all);
    float* z_all  = devptr(g_z_all);
    float* epart  = devptr(g_epart);
    float* beta   = devptr(g_beta);
    float* zfine  = devptr(g_zfine);
    float* z2     = devptr(g_z2);
    float* Uf     = devptr(g_Uf);
    float* Uc     = devptr(g_Uc);
    float* diag   = devptr(g_diag);
    float* part   = devptr(g_part);

    bf16 *f0h = devptrb(g_feat0_h), *f0l = devptrb(g_feat0_l);
    bf16 *mkh = devptrb(g_mask_h),  *mkl = devptrb(g_mask_l);
    bf16 *f1h = devptrb(g_feat1_h), *f1l = devptrb(g_feat1_l);
    bf16 *f2h = devptrb(g_feat2_h), *f2l = devptrb(g_feat2_l);
    bf16 *w0h = devptrb(g_fc0w_h),  *w0l = devptrb(g_fc0w_l);
    bf16 *w1h = devptrb(g_fc1w_h),  *w1l = devptrb(g_fc1w_l);
    bf16 *w2h = devptrb(g_fc2w_h),  *w2l = devptrb(g_fc2w_l);
    bf16 *a0h = devptrb(g_ag0w_h),  *a0l = devptrb(g_ag0w_l);
    bf16 *a1h = devptrb(g_ag1w_h),  *a1l = devptrb(g_ag1w_l);
    bf16 *gw1h = devptrb(g_w1_h),   *gw1l = devptrb(g_w1_l);
    bf16 *g0h = devptrb(g_agg0_h),  *g0l = devptrb(g_agg0_l);
    bf16 *g1h = devptrb(g_agg1_h),  *g1l = devptrb(g_agg1_l);
    bf16 *X5h = devptrb(g_X5h),     *X5l = devptrb(g_X5l);

    const int NE = Ndim * Edim;
    const int NH = Ndim * Hdim;

    // ---- split all static fp32 operands into bf16 hi/lo planes ----
    {
        SJobs js;
        js.j[0] = { feat0,     f0h, f0l, (Ndim*D0)/4 };
        js.j[1] = { mask_feat, mkh, mkl, (Ndim*D0)/4 };
        js.j[2] = { feat1,     f1h, f1l, (Mdim*D1)/4 };
        js.j[3] = { feat2,     f2h, f2l, (Mdim*D1)/4 };
        js.j[4] = { fc0_w,     w0h, w0l, (D0*Hdim)/4 };
        js.j[5] = { fc1_w,     w1h, w1l, (D1*Hdim)/4 };
        js.j[6] = { fc2_w,     w2h, w2l, (D1*Hdim)/4 };
        js.j[7] = { agg0_w,    a0h, a0l, (Hdim*Hdim)/4 };
        js.j[8] = { agg1_w,    a1h, a1l, (Hdim*Hdim)/4 };
        js.j[9] = { gcn_w1,    gw1h, gw1l, (Hdim*Edim)/4 };
        split_kernel<<<dim3(128, 10), 256>>>(js);
    }

    // ---- encoders via HMMA; seg0 also emits X5 slice0 (h_tar planes) ----
    {
        SegsH sgs;
        sgs.nseg = 4;
        sgs.s[0] = { f0h, f0l, w0h, w0l, fc0_b, h_tar,  X5h, X5l, nullptr, nullptr, D0, 8  };
        sgs.s[1] = { mkh, mkl, w0h, w0l, fc0_b, h_mask, nullptr, nullptr, nullptr, nullptr, D0, 16 };
        sgs.s[2] = { f1h, f1l, w1h, w1l, fc1_b, h_nei0, nullptr, nullptr, nullptr, nullptr, D1, 48 };
        sgs.s[3] = { f2h, f2l, w2h, w2l, fc2_b, h_nei1, nullptr, nullptr, nullptr, nullptr, D1, 80 };
        hmma_gemm<1><<<dim3(Hdim/128, 80), 256>>>(sgs, Hdim, nullptr, nullptr);
    }

    // ---- neighbor mean aggregation (both matrices in one launch) ----
    spmm2_kernel<<<dim3(Ndim, 2), 256>>>(nei0, nei1, h_nei0, h_nei1, g0h, g0l, g1h, g1l);

    // ---- agg GEMMs (HMMA): emit views/masks planes into X5 slices 1..4 ----
    {
        SegsH sgs;
        sgs.nseg = 2;
        sgs.s[0] = { g0h, g0l, a0h, a0l, nullptr, nullptr,
                     X5h + 1*NH, X5l + 1*NH, X5h + 2*NH, X5l + 2*NH, Hdim, 8  };
        sgs.s[1] = { g1h, g1l, a1h, a1l, nullptr, nullptr,
                     X5h + 3*NH, X5l + 3*NH, X5h + 4*NH, X5l + 4*NH, Hdim, 16 };
        sgs.s[2] = sgs.s[1]; sgs.s[3] = sgs.s[1];
        hmma_gemm<2><<<dim3(Hdim/128, 16), 256>>>(sgs, Hdim, h_tar, h_mask);
    }

    // ---- GCN stage A: xw = X5 @ gcn_w1 (one stacked HMMA GEMM, M=5120) ----
    hmma_gemm64<<<5*Ndim/64, 256>>>(X5h, X5l, gw1h, gw1l, xw_all);

    // ---- GCN stage B: h1 = relu(adj @ xw + b1) ----
    {
        Adj4 oth = {{ adj0, madj0, adj1, madj1 }};
        gcn_spmm_kernel<<<dim3(Ndim, 5), 64>>>(adj0, adj1, oth, xw_all, gcn_b1, h1_all, 1, 0);
    }
    // ---- GCN stage C: hw = h1 @ gcn_w2 ----
    {
        In5 ins = {{ h1_all, h1_all + NE, h1_all + 2*NE, h1_all + 3*NE, h1_all + 4*NE }};
        gemm_small<0><<<5*32, 128>>>(ins, gcn_w2, nullptr, hw_all, Edim, 32);
    }
    // ---- GCN stage D: z = adj @ hw + b2, fused l2norm for views ----
    {
        Adj4 oth = {{ adj0, madj0, adj1, madj1 }};
        gcn_spmm_kernel<<<dim3(Ndim, 5), 64>>>(adj0, adj1, oth, hw_all, gcn_b2, z_all, 0, 1);
    }

    // ---- semantic attention over (already normalized) hs, z_fine ----
    float* hs = z_all + NE;
    att_kernel<<<dim3(4,4), 256>>>(hs, att_w, att_b, att_vec, epart);
    beta_kernel<<<1, 1>>>(epart, beta);
    zfine_kernel<<<(NE + 255)/256, 256>>>(hs, beta, zfine, NE);

    // ---- projections ----
    {
        In5 ins = {{ z_all, zfine, zfine, zfine, zfine }};
        gemm_small<3><<<2*32, 128>>>(ins, proj_w, proj_b, z2, Edim, 32);
    }
    l2norm_kernel<<<(2*Ndim)/8, 256>>>(z2, 2*Ndim);
    float* zc = z2;
    float* zf = z2 + NE;

    // ---- weighted InfoNCE ----
    u_diag_kernel<<<Ndim/16, 256>>>(zf, zc, mlp1_w, mlp1_b, Uf, Uc, diag);
    pair_kernel<<<dim3(64, 64), 256>>>(zf, zc, Uf, Uc, mlp2_w, mlp2_b, part);
    loss_kernel<<<1, 256>>>(part, diag, (float*)d_out);
}

// round 9
// speedup vs baseline: 2.8649x; 1.0564x over previous
#include <cuda_runtime.h>
#include <cuda_bf16.h>
#include <math.h>
#include <stdint.h>
#include <stddef.h>

#define Ndim 1024
#define Mdim 4096
#define D0 1024
#define D1 512
#define Hdim 512
#define Edim 64

typedef unsigned long long ull;
typedef __nv_bfloat16 bf16;

// ---------------- scratch (device globals; no allocation allowed) ----------------
__device__ float g_h_tar[Ndim*Hdim];
__device__ float g_h_mask[Ndim*Hdim];
__device__ float g_h_nei0[Mdim*Hdim];
__device__ float g_h_nei1[Mdim*Hdim];
__device__ float g_xw_all[5*Ndim*Edim];
__device__ float g_hw_all[5*Ndim*Edim];
__device__ float g_z_all[5*Ndim*Edim];
__device__ float g_epart[16];
__device__ float g_beta[4];
__device__ float g_zfine[Ndim*Edim];
__device__ float g_z2[2*Ndim*Edim];
__device__ float g_Uf[Ndim*16];
__device__ float g_Uc[Ndim*16];
__device__ float g_diag[Ndim];
__device__ float g_part[64*Ndim];

// bf16 hi/lo planes
__device__ bf16 g_feat0_h[Ndim*D0],  g_feat0_l[Ndim*D0];
__device__ bf16 g_mask_h[Ndim*D0],   g_mask_l[Ndim*D0];
__device__ bf16 g_feat1_h[Mdim*D1],  g_feat1_l[Mdim*D1];
__device__ bf16 g_feat2_h[Mdim*D1],  g_feat2_l[Mdim*D1];
__device__ bf16 g_fc0w_h[D0*Hdim],   g_fc0w_l[D0*Hdim];
__device__ bf16 g_fc1w_h[D1*Hdim],   g_fc1w_l[D1*Hdim];
__device__ bf16 g_fc2w_h[D1*Hdim],   g_fc2w_l[D1*Hdim];
__device__ bf16 g_ag0w_h[Hdim*Hdim], g_ag0w_l[Hdim*Hdim];
__device__ bf16 g_ag1w_h[Hdim*Hdim], g_ag1w_l[Hdim*Hdim];
__device__ bf16 g_w1_h[Hdim*Edim],   g_w1_l[Hdim*Edim];
__device__ bf16 g_w2_h[Edim*Edim],   g_w2_l[Edim*Edim];
__device__ bf16 g_agg0_h[Ndim*Hdim], g_agg0_l[Ndim*Hdim];
__device__ bf16 g_agg1_h[Ndim*Hdim], g_agg1_l[Ndim*Hdim];
// stacked GCN input planes: slice0=h_tar, 1=views0, 2=masks0, 3=views1, 4=masks1
__device__ bf16 g_X5h[5*Ndim*Hdim], g_X5l[5*Ndim*Hdim];
// h1 planes (stage B output)
__device__ bf16 g_h1b_h[5*Ndim*Edim], g_h1b_l[5*Ndim*Edim];

__device__ __forceinline__ float eluf(float x){ return x > 0.f ? x : expm1f(x); }
__device__ __forceinline__ float fast_tanh(float x){
    x = fminf(fmaxf(x, -20.f), 20.f);
    float e = __expf(2.f*x);
    return __fdividef(e - 1.f, e + 1.f);
}
__device__ __forceinline__ ull dup2(float x){
    ull r; asm("mov.b64 %0, {%1, %1};" : "=l"(r) : "f"(x)); return r;
}
__device__ __forceinline__ ull fma2(ull a, ull b, ull c){
    ull d; asm("fma.rn.f32x2 %0, %1, %2, %3;" : "=l"(d) : "l"(a), "l"(b), "l"(c)); return d;
}
__device__ __forceinline__ void unpack2(ull v, float& lo, float& hi){
    asm("mov.b64 {%0, %1}, %2;" : "=f"(lo), "=f"(hi) : "l"(v));
}
__device__ __forceinline__ uint32_t smem_u32(const void* p){
    uint32_t r;
    asm("{ .reg .u64 t; cvta.to.shared.u64 t, %1; cvt.u32.u64 %0, t; }" : "=r"(r) : "l"(p));
    return r;
}
__device__ __forceinline__ void ldmA4(uint32_t* r, uint32_t addr){
    asm volatile("ldmatrix.sync.aligned.m8n8.x4.shared.b16 {%0,%1,%2,%3}, [%4];"
        : "=r"(r[0]),"=r"(r[1]),"=r"(r[2]),"=r"(r[3]) : "r"(addr));
}
__device__ __forceinline__ void ldmBT4(uint32_t* r, uint32_t addr){
    asm volatile("ldmatrix.sync.aligned.m8n8.x4.trans.shared.b16 {%0,%1,%2,%3}, [%4];"
        : "=r"(r[0]),"=r"(r[1]),"=r"(r[2]),"=r"(r[3]) : "r"(addr));
}
__device__ __forceinline__ void mma_bf16(float* d, const uint32_t* a, const uint32_t* b){
    asm volatile("mma.sync.aligned.m16n8k16.row.col.f32.bf16.bf16.f32 "
        "{%0,%1,%2,%3}, {%4,%5,%6,%7}, {%8,%9}, {%0,%1,%2,%3};"
        : "+f"(d[0]),"+f"(d[1]),"+f"(d[2]),"+f"(d[3])
        : "r"(a[0]),"r"(a[1]),"r"(a[2]),"r"(a[3]), "r"(b[0]),"r"(b[1]));
}
__device__ __forceinline__ void store_split2(float v0, float v1, bf16* H, bf16* L, size_t idx){
    bf16 h0 = __float2bfloat16(v0), h1 = __float2bfloat16(v1);
    bf16 l0 = __float2bfloat16(v0 - __bfloat162float(h0));
    bf16 l1 = __float2bfloat16(v1 - __bfloat162float(h1));
    __nv_bfloat162 hh; hh.x = h0; hh.y = h1;
    __nv_bfloat162 ll; ll.x = l0; ll.y = l1;
    *(__nv_bfloat162*)&H[idx] = hh;
    *(__nv_bfloat162*)&L[idx] = ll;
}

// ---------------- split: fp32 -> bf16 hi/lo planes ----------------
struct SJob { const float* s; bf16* h; bf16* l; int n4; };
struct SJobs { SJob j[11]; };

__global__ __launch_bounds__(256) void split_kernel(SJobs jobs)
{
    SJob jb = jobs.j[blockIdx.y];
    const int stride = gridDim.x * blockDim.x;
    for (int i = blockIdx.x * blockDim.x + threadIdx.x; i < jb.n4; i += stride) {
        float4 v = ((const float4*)jb.s)[i];
        bf16 h0 = __float2bfloat16(v.x);
        bf16 h1 = __float2bfloat16(v.y);
        bf16 h2 = __float2bfloat16(v.z);
        bf16 h3 = __float2bfloat16(v.w);
        bf16 l0 = __float2bfloat16(v.x - __bfloat162float(h0));
        bf16 l1 = __float2bfloat16(v.y - __bfloat162float(h1));
        bf16 l2 = __float2bfloat16(v.z - __bfloat162float(h2));
        bf16 l3 = __float2bfloat16(v.w - __bfloat162float(h3));
        ushort4 H, L;
        H.x = __bfloat16_as_ushort(h0); H.y = __bfloat16_as_ushort(h1);
        H.z = __bfloat16_as_ushort(h2); H.w = __bfloat16_as_ushort(h3);
        L.x = __bfloat16_as_ushort(l0); L.y = __bfloat16_as_ushort(l1);
        L.z = __bfloat16_as_ushort(l2); L.w = __bfloat16_as_ushort(l3);
        ((ushort4*)jb.h)[i] = H;
        ((ushort4*)jb.l)[i] = L;
    }
}

// ================= HMMA GEMM: bf16-split 3-product, reg-prefetch, templated BM ====
// BM = 32*MT, BN=128, BK=32, 256 threads (8 warps: 2m x 4n), warp tile (16*MT)x32.
// EPI 1: C=elu(v+bias) fp32, optional split planes Bh/Bl.
// EPI 2: planes Bh/Bl = split(elu(aux0+v)), B2h/B2l = split(elu(aux1+v)). No fp32 out.
struct SegH { const bf16 *Ah, *Al, *Wh, *Wl; const float* bias;
              float* C; bf16 *Bh, *Bl, *B2h, *B2l; int K; int tileEnd; };
struct SegsH { SegH s[4]; int nseg; };

template<int EPI, int MT>
__global__ __launch_bounds__(256, (MT < 4) ? 2 : 1) void hmma_gemm(
    SegsH segs, int Nd, const float* __restrict__ aux0, const float* __restrict__ aux1)
{
    constexpr int BM = 32 * MT;
    __shared__ __align__(16) bf16 Ah_s[BM][40];
    __shared__ __align__(16) bf16 Al_s[BM][40];
    __shared__ __align__(16) bf16 Wh_s[32][136];
    __shared__ __align__(16) bf16 Wl_s[32][136];

    const int tid = threadIdx.x;
    const int by  = blockIdx.y;
    int si = 0, tileStart = 0;
    #pragma unroll
    for (int i = 0; i < 3; i++)
        if (i < segs.nseg && by >= segs.s[i].tileEnd) { si = i + 1; tileStart = segs.s[i].tileEnd; }
    const SegH sg = segs.s[si];
    const int K  = sg.K;
    const int bm = (by - tileStart) * BM;
    const int bn = blockIdx.x * 128;

    const int lane = tid & 31;
    const int w    = tid >> 5;
    const int wm   = w >> 2;
    const int wn   = w & 3;

    // A loader mapping
    int arow, aseg; bool aact;
    if constexpr (MT == 4)      { arow = tid >> 1;        aseg = (tid & 1) * 16; aact = true; }
    else if constexpr (MT == 2) { arow = tid >> 2;        aseg = (tid & 3) * 8;  aact = true; }
    else                        { arow = (tid >> 2) & 31; aseg = (tid & 3) * 8;  aact = (tid < 128); }
    const int krow = tid >> 3;
    const int nsg  = (tid & 7) * 16;

    const uint32_t aBaseH = smem_u32(&Ah_s[0][0]);
    const uint32_t aBaseL = smem_u32(&Al_s[0][0]);
    const uint32_t wBaseH = smem_u32(&Wh_s[0][0]);
    const uint32_t wBaseL = smem_u32(&Wl_s[0][0]);
    const uint32_t aoff = ((wm*16*MT + (lane & 15)) * 40 + (lane >> 4) * 8) * 2;
    const uint32_t boff = ((lane & 15) * 136 + wn*32 + (lane >> 4) * 8) * 2;

    const bf16* Agh = sg.Ah + (size_t)(bm + arow) * K + aseg;
    const bf16* Agl = sg.Al + (size_t)(bm + arow) * K + aseg;
    const bf16* Wgh = sg.Wh + (size_t)krow * Nd + bn + nsg;
    const bf16* Wgl = sg.Wl + (size_t)krow * Nd + bn + nsg;

    float d[MT][4][4];
    #pragma unroll
    for (int mt = 0; mt < MT; mt++)
        #pragma unroll
        for (int nt = 0; nt < 4; nt++)
            #pragma unroll
            for (int q = 0; q < 4; q++) d[mt][nt][q] = 0.f;

    const int nk = K >> 5;

    uint4 ah0 = {}, ah1 = {}, al0 = {}, al1 = {};
    uint4 wh0, wh1, wl0, wl1;
    if (aact) {
        ah0 = *(const uint4*)(Agh);
        al0 = *(const uint4*)(Agl);
        if constexpr (MT == 4) { ah1 = *(const uint4*)(Agh + 8); al1 = *(const uint4*)(Agl + 8); }
    }
    wh0 = *(const uint4*)(Wgh);  wh1 = *(const uint4*)(Wgh + 8);
    wl0 = *(const uint4*)(Wgl);  wl1 = *(const uint4*)(Wgl + 8);
    if (aact) {
        *(uint4*)&Ah_s[arow][aseg] = ah0;
        *(uint4*)&Al_s[arow][aseg] = al0;
        if constexpr (MT == 4) { *(uint4*)&Ah_s[arow][aseg+8] = ah1; *(uint4*)&Al_s[arow][aseg+8] = al1; }
    }
    *(uint4*)&Wh_s[krow][nsg]   = wh0;  *(uint4*)&Wh_s[krow][nsg+8] = wh1;
    *(uint4*)&Wl_s[krow][nsg]   = wl0;  *(uint4*)&Wl_s[krow][nsg+8] = wl1;
    __syncthreads();

    for (int t = 0; t < nk; t++) {
        const bool has = (t + 1 < nk);
        if (has) {
            const int k0 = (t + 1) * 32;
            if (aact) {
                ah0 = *(const uint4*)(Agh + k0);
                al0 = *(const uint4*)(Agl + k0);
                if constexpr (MT == 4) { ah1 = *(const uint4*)(Agh + k0 + 8); al1 = *(const uint4*)(Agl + k0 + 8); }
            }
            wh0 = *(const uint4*)(Wgh + (size_t)k0 * Nd);  wh1 = *(const uint4*)(Wgh + (size_t)k0 * Nd + 8);
            wl0 = *(const uint4*)(Wgl + (size_t)k0 * Nd);  wl1 = *(const uint4*)(Wgl + (size_t)k0 * Nd + 8);
        }
        #pragma unroll
        for (int ks = 0; ks < 2; ks++) {
            uint32_t ah[MT][4], al[MT][4];
            #pragma unroll
            for (int mt = 0; mt < MT; mt++) {
                const uint32_t o = aoff + (mt * 16 * 40 + ks * 16) * 2;
                ldmA4(ah[mt], aBaseH + o);
                ldmA4(al[mt], aBaseL + o);
            }
            uint32_t bh[2][4], bl[2][4];
            #pragma unroll
            for (int np = 0; np < 2; np++) {
                const uint32_t o = boff + (ks * 16 * 136 + np * 16) * 2;
                ldmBT4(bh[np], wBaseH + o);
                ldmBT4(bl[np], wBaseL + o);
            }
            #pragma unroll
            for (int mt = 0; mt < MT; mt++) {
                #pragma unroll
                for (int nt = 0; nt < 4; nt++) {
                    const uint32_t* bph = &bh[nt >> 1][(nt & 1) * 2];
                    const uint32_t* bpl = &bl[nt >> 1][(nt & 1) * 2];
                    mma_bf16(d[mt][nt], al[mt], bph);
                    mma_bf16(d[mt][nt], ah[mt], bpl);
                    mma_bf16(d[mt][nt], ah[mt], bph);
                }
            }
        }
        if (has) {
            __syncthreads();
            if (aact) {
                *(uint4*)&Ah_s[arow][aseg] = ah0;
                *(uint4*)&Al_s[arow][aseg] = al0;
                if constexpr (MT == 4) { *(uint4*)&Ah_s[arow][aseg+8] = ah1; *(uint4*)&Al_s[arow][aseg+8] = al1; }
            }
            *(uint4*)&Wh_s[krow][nsg]   = wh0;  *(uint4*)&Wh_s[krow][nsg+8] = wh1;
            *(uint4*)&Wl_s[krow][nsg]   = wl0;  *(uint4*)&Wl_s[krow][nsg+8] = wl1;
            __syncthreads();
        }
    }

    // epilogue
    const int g  = lane >> 2;
    const int tq = lane & 3;
    #pragma unroll
    for (int mt = 0; mt < MT; mt++) {
        #pragma unroll
        for (int nt = 0; nt < 4; nt++) {
            const int r = bm + wm*16*MT + mt*16 + g;
            const int c = bn + wn*32 + nt*8 + tq*2;
            #pragma unroll
            for (int half = 0; half < 2; half++) {
                const int rr = r + half * 8;
                float v0 = d[mt][nt][half*2 + 0];
                float v1 = d[mt][nt][half*2 + 1];
                const size_t idx = (size_t)rr * Nd + c;
                if (EPI == 1) {
                    v0 = eluf(v0 + sg.bias[c]); v1 = eluf(v1 + sg.bias[c+1]);
                    *(float2*)&sg.C[idx] = make_float2(v0, v1);
                    if (sg.Bh) store_split2(v0, v1, sg.Bh, sg.Bl, idx);
                } else if (EPI == 2) {
                    float2 a0 = *(const float2*)&aux0[idx];
                    float2 a1 = *(const float2*)&aux1[idx];
                    store_split2(eluf(a0.x + v0), eluf(a0.y + v1), sg.Bh,  sg.Bl,  idx);
                    store_split2(eluf(a1.x + v0), eluf(a1.y + v1), sg.B2h, sg.B2l, idx);
                }
            }
        }
    }
}

// ================= hmma_gemm64: N=64 GEMM (GCN stages A and C) ===================
// BM=64, BN=64, BK=32, 256 threads (8 warps: 4m x 2n), warp tile 16x32.
__global__ __launch_bounds__(256) void hmma_gemm64(
    const bf16* __restrict__ Ah, const bf16* __restrict__ Al,
    const bf16* __restrict__ Wh, const bf16* __restrict__ Wl,
    float* __restrict__ out, int K)
{
    __shared__ __align__(16) bf16 Ah_s[64][40];
    __shared__ __align__(16) bf16 Al_s[64][40];
    __shared__ __align__(16) bf16 Wh_s[32][72];
    __shared__ __align__(16) bf16 Wl_s[32][72];

    const int tid = threadIdx.x;
    const int bm = blockIdx.x * 64;
    const int lane = tid & 31;
    const int w    = tid >> 5;
    const int wm   = w >> 1;    // 0..3
    const int wn   = w & 1;     // 0..1

    const int arow = tid >> 2;          // 0..63
    const int acol = (tid & 3) * 8;     // 0..24
    const int krow = tid >> 3;          // 0..31
    const int ncol = (tid & 7) * 8;     // 0..56

    const uint32_t aBaseH = smem_u32(&Ah_s[0][0]);
    const uint32_t aBaseL = smem_u32(&Al_s[0][0]);
    const uint32_t wBaseH = smem_u32(&Wh_s[0][0]);
    const uint32_t wBaseL = smem_u32(&Wl_s[0][0]);
    const uint32_t aoff = ((wm*16 + (lane & 15)) * 40 + (lane >> 4) * 8) * 2;
    const uint32_t boff = ((lane & 15) * 72 + wn*32 + (lane >> 4) * 8) * 2;

    const bf16* Agh = Ah + (size_t)(bm + arow) * K + acol;
    const bf16* Agl = Al + (size_t)(bm + arow) * K + acol;
    const bf16* Wgh = Wh + (size_t)krow * Edim + ncol;
    const bf16* Wgl = Wl + (size_t)krow * Edim + ncol;

    float d[4][4];
    #pragma unroll
    for (int nt = 0; nt < 4; nt++)
        #pragma unroll
        for (int q = 0; q < 4; q++) d[nt][q] = 0.f;

    const int nk = K >> 5;

    uint4 aH = *(const uint4*)(Agh);
    uint4 aL = *(const uint4*)(Agl);
    uint4 wH = *(const uint4*)(Wgh);
    uint4 wL = *(const uint4*)(Wgl);
    *(uint4*)&Ah_s[arow][acol] = aH;
    *(uint4*)&Al_s[arow][acol] = aL;
    *(uint4*)&Wh_s[krow][ncol] = wH;
    *(uint4*)&Wl_s[krow][ncol] = wL;
    __syncthreads();

    for (int t = 0; t < nk; t++) {
        const bool has = (t + 1 < nk);
        if (has) {
            const int k0 = (t + 1) * 32;
            aH = *(const uint4*)(Agh + k0);
            aL = *(const uint4*)(Agl + k0);
            wH = *(const uint4*)(Wgh + (size_t)k0 * Edim);
            wL = *(const uint4*)(Wgl + (size_t)k0 * Edim);
        }
        #pragma unroll
        for (int ks = 0; ks < 2; ks++) {
            uint32_t ah[4], al[4];
            {
                const uint32_t o = aoff + (ks * 16) * 2;
                ldmA4(ah, aBaseH + o);
                ldmA4(al, aBaseL + o);
            }
            uint32_t bh[2][4], bl[2][4];
            #pragma unroll
            for (int np = 0; np < 2; np++) {
                const uint32_t o = boff + (ks * 16 * 72 + np * 16) * 2;
                ldmBT4(bh[np], wBaseH + o);
                ldmBT4(bl[np], wBaseL + o);
            }
            #pragma unroll
            for (int nt = 0; nt < 4; nt++) {
                const uint32_t* bph = &bh[nt >> 1][(nt & 1) * 2];
                const uint32_t* bpl = &bl[nt >> 1][(nt & 1) * 2];
                mma_bf16(d[nt], al, bph);
                mma_bf16(d[nt], ah, bpl);
                mma_bf16(d[nt], ah, bph);
            }
        }
        if (has) {
            __syncthreads();
            *(uint4*)&Ah_s[arow][acol] = aH;
            *(uint4*)&Al_s[arow][acol] = aL;
            *(uint4*)&Wh_s[krow][ncol] = wH;
            *(uint4*)&Wl_s[krow][ncol] = wL;
            __syncthreads();
        }
    }

    const int g  = lane >> 2;
    const int tq = lane & 3;
    #pragma unroll
    for (int nt = 0; nt < 4; nt++) {
        #pragma unroll
        for (int half = 0; half < 2; half++) {
            const int rr = bm + wm*16 + g + half*8;
            const int c  = wn*32 + nt*8 + tq*2;
            *(float2*)&out[(size_t)rr * Edim + c] =
                make_float2(d[nt][half*2 + 0], d[nt][half*2 + 1]);
        }
    }
}

// ================= small GEMM: N=64, batched, f32x2; ACT 4 = tanh + row L2norm ====
struct In5 { const float* p[5]; };

template<int ACT>
__global__ __launch_bounds__(128) void gemm_small(
    In5 ins, const float* __restrict__ W, const float* __restrict__ bias,
    float* __restrict__ out, int K, int tilesPer)
{
    __shared__ __align__(16) float As[16][32];
    __shared__ __align__(16) float Bs[16][64];
    const int tid = threadIdx.x;
    const int g  = blockIdx.x / tilesPer;
    const int tb = blockIdx.x % tilesPer;
    const float* A = ins.p[g] + (size_t)tb * 32 * K;
    float* C = out + ((size_t)g * tilesPer * 32 + tb * 32) * 64;

    const int tx = tid & 15;
    const int ty = tid >> 4;
    const int ar = tid >> 2, akc = (tid & 3) * 4;
    const int br = tid >> 4, bc = (tid & 15) * 4;

    ull acc[4][2];
    #pragma unroll
    for (int i = 0; i < 4; i++) { acc[i][0] = 0ull; acc[i][1] = 0ull; }

    for (int k0 = 0; k0 < K; k0 += 16) {
        float4 av  = *(const float4*)(A + (size_t)ar * K + k0 + akc);
        float4 bv0 = *(const float4*)(W + (size_t)(k0 + br) * 64 + bc);
        float4 bv1 = *(const float4*)(W + (size_t)(k0 + br + 8) * 64 + bc);
        __syncthreads();
        As[akc+0][ar] = av.x; As[akc+1][ar] = av.y; As[akc+2][ar] = av.z; As[akc+3][ar] = av.w;
        *(float4*)&Bs[br][bc]   = bv0;
        *(float4*)&Bs[br+8][bc] = bv1;
        __syncthreads();
        #pragma unroll
        for (int kk = 0; kk < 16; kk++) {
            float4 av2 = *(const float4*)&As[kk][ty*4];
            ulonglong2 bp = *(const ulonglong2*)&Bs[kk][tx*4];
            ull a2[4] = {dup2(av2.x), dup2(av2.y), dup2(av2.z), dup2(av2.w)};
            #pragma unroll
            for (int i = 0; i < 4; i++) {
                acc[i][0] = fma2(a2[i], bp.x, acc[i][0]);
                acc[i][1] = fma2(a2[i], bp.y, acc[i][1]);
            }
        }
    }
    if (ACT == 4) {
        // tanh + fused row L2 norm (rows span the 16 tx lanes of a half-warp)
        float vr[4][4];
        #pragma unroll
        for (int i = 0; i < 4; i++) {
            #pragma unroll
            for (int j = 0; j < 2; j++) {
                float v0, v1; unpack2(acc[i][j], v0, v1);
                const int c = tx * 4 + 2 * j;
                vr[i][2*j]   = tanhf(v0 + bias[c]);
                vr[i][2*j+1] = tanhf(v1 + bias[c+1]);
            }
        }
        #pragma unroll
        for (int i = 0; i < 4; i++) {
            float s = vr[i][0]*vr[i][0] + vr[i][1]*vr[i][1]
                    + vr[i][2]*vr[i][2] + vr[i][3]*vr[i][3];
            #pragma unroll
            for (int o = 8; o > 0; o >>= 1) s += __shfl_xor_sync(0xffffffffu, s, o, 16);
            const float inv = 1.f / fmaxf(sqrtf(s), 1e-12f);
            const int row = ty * 4 + i;
            *(float4*)&C[(size_t)row * 64 + tx * 4] =
                make_float4(vr[i][0]*inv, vr[i][1]*inv, vr[i][2]*inv, vr[i][3]*inv);
        }
    } else {
        #pragma unroll
        for (int i = 0; i < 4; i++) {
            const int row = ty * 4 + i;
            #pragma unroll
            for (int j = 0; j < 2; j++) {
                float v0, v1; unpack2(acc[i][j], v0, v1);
                const int c = tx * 4 + 2 * j;
                if (bias) { v0 += bias[c]; v1 += bias[c+1]; }
                if (ACT == 3) { v0 = tanhf(v0); v1 = tanhf(v1); }
                *(float2*)&C[(size_t)row * 64 + c] = make_float2(v0, v1);
            }
        }
    }
}

// ========== nei SpMM (mean over nnz) -> bf16 hi/lo planes; ballot compaction ======
__global__ __launch_bounds__(256) void spmm2_kernel(
    const float* __restrict__ nei0, const float* __restrict__ nei1,
    const float* __restrict__ X0, const float* __restrict__ X1,
    bf16* __restrict__ Y0h, bf16* __restrict__ Y0l,
    bf16* __restrict__ Y1h, bf16* __restrict__ Y1l)
{
    __shared__ int   s_idx[512];
    __shared__ float s_val[512];
    __shared__ int   warpTot[8];
    __shared__ int   warpBase[8];
    __shared__ int   s_tot;
    const int row = blockIdx.x;
    const int which = blockIdx.y;
    const float* A = which ? nei1 : nei0;
    const float* X = which ? X1 : X0;
    bf16* Yh = which ? Y1h : Y0h;
    bf16* Yl = which ? Y1l : Y0l;
    const int tid = threadIdx.x;
    const int lane = tid & 31;
    const int wrp  = tid >> 5;

    const float4* arow = (const float4*)(A + (size_t)row * Mdim);
    int base = 0;
    #pragma unroll
    for (int chunk = 0; chunk < 4; chunk++) {
        float4 v = arow[chunk * 256 + tid];
        int m = (v.x != 0.f ? 1 : 0) | (v.y != 0.f ? 2 : 0)
              | (v.z != 0.f ? 4 : 0) | (v.w != 0.f ? 8 : 0);
        int c = __popc(m);
        int incl = c;
        #pragma unroll
        for (int o = 1; o < 32; o <<= 1) {
            int n = __shfl_up_sync(0xffffffffu, incl, o);
            if (lane >= o) incl += n;
        }
        if (lane == 31) warpTot[wrp] = incl;
        __syncthreads();
        if (tid == 0) {
            int r = 0;
            #pragma unroll
            for (int i = 0; i < 8; i++) { warpBase[i] = r; r += warpTot[i]; }
            s_tot = r;
        }
        __syncthreads();
        int off = base + warpBase[wrp] + incl - c;
        const int colbase = (chunk * 256 + tid) * 4;
        if (m & 1) { if (off < 512) { s_idx[off] = colbase;     s_val[off] = v.x; } off++; }
        if (m & 2) { if (off < 512) { s_idx[off] = colbase + 1; s_val[off] = v.y; } off++; }
        if (m & 4) { if (off < 512) { s_idx[off] = colbase + 2; s_val[off] = v.z; } off++; }
        if (m & 8) { if (off < 512) { s_idx[off] = colbase + 3; s_val[off] = v.w; } off++; }
        base += s_tot;
        __syncthreads();
    }
    const int total = min(base, 512);
    const float inv = 1.f / fmaxf((float)base, 1.f);
    const float2* Xp = (const float2*)X + tid;
    float2 acc = make_float2(0.f, 0.f);
    int t = 0;
    for (; t + 4 <= total; t += 4) {
        int i0 = s_idx[t], i1 = s_idx[t+1], i2 = s_idx[t+2], i3 = s_idx[t+3];
        float w0 = s_val[t], w1 = s_val[t+1], w2 = s_val[t+2], w3 = s_val[t+3];
        float2 x0 = Xp[(size_t)i0 * 256];
        float2 x1 = Xp[(size_t)i1 * 256];
        float2 x2 = Xp[(size_t)i2 * 256];
        float2 x3 = Xp[(size_t)i3 * 256];
        acc.x += w0*x0.x + w1*x1.x + w2*x2.x + w3*x3.x;
        acc.y += w0*x0.y + w1*x1.y + w2*x2.y + w3*x3.y;
    }
    for (; t < total; t++) {
        int i0 = s_idx[t]; float w0 = s_val[t];
        float2 x0 = Xp[(size_t)i0 * 256];
        acc.x += w0 * x0.x; acc.y += w0 * x0.y;
    }
    store_split2(acc.x * inv, acc.y * inv, Yh, Yl, (size_t)row * Hdim + tid * 2);
}

// ========== batched GCN SpMM (ballot); g==0 uses mean(adj0,adj1) on the fly ======
// planes=1: write relu'd result as bf16 hi/lo planes. planes=0: fp32 (+optional l2norm g>0).
struct Adj4 { const float* a[4]; };
__global__ __launch_bounds__(64) void gcn_spmm_kernel(
    const float* __restrict__ adj0, const float* __restrict__ adj1, Adj4 others,
    const float* __restrict__ Xall, const float* __restrict__ bias,
    float* __restrict__ Yall, bf16* __restrict__ Yh, bf16* __restrict__ Yl,
    int relu, int donorm, int planes)
{
    __shared__ int   s_idx[512];
    __shared__ float s_val[512];
    __shared__ int   warpTot[2];
    __shared__ int   warpBase[2];
    __shared__ int   s_tot;
    __shared__ float s_sq[2];
    const int g   = blockIdx.y;
    const int row = blockIdx.x;
    const int tid = threadIdx.x;
    const int lane = tid & 31;
    const int wrp  = tid >> 5;
    const float* X = Xall + (size_t)g * Ndim * Edim;

    const float4* r0 = (const float4*)((g == 0 ? adj0 : others.a[g-1]) + (size_t)row * Ndim);
    const float4* r1 = (const float4*)(adj1 + (size_t)row * Ndim);

    int base = 0;
    #pragma unroll
    for (int chunk = 0; chunk < 4; chunk++) {
        float4 v = r0[chunk * 64 + tid];
        if (g == 0) {
            float4 v1 = r1[chunk * 64 + tid];
            v.x = 0.5f * (v.x + v1.x); v.y = 0.5f * (v.y + v1.y);
            v.z = 0.5f * (v.z + v1.z); v.w = 0.5f * (v.w + v1.w);
        }
        int m = (v.x != 0.f ? 1 : 0) | (v.y != 0.f ? 2 : 0)
              | (v.z != 0.f ? 4 : 0) | (v.w != 0.f ? 8 : 0);
        int c = __popc(m);
        int incl = c;
        #pragma unroll
        for (int o = 1; o < 32; o <<= 1) {
            int n = __shfl_up_sync(0xffffffffu, incl, o);
            if (lane >= o) incl += n;
        }
        if (lane == 31) warpTot[wrp] = incl;
        __syncthreads();
        if (tid == 0) {
            warpBase[0] = 0; warpBase[1] = warpTot[0];
            s_tot = warpTot[0] + warpTot[1];
        }
        __syncthreads();
        int off = base + warpBase[wrp] + incl - c;
        const int colbase = (chunk * 64 + tid) * 4;
        if (m & 1) { if (off < 512) { s_idx[off] = colbase;     s_val[off] = v.x; } off++; }
        if (m & 2) { if (off < 512) { s_idx[off] = colbase + 1; s_val[off] = v.y; } off++; }
        if (m & 4) { if (off < 512) { s_idx[off] = colbase + 2; s_val[off] = v.z; } off++; }
        if (m & 8) { if (off < 512) { s_idx[off] = colbase + 3; s_val[off] = v.w; } off++; }
        base += s_tot;
        __syncthreads();
    }
    const int total = min(base, 512);
    const int e = tid;
    float v = 0.f;
    int t = 0;
    for (; t + 4 <= total; t += 4) {
        int i0 = s_idx[t], i1 = s_idx[t+1], i2 = s_idx[t+2], i3 = s_idx[t+3];
        float w0 = s_val[t], w1 = s_val[t+1], w2 = s_val[t+2], w3 = s_val[t+3];
        v += w0 * X[(size_t)i0 * Edim + e] + w1 * X[(size_t)i1 * Edim + e]
           + w2 * X[(size_t)i2 * Edim + e] + w3 * X[(size_t)i3 * Edim + e];
    }
    for (; t < total; t++) v += s_val[t] * X[(size_t)s_idx[t] * Edim + e];
    v += bias[e];
    if (relu) v = fmaxf(v, 0.f);
    const size_t oidx = (size_t)g * Ndim * Edim + (size_t)row * Edim + e;
    if (planes) {
        bf16 h = __float2bfloat16(v);
        Yh[oidx] = h;
        Yl[oidx] = __float2bfloat16(v - __bfloat162float(h));
        return;
    }
    if (donorm && g > 0) {
        float sq = v * v;
        #pragma unroll
        for (int o = 16; o > 0; o >>= 1) sq += __shfl_xor_sync(0xffffffffu, sq, o);
        if (lane == 0) s_sq[wrp] = sq;
        __syncthreads();
        const float nrm = fmaxf(sqrtf(s_sq[0] + s_sq[1]), 1e-12f);
        v /= nrm;
    }
    Yall[oidx] = v;
}

// ---------------- elementwise / tail kernels ----------------
__global__ __launch_bounds__(256) void att_kernel(
    const float* __restrict__ hs, const float* __restrict__ att_w,
    const float* __restrict__ att_b, const float* __restrict__ att_vec,
    float* __restrict__ epart)
{
    __shared__ float w_s[64*64];
    __shared__ float b_s[64];
    __shared__ float v_s[64];
    __shared__ float red[256];
    const int tid = threadIdx.x;
    for (int i = tid; i < 64*64; i += 256) w_s[i] = att_w[i];
    if (tid < 64) { b_s[tid] = att_b[tid]; v_s[tid] = att_vec[tid]; }
    __syncthreads();
    const int v = blockIdx.y;
    const int n = blockIdx.x * 256 + tid;
    const float* row = hs + ((size_t)v * Ndim + n) * 64;
    float r[64];
    #pragma unroll
    for (int f = 0; f < 64; f++) r[f] = row[f];
    float s = 0.f;
    for (int e = 0; e < 64; e++) {
        float acc = b_s[e];
        #pragma unroll
        for (int f = 0; f < 64; f++) acc += r[f] * w_s[f*64 + e];
        s += v_s[e] * tanhf(acc);
    }
    red[tid] = s;
    __syncthreads();
    for (int st = 128; st > 0; st >>= 1) {
        if (tid < st) red[tid] += red[tid + st];
        __syncthreads();
    }
    if (tid == 0) epart[v*4 + blockIdx.x] = red[0];
}

__global__ void beta_kernel(const float* __restrict__ epart, float* __restrict__ beta)
{
    float e[4];
    float m = -1e30f;
    for (int v = 0; v < 4; v++) {
        e[v] = (epart[v*4+0] + epart[v*4+1] + epart[v*4+2] + epart[v*4+3]) / (float)Ndim;
        m = fmaxf(m, e[v]);
    }
    float s = 0.f;
    for (int v = 0; v < 4; v++) { float b = expf(e[v] - m); beta[v] = b; s += b; }
    for (int v = 0; v < 4; v++) beta[v] /= s;
}

__global__ void zfine_kernel(const float* __restrict__ hs, const float* __restrict__ beta,
                             float* __restrict__ zfine, int n)
{
    int i = blockIdx.x * blockDim.x + threadIdx.x;
    if (i < n) {
        float s = beta[0]*hs[i] + beta[1]*hs[(size_t)Ndim*Edim + i]
                + beta[2]*hs[(size_t)2*Ndim*Edim + i] + beta[3]*hs[(size_t)3*Ndim*Edim + i];
        zfine[i] = s;
    }
}

__global__ __launch_bounds__(256) void u_diag_kernel(
    const float* __restrict__ zf, const float* __restrict__ zc,
    const float* __restrict__ mlp1_w, const float* __restrict__ mlp1_b,
    float* __restrict__ Uf, float* __restrict__ Uc, float* __restrict__ diag)
{
    __shared__ float w_s[64*16];
    const int tid = threadIdx.x;
    for (int i = tid; i < 64*16; i += 256) w_s[i] = mlp1_w[i];
    __syncthreads();
    const int n = blockIdx.x * 16 + (tid >> 4);
    const int k = tid & 15;
    const float* zfr = zf + (size_t)n * 64;
    const float* zcr = zc + (size_t)n * 64;
    float af = 0.f, acr = 0.f;
    #pragma unroll
    for (int e = 0; e < 64; e++) {
        float w = w_s[e*16 + k];
        af  += zfr[e] * w;
        acr += zcr[e] * w;
    }
    Uf[(size_t)n*16 + k] = af + mlp1_b[k];
    Uc[(size_t)n*16 + k] = acr;
    float p = 0.f;
    #pragma unroll
    for (int e = 0; e < 4; e++) p += zfr[4*k + e] * zcr[4*k + e];
    #pragma unroll
    for (int o = 8; o > 0; o >>= 1) p += __shfl_down_sync(0xffffffffu, p, o, 16);
    if (k == 0) diag[n] = 2.f * p;
}

__global__ __launch_bounds__(256) void pair_kernel(
    const float* __restrict__ zf, const float* __restrict__ zc,
    const float* __restrict__ Uf, const float* __restrict__ Uc,
    const float* __restrict__ mlp2_w, const float* __restrict__ mlp2_b,
    float* __restrict__ part)
{
    __shared__ float zf_s[16][68];
    __shared__ float zc_s[16][68];
    __shared__ float uc_s[16][17];
    __shared__ float m2_s[16];
    const int tid = threadIdx.x;
    const int bi = blockIdx.y * 16;
    const int bj = blockIdx.x * 16;
    const int lr = tid >> 4, lc = (tid & 15) << 2;
    *(float4*)&zf_s[lr][lc] = *(const float4*)(zf + (size_t)(bi + lr) * 64 + lc);
    *(float4*)&zc_s[lr][lc] = *(const float4*)(zc + (size_t)(bj + lr) * 64 + lc);
    uc_s[tid >> 4][tid & 15] = Uc[(size_t)(bj + (tid >> 4)) * 16 + (tid & 15)];
    if (tid < 16) m2_s[tid] = mlp2_w[tid];
    __syncthreads();
    const int ti = tid >> 4, tj = tid & 15;
    const int i = bi + ti;
    float uf[16];
    #pragma unroll
    for (int k = 0; k < 16; k++) uf[k] = Uf[(size_t)i*16 + k];
    float dot = 0.f;
    #pragma unroll
    for (int e = 0; e < 64; e++) dot += zf_s[ti][e] * zc_s[tj][e];
    float sacc = mlp2_b[0];
    #pragma unroll
    for (int k = 0; k < 16; k++) sacc += m2_s[k] * fast_tanh(uf[k] + uc_s[tj][k]);
    float w = 1.f / (1.f + __expf(-fminf(fmaxf(sacc, -30.f), 30.f)));
    float contrib = __expf(2.f * dot) * w;
    #pragma unroll
    for (int off = 8; off > 0; off >>= 1)
        contrib += __shfl_down_sync(0xffffffffu, contrib, off, 16);
    if (tj == 0) part[(size_t)blockIdx.x * Ndim + i] = contrib;
}

__global__ void loss_kernel(const float* __restrict__ part, const float* __restrict__ diag,
                            float* __restrict__ out)
{
    __shared__ float red[256];
    const int tid = threadIdx.x;
    float s = 0.f;
    for (int i = tid; i < Ndim; i += 256) {
        float d = 0.f;
        for (int b = 0; b < 64; b++) d += part[(size_t)b * Ndim + i];
        s += logf(d) - diag[i];
    }
    red[tid] = s;
    __syncthreads();
    for (int st = 128; st > 0; st >>= 1) {
        if (tid < st) red[tid] += red[tid + st];
        __syncthreads();
    }
    if (tid == 0) out[0] = red[0] / (float)Ndim;
}

// ---------------- host ----------------
static float* devptr(const void* sym) {
    void* p = nullptr;
    cudaGetSymbolAddress(&p, sym);
    return (float*)p;
}
static bf16* devptrb(const void* sym) {
    void* p = nullptr;
    cudaGetSymbolAddress(&p, sym);
    return (bf16*)p;
}

extern "C" void kernel_launch(void* const* d_in, const int* in_sizes, int n_in,
                              void* d_out, int out_size)
{
    const float* feat0     = (const float*)d_in[0];
    const float* feat1     = (const float*)d_in[1];
    const float* feat2     = (const float*)d_in[2];
    const float* mask_feat = (const float*)d_in[3];
    const float* nei0      = (const float*)d_in[4];
    const float* nei1      = (const float*)d_in[5];
    const float* adj0      = (const float*)d_in[6];
    const float* adj1      = (const float*)d_in[7];
    const float* madj0     = (const float*)d_in[8];
    const float* madj1     = (const float*)d_in[9];
    const float* fc0_w     = (const float*)d_in[10];
    const float* fc0_b     = (const float*)d_in[11];
    const float* fc1_w     = (const float*)d_in[12];
    const float* fc1_b     = (const float*)d_in[13];
    const float* fc2_w     = (const float*)d_in[14];
    const float* fc2_b     = (const float*)d_in[15];
    const float* agg0_w    = (const float*)d_in[16];
    const float* agg1_w    = (const float*)d_in[17];
    const float* gcn_w1    = (const float*)d_in[18];
    const float* gcn_b1    = (const float*)d_in[19];
    const float* gcn_w2    = (const float*)d_in[20];
    const float* gcn_b2    = (const float*)d_in[21];
    const float* att_w     = (const float*)d_in[22];
    const float* att_b     = (const float*)d_in[23];
    const float* att_vec   = (const float*)d_in[24];
    const float* proj_w    = (const float*)d_in[25];
    const float* proj_b    = (const float*)d_in[26];
    const float* mlp1_w    = (const float*)d_in[27];
    const float* mlp1_b    = (const float*)d_in[28];
    const float* mlp2_w    = (const float*)d_in[29];
    const float* mlp2_b    = (const float*)d_in[30];

    float* h_tar  = devptr(g_h_tar);
    float* h_mask = devptr(g_h_mask);
    float* h_nei0 = devptr(g_h_nei0);
    float* h_nei1 = devptr(g_h_nei1);
    float* xw_all = devptr(g_xw_all);
    float* hw_all = devptr(g_hw_all);
    float* z_all  = devptr(g_z_all);
    float* epart  = devptr(g_epart);
    float* beta   = devptr(g_beta);
    float* zfine  = devptr(g_zfine);
    float* z2     = devptr(g_z2);
    float* Uf     = devptr(g_Uf);
    float* Uc     = devptr(g_Uc);
    float* diag   = devptr(g_diag);
    float* part   = devptr(g_part);

    bf16 *f0h = devptrb(g_feat0_h), *f0l = devptrb(g_feat0_l);
    bf16 *mkh = devptrb(g_mask_h),  *mkl = devptrb(g_mask_l);
    bf16 *f1h = devptrb(g_feat1_h), *f1l = devptrb(g_feat1_l);
    bf16 *f2h = devptrb(g_feat2_h), *f2l = devptrb(g_feat2_l);
    bf16 *w0h = devptrb(g_fc0w_h),  *w0l = devptrb(g_fc0w_l);
    bf16 *w1h = devptrb(g_fc1w_h),  *w1l = devptrb(g_fc1w_l);
    bf16 *w2h = devptrb(g_fc2w_h),  *w2l = devptrb(g_fc2w_l);
    bf16 *a0h = devptrb(g_ag0w_h),  *a0l = devptrb(g_ag0w_l);
    bf16 *a1h = devptrb(g_ag1w_h),  *a1l = devptrb(g_ag1w_l);
    bf16 *gw1h = devptrb(g_w1_h),   *gw1l = devptrb(g_w1_l);
    bf16 *gw2h = devptrb(g_w2_h),   *gw2l = devptrb(g_w2_l);
    bf16 *g0h = devptrb(g_agg0_h),  *g0l = devptrb(g_agg0_l);
    bf16 *g1h = devptrb(g_agg1_h),  *g1l = devptrb(g_agg1_l);
    bf16 *X5h = devptrb(g_X5h),     *X5l = devptrb(g_X5l);
    bf16 *h1bh = devptrb(g_h1b_h),  *h1bl = devptrb(g_h1b_l);

    const int NE = Ndim * Edim;
    const int NH = Ndim * Hdim;

    // ---- split all static fp32 operands into bf16 hi/lo planes ----
    {
        SJobs js;
        js.j[0]  = { feat0,     f0h, f0l, (Ndim*D0)/4 };
        js.j[1]  = { mask_feat, mkh, mkl, (Ndim*D0)/4 };
        js.j[2]  = { feat1,     f1h, f1l, (Mdim*D1)/4 };
        js.j[3]  = { feat2,     f2h, f2l, (Mdim*D1)/4 };
        js.j[4]  = { fc0_w,     w0h, w0l, (D0*Hdim)/4 };
        js.j[5]  = { fc1_w,     w1h, w1l, (D1*Hdim)/4 };
        js.j[6]  = { fc2_w,     w2h, w2l, (D1*Hdim)/4 };
        js.j[7]  = { agg0_w,    a0h, a0l, (Hdim*Hdim)/4 };
        js.j[8]  = { agg1_w,    a1h, a1l, (Hdim*Hdim)/4 };
        js.j[9]  = { gcn_w1,    gw1h, gw1l, (Hdim*Edim)/4 };
        js.j[10] = { gcn_w2,    gw2h, gw2l, (Edim*Edim)/4 };
        split_kernel<<<dim3(128, 11), 256>>>(js);
    }

    // ---- encoders via HMMA (MT=2, 640 blocks); seg0 also emits X5 slice0 ----
    {
        SegsH sgs;
        sgs.nseg = 4;
        sgs.s[0] = { f0h, f0l, w0h, w0l, fc0_b, h_tar,  X5h, X5l, nullptr, nullptr, D0, 16  };
        sgs.s[1] = { mkh, mkl, w0h, w0l, fc0_b, h_mask, nullptr, nullptr, nullptr, nullptr, D0, 32 };
        sgs.s[2] = { f1h, f1l, w1h, w1l, fc1_b, h_nei0, nullptr, nullptr, nullptr, nullptr, D1, 96 };
        sgs.s[3] = { f2h, f2l, w2h, w2l, fc2_b, h_nei1, nullptr, nullptr, nullptr, nullptr, D1, 160 };
        hmma_gemm<1,2><<<dim3(Hdim/128, 160), 256>>>(sgs, Hdim, nullptr, nullptr);
    }

    // ---- neighbor mean aggregation (both matrices in one launch) ----
    spmm2_kernel<<<dim3(Ndim, 2), 256>>>(nei0, nei1, h_nei0, h_nei1, g0h, g0l, g1h, g1l);

    // ---- agg GEMMs (HMMA MT=1, 256 blocks): emit views/masks planes into X5 ----
    {
        SegsH sgs;
        sgs.nseg = 2;
        sgs.s[0] = { g0h, g0l, a0h, a0l, nullptr, nullptr,
                     X5h + 1*NH, X5l + 1*NH, X5h + 2*NH, X5l + 2*NH, Hdim, 32 };
        sgs.s[1] = { g1h, g1l, a1h, a1l, nullptr, nullptr,
                     X5h + 3*NH, X5l + 3*NH, X5h + 4*NH, X5l + 4*NH, Hdim, 64 };
        sgs.s[2] = sgs.s[1]; sgs.s[3] = sgs.s[1];
        hmma_gemm<2,1><<<dim3(Hdim/128, 64), 256>>>(sgs, Hdim, h_tar, h_mask);
    }

    // ---- GCN stage A: xw = X5 @ gcn_w1 (stacked HMMA, M=5120, K=512) ----
    hmma_gemm64<<<5*Ndim/64, 256>>>(X5h, X5l, gw1h, gw1l, xw_all, Hdim);

    // ---- GCN stage B: h1 = relu(adj @ xw + b1) -> bf16 planes ----
    {
        Adj4 oth = {{ adj0, madj0, adj1, madj1 }};
        gcn_spmm_kernel<<<dim3(Ndim, 5), 64>>>(adj0, adj1, oth, xw_all, gcn_b1,
                                               nullptr, h1bh, h1bl, 1, 0, 1);
    }
    // ---- GCN stage C: hw = h1 @ gcn_w2 (stacked HMMA, M=5120, K=64) ----
    hmma_gemm64<<<5*Ndim/64, 256>>>(h1bh, h1bl, gw2h, gw2l, hw_all, Edim);

    // ---- GCN stage D: z = adj @ hw + b2, fused l2norm for views ----
    {
        Adj4 oth = {{ adj0, madj0, adj1, madj1 }};
        gcn_spmm_kernel<<<dim3(Ndim, 5), 64>>>(adj0, adj1, oth, hw_all, gcn_b2,
                                               z_all, nullptr, nullptr, 0, 1, 0);
    }

    // ---- semantic attention over (already normalized) hs, z_fine ----
    float* hs = z_all + NE;
    att_kernel<<<dim3(4,4), 256>>>(hs, att_w, att_b, att_vec, epart);
    beta_kernel<<<1, 1>>>(epart, beta);
    zfine_kernel<<<(NE + 255)/256, 256>>>(hs, beta, zfine, NE);

    // ---- projections with fused tanh + L2 norm ----
    {
        In5 ins = {{ z_all, zfine, zfine, zfine, zfine }};
        gemm_small<4><<<2*32, 128>>>(ins, proj_w, proj_b, z2, Edim, 32);
    }
    float* zc = z2;
    float* zf = z2 + NE;

    // ---- weighted InfoNCE ----
    u_diag_kernel<<<Ndim/16, 256>>>(zf, zc, mlp1_w, mlp1_b, Uf, Uc, diag);
    pair_kernel<<<dim3(64, 64), 256>>>(zf, zc, Uf, Uc, mlp2_w, mlp2_b, part);
    loss_kernel<<<1, 256>>>(part, diag, (float*)d_out);
}

// round 10
// speedup vs baseline: 2.8653x; 1.0001x over previous
#include <cuda_runtime.h>
#include <cuda_bf16.h>
#include <math.h>
#include <stdint.h>
#include <stddef.h>

#define Ndim 1024
#define Mdim 4096
#define D0 1024
#define D1 512
#define Hdim 512
#define Edim 64
#define CSR_CAP 128

typedef unsigned long long ull;
typedef __nv_bfloat16 bf16;

// ---------------- scratch (device globals; no allocation allowed) ----------------
__device__ float g_h_tar[Ndim*Hdim];
__device__ float g_h_mask[Ndim*Hdim];
__device__ float g_h_nei0[Mdim*Hdim];
__device__ float g_h_nei1[Mdim*Hdim];
__device__ float g_xw_all[5*Ndim*Edim];
__device__ float g_hw_all[5*Ndim*Edim];
__device__ float g_z_all[5*Ndim*Edim];
__device__ float g_epart[16];
__device__ float g_beta[4];
__device__ float g_zfine[Ndim*Edim];
__device__ float g_z2[2*Ndim*Edim];
__device__ float g_Uf[Ndim*16];
__device__ float g_Uc[Ndim*16];
__device__ float g_diag[Ndim];
__device__ float g_part[64*Ndim];

// CSR: slots 0=mean, 1=adj0, 2=madj0, 3=adj1, 4=madj1, 5=nei0, 6=nei1
__device__ int   g_csr_cnt[7*Ndim];
__device__ int   g_csr_full[7*Ndim];
__device__ int   g_csr_idx[7*Ndim*CSR_CAP];
__device__ float g_csr_val[7*Ndim*CSR_CAP];

// bf16 hi/lo planes
__device__ bf16 g_feat0_h[Ndim*D0],  g_feat0_l[Ndim*D0];
__device__ bf16 g_mask_h[Ndim*D0],   g_mask_l[Ndim*D0];
__device__ bf16 g_feat1_h[Mdim*D1],  g_feat1_l[Mdim*D1];
__device__ bf16 g_feat2_h[Mdim*D1],  g_feat2_l[Mdim*D1];
__device__ bf16 g_fc0w_h[D0*Hdim],   g_fc0w_l[D0*Hdim];
__device__ bf16 g_fc1w_h[D1*Hdim],   g_fc1w_l[D1*Hdim];
__device__ bf16 g_fc2w_h[D1*Hdim],   g_fc2w_l[D1*Hdim];
__device__ bf16 g_ag0w_h[Hdim*Hdim], g_ag0w_l[Hdim*Hdim];
__device__ bf16 g_ag1w_h[Hdim*Hdim], g_ag1w_l[Hdim*Hdim];
__device__ bf16 g_w1_h[Hdim*Edim],   g_w1_l[Hdim*Edim];
__device__ bf16 g_w2_h[Edim*Edim],   g_w2_l[Edim*Edim];
__device__ bf16 g_agg0_h[Ndim*Hdim], g_agg0_l[Ndim*Hdim];
__device__ bf16 g_agg1_h[Ndim*Hdim], g_agg1_l[Ndim*Hdim];
// stacked GCN input planes: slice0=h_tar, 1=views0, 2=masks0, 3=views1, 4=masks1
__device__ bf16 g_X5h[5*Ndim*Hdim], g_X5l[5*Ndim*Hdim];
// h1 planes (stage B output)
__device__ bf16 g_h1b_h[5*Ndim*Edim], g_h1b_l[5*Ndim*Edim];

__device__ __forceinline__ float eluf(float x){ return x > 0.f ? x : expm1f(x); }
__device__ __forceinline__ float fast_tanh(float x){
    x = fminf(fmaxf(x, -20.f), 20.f);
    float e = __expf(2.f*x);
    return __fdividef(e - 1.f, e + 1.f);
}
__device__ __forceinline__ ull dup2(float x){
    ull r; asm("mov.b64 %0, {%1, %1};" : "=l"(r) : "f"(x)); return r;
}
__device__ __forceinline__ ull fma2(ull a, ull b, ull c){
    ull d; asm("fma.rn.f32x2 %0, %1, %2, %3;" : "=l"(d) : "l"(a), "l"(b), "l"(c)); return d;
}
__device__ __forceinline__ void unpack2(ull v, float& lo, float& hi){
    asm("mov.b64 {%0, %1}, %2;" : "=f"(lo), "=f"(hi) : "l"(v));
}
__device__ __forceinline__ uint32_t smem_u32(const void* p){
    uint32_t r;
    asm("{ .reg .u64 t; cvta.to.shared.u64 t, %1; cvt.u32.u64 %0, t; }" : "=r"(r) : "l"(p));
    return r;
}
__device__ __forceinline__ void ldmA4(uint32_t* r, uint32_t addr){
    asm volatile("ldmatrix.sync.aligned.m8n8.x4.shared.b16 {%0,%1,%2,%3}, [%4];"
        : "=r"(r[0]),"=r"(r[1]),"=r"(r[2]),"=r"(r[3]) : "r"(addr));
}
__device__ __forceinline__ void ldmBT4(uint32_t* r, uint32_t addr){
    asm volatile("ldmatrix.sync.aligned.m8n8.x4.trans.shared.b16 {%0,%1,%2,%3}, [%4];"
        : "=r"(r[0]),"=r"(r[1]),"=r"(r[2]),"=r"(r[3]) : "r"(addr));
}
__device__ __forceinline__ void mma_bf16(float* d, const uint32_t* a, const uint32_t* b){
    asm volatile("mma.sync.aligned.m16n8k16.row.col.f32.bf16.bf16.f32 "
        "{%0,%1,%2,%3}, {%4,%5,%6,%7}, {%8,%9}, {%0,%1,%2,%3};"
        : "+f"(d[0]),"+f"(d[1]),"+f"(d[2]),"+f"(d[3])
        : "r"(a[0]),"r"(a[1]),"r"(a[2]),"r"(a[3]), "r"(b[0]),"r"(b[1]));
}
__device__ __forceinline__ void store_split2(float v0, float v1, bf16* H, bf16* L, size_t idx){
    bf16 h0 = __float2bfloat16(v0), h1 = __float2bfloat16(v1);
    bf16 l0 = __float2bfloat16(v0 - __bfloat162float(h0));
    bf16 l1 = __float2bfloat16(v1 - __bfloat162float(h1));
    __nv_bfloat162 hh; hh.x = h0; hh.y = h1;
    __nv_bfloat162 ll; ll.x = l0; ll.y = l1;
    *(__nv_bfloat162*)&H[idx] = hh;
    *(__nv_bfloat162*)&L[idx] = ll;
}

// ---------------- split: fp32 -> bf16 hi/lo planes ----------------
struct SJob { const float* s; bf16* h; bf16* l; int n4; };
struct SJobs { SJob j[11]; };

__global__ __launch_bounds__(256) void split_kernel(SJobs jobs)
{
    SJob jb = jobs.j[blockIdx.y];
    const int stride = gridDim.x * blockDim.x;
    for (int i = blockIdx.x * blockDim.x + threadIdx.x; i < jb.n4; i += stride) {
        float4 v = ((const float4*)jb.s)[i];
        bf16 h0 = __float2bfloat16(v.x);
        bf16 h1 = __float2bfloat16(v.y);
        bf16 h2 = __float2bfloat16(v.z);
        bf16 h3 = __float2bfloat16(v.w);
        bf16 l0 = __float2bfloat16(v.x - __bfloat162float(h0));
        bf16 l1 = __float2bfloat16(v.y - __bfloat162float(h1));
        bf16 l2 = __float2bfloat16(v.z - __bfloat162float(h2));
        bf16 l3 = __float2bfloat16(v.w - __bfloat162float(h3));
        ushort4 H, L;
        H.x = __bfloat16_as_ushort(h0); H.y = __bfloat16_as_ushort(h1);
        H.z = __bfloat16_as_ushort(h2); H.w = __bfloat16_as_ushort(h3);
        L.x = __bfloat16_as_ushort(l0); L.y = __bfloat16_as_ushort(l1);
        L.z = __bfloat16_as_ushort(l2); L.w = __bfloat16_as_ushort(l3);
        ((ushort4*)jb.h)[i] = H;
        ((ushort4*)jb.l)[i] = L;
    }
}

// ---------------- CSR build: ballot compaction of 7 sparse operands ----------------
__global__ __launch_bounds__(128) void csr_build_kernel(
    const float* __restrict__ adj0, const float* __restrict__ adj1,
    const float* __restrict__ madj0, const float* __restrict__ madj1,
    const float* __restrict__ nei0, const float* __restrict__ nei1)
{
    const int slot = blockIdx.y;
    const int row  = blockIdx.x;
    const int tid  = threadIdx.x;
    const int lane = tid & 31;
    const int wrp  = tid >> 5;
    __shared__ int warpTot[4];
    __shared__ int warpBase[4];
    __shared__ int s_tot;

    const float* A; const float* B = nullptr; int ncols;
    switch (slot) {
        case 0:  A = adj0;  B = adj1; ncols = Ndim; break;
        case 1:  A = adj0;  ncols = Ndim; break;
        case 2:  A = madj0; ncols = Ndim; break;
        case 3:  A = adj1;  ncols = Ndim; break;
        case 4:  A = madj1; ncols = Ndim; break;
        case 5:  A = nei0;  ncols = Mdim; break;
        default: A = nei1;  ncols = Mdim; break;
    }
    const float4* r0 = (const float4*)(A + (size_t)row * ncols);
    const float4* r1 = B ? (const float4*)(B + (size_t)row * ncols) : nullptr;
    int*   oid = g_csr_idx + ((size_t)slot * Ndim + row) * CSR_CAP;
    float* ova = g_csr_val + ((size_t)slot * Ndim + row) * CSR_CAP;
    const int nchunk = ncols / 512;   // 128 threads x 4 floats

    int base = 0;
    for (int chunk = 0; chunk < nchunk; chunk++) {
        float4 v = r0[chunk * 128 + tid];
        if (r1) {
            float4 w = r1[chunk * 128 + tid];
            v.x = 0.5f * (v.x + w.x); v.y = 0.5f * (v.y + w.y);
            v.z = 0.5f * (v.z + w.z); v.w = 0.5f * (v.w + w.w);
        }
        int m = (v.x != 0.f ? 1 : 0) | (v.y != 0.f ? 2 : 0)
              | (v.z != 0.f ? 4 : 0) | (v.w != 0.f ? 8 : 0);
        int c = __popc(m);
        int incl = c;
        #pragma unroll
        for (int o = 1; o < 32; o <<= 1) {
            int n = __shfl_up_sync(0xffffffffu, incl, o);
            if (lane >= o) incl += n;
        }
        if (lane == 31) warpTot[wrp] = incl;
        __syncthreads();
        if (tid == 0) {
            int r = 0;
            #pragma unroll
            for (int i = 0; i < 4; i++) { warpBase[i] = r; r += warpTot[i]; }
            s_tot = r;
        }
        __syncthreads();
        int off = base + warpBase[wrp] + incl - c;
        const int colbase = (chunk * 128 + tid) * 4;
        if (m & 1) { if (off < CSR_CAP) { oid[off] = colbase;     ova[off] = v.x; } off++; }
        if (m & 2) { if (off < CSR_CAP) { oid[off] = colbase + 1; ova[off] = v.y; } off++; }
        if (m & 4) { if (off < CSR_CAP) { oid[off] = colbase + 2; ova[off] = v.z; } off++; }
        if (m & 8) { if (off < CSR_CAP) { oid[off] = colbase + 3; ova[off] = v.w; } off++; }
        base += s_tot;
        __syncthreads();
    }
    if (tid == 0) {
        g_csr_cnt[slot * Ndim + row]  = min(base, CSR_CAP);
        g_csr_full[slot * Ndim + row] = base;
    }
}

// ================= HMMA GEMM: bf16-split 3-product, reg-prefetch, templated BM ====
// BM = 32*MT, BN=128, BK=32, 256 threads (8 warps: 2m x 4n), warp tile (16*MT)x32.
// EPI 1: C=elu(v+bias) fp32, optional split planes Bh/Bl.
// EPI 2: planes Bh/Bl = split(elu(aux0+v)), B2h/B2l = split(elu(aux1+v)). No fp32 out.
struct SegH { const bf16 *Ah, *Al, *Wh, *Wl; const float* bias;
              float* C; bf16 *Bh, *Bl, *B2h, *B2l; int K; int tileEnd; };
struct SegsH { SegH s[4]; int nseg; };

template<int EPI, int MT>
__global__ __launch_bounds__(256, (MT < 4) ? 2 : 1) void hmma_gemm(
    SegsH segs, int Nd, const float* __restrict__ aux0, const float* __restrict__ aux1)
{
    constexpr int BM = 32 * MT;
    __shared__ __align__(16) bf16 Ah_s[BM][40];
    __shared__ __align__(16) bf16 Al_s[BM][40];
    __shared__ __align__(16) bf16 Wh_s[32][136];
    __shared__ __align__(16) bf16 Wl_s[32][136];

    const int tid = threadIdx.x;
    const int by  = blockIdx.y;
    int si = 0, tileStart = 0;
    #pragma unroll
    for (int i = 0; i < 3; i++)
        if (i < segs.nseg && by >= segs.s[i].tileEnd) { si = i + 1; tileStart = segs.s[i].tileEnd; }
    const SegH sg = segs.s[si];
    const int K  = sg.K;
    const int bm = (by - tileStart) * BM;
    const int bn = blockIdx.x * 128;

    const int lane = tid & 31;
    const int w    = tid >> 5;
    const int wm   = w >> 2;
    const int wn   = w & 3;

    // A loader mapping
    int arow, aseg; bool aact;
    if constexpr (MT == 4)      { arow = tid >> 1;        aseg = (tid & 1) * 16; aact = true; }
    else if constexpr (MT == 2) { arow = tid >> 2;        aseg = (tid & 3) * 8;  aact = true; }
    else                        { arow = (tid >> 2) & 31; aseg = (tid & 3) * 8;  aact = (tid < 128); }
    const int krow = tid >> 3;
    const int nsg  = (tid & 7) * 16;

    const uint32_t aBaseH = smem_u32(&Ah_s[0][0]);
    const uint32_t aBaseL = smem_u32(&Al_s[0][0]);
    const uint32_t wBaseH = smem_u32(&Wh_s[0][0]);
    const uint32_t wBaseL = smem_u32(&Wl_s[0][0]);
    const uint32_t aoff = ((wm*16*MT + (lane & 15)) * 40 + (lane >> 4) * 8) * 2;
    const uint32_t boff = ((lane & 15) * 136 + wn*32 + (lane >> 4) * 8) * 2;

    const bf16* Agh = sg.Ah + (size_t)(bm + arow) * K + aseg;
    const bf16* Agl = sg.Al + (size_t)(bm + arow) * K + aseg;
    const bf16* Wgh = sg.Wh + (size_t)krow * Nd + bn + nsg;
    const bf16* Wgl = sg.Wl + (size_t)krow * Nd + bn + nsg;

    float d[MT][4][4];
    #pragma unroll
    for (int mt = 0; mt < MT; mt++)
        #pragma unroll
        for (int nt = 0; nt < 4; nt++)
            #pragma unroll
            for (int q = 0; q < 4; q++) d[mt][nt][q] = 0.f;

    const int nk = K >> 5;

    uint4 ah0 = {}, ah1 = {}, al0 = {}, al1 = {};
    uint4 wh0, wh1, wl0, wl1;
    if (aact) {
        ah0 = *(const uint4*)(Agh);
        al0 = *(const uint4*)(Agl);
        if constexpr (MT == 4) { ah1 = *(const uint4*)(Agh + 8); al1 = *(const uint4*)(Agl + 8); }
    }
    wh0 = *(const uint4*)(Wgh);  wh1 = *(const uint4*)(Wgh + 8);
    wl0 = *(const uint4*)(Wgl);  wl1 = *(const uint4*)(Wgl + 8);
    if (aact) {
        *(uint4*)&Ah_s[arow][aseg] = ah0;
        *(uint4*)&Al_s[arow][aseg] = al0;
        if constexpr (MT == 4) { *(uint4*)&Ah_s[arow][aseg+8] = ah1; *(uint4*)&Al_s[arow][aseg+8] = al1; }
    }
    *(uint4*)&Wh_s[krow][nsg]   = wh0;  *(uint4*)&Wh_s[krow][nsg+8] = wh1;
    *(uint4*)&Wl_s[krow][nsg]   = wl0;  *(uint4*)&Wl_s[krow][nsg+8] = wl1;
    __syncthreads();

    for (int t = 0; t < nk; t++) {
        const bool has = (t + 1 < nk);
        if (has) {
            const int k0 = (t + 1) * 32;
            if (aact) {
                ah0 = *(const uint4*)(Agh + k0);
                al0 = *(const uint4*)(Agl + k0);
                if constexpr (MT == 4) { ah1 = *(const uint4*)(Agh + k0 + 8); al1 = *(const uint4*)(Agl + k0 + 8); }
            }
            wh0 = *(const uint4*)(Wgh + (size_t)k0 * Nd);  wh1 = *(const uint4*)(Wgh + (size_t)k0 * Nd + 8);
            wl0 = *(const uint4*)(Wgl + (size_t)k0 * Nd);  wl1 = *(const uint4*)(Wgl + (size_t)k0 * Nd + 8);
        }
        #pragma unroll
        for (int ks = 0; ks < 2; ks++) {
            uint32_t ah[MT][4], al[MT][4];
            #pragma unroll
            for (int mt = 0; mt < MT; mt++) {
                const uint32_t o = aoff + (mt * 16 * 40 + ks * 16) * 2;
                ldmA4(ah[mt], aBaseH + o);
                ldmA4(al[mt], aBaseL + o);
            }
            uint32_t bh[2][4], bl[2][4];
            #pragma unroll
            for (int np = 0; np < 2; np++) {
                const uint32_t o = boff + (ks * 16 * 136 + np * 16) * 2;
                ldmBT4(bh[np], wBaseH + o);
                ldmBT4(bl[np], wBaseL + o);
            }
            // product-outer order: consecutive MMAs never share an accumulator
            #pragma unroll
            for (int p = 0; p < 3; p++) {
                #pragma unroll
                for (int mt = 0; mt < MT; mt++) {
                    #pragma unroll
                    for (int nt = 0; nt < 4; nt++) {
                        const uint32_t* bph = &bh[nt >> 1][(nt & 1) * 2];
                        const uint32_t* bpl = &bl[nt >> 1][(nt & 1) * 2];
                        const uint32_t* aa = (p == 0) ? al[mt] : ah[mt];
                        const uint32_t* bb = (p == 1) ? bpl : bph;
                        mma_bf16(d[mt][nt], aa, bb);
                    }
                }
            }
        }
        if (has) {
            __syncthreads();
            if (aact) {
                *(uint4*)&Ah_s[arow][aseg] = ah0;
                *(uint4*)&Al_s[arow][aseg] = al0;
                if constexpr (MT == 4) { *(uint4*)&Ah_s[arow][aseg+8] = ah1; *(uint4*)&Al_s[arow][aseg+8] = al1; }
            }
            *(uint4*)&Wh_s[krow][nsg]   = wh0;  *(uint4*)&Wh_s[krow][nsg+8] = wh1;
            *(uint4*)&Wl_s[krow][nsg]   = wl0;  *(uint4*)&Wl_s[krow][nsg+8] = wl1;
            __syncthreads();
        }
    }

    // epilogue
    const int g  = lane >> 2;
    const int tq = lane & 3;
    #pragma unroll
    for (int mt = 0; mt < MT; mt++) {
        #pragma unroll
        for (int nt = 0; nt < 4; nt++) {
            const int r = bm + wm*16*MT + mt*16 + g;
            const int c = bn + wn*32 + nt*8 + tq*2;
            #pragma unroll
            for (int half = 0; half < 2; half++) {
                const int rr = r + half * 8;
                float v0 = d[mt][nt][half*2 + 0];
                float v1 = d[mt][nt][half*2 + 1];
                const size_t idx = (size_t)rr * Nd + c;
                if (EPI == 1) {
                    v0 = eluf(v0 + sg.bias[c]); v1 = eluf(v1 + sg.bias[c+1]);
                    *(float2*)&sg.C[idx] = make_float2(v0, v1);
                    if (sg.Bh) store_split2(v0, v1, sg.Bh, sg.Bl, idx);
                } else if (EPI == 2) {
                    float2 a0 = *(const float2*)&aux0[idx];
                    float2 a1 = *(const float2*)&aux1[idx];
                    store_split2(eluf(a0.x + v0), eluf(a0.y + v1), sg.Bh,  sg.Bl,  idx);
                    store_split2(eluf(a1.x + v0), eluf(a1.y + v1), sg.B2h, sg.B2l, idx);
                }
            }
        }
    }
}

// ================= hmma_gemm64: N=64 GEMM (GCN stages A and C) ===================
// BM=64, BN=64, BK=32, 256 threads (8 warps: 4m x 2n), warp tile 16x32.
__global__ __launch_bounds__(256) void hmma_gemm64(
    const bf16* __restrict__ Ah, const bf16* __restrict__ Al,
    const bf16* __restrict__ Wh, const bf16* __restrict__ Wl,
    float* __restrict__ out, int K)
{
    __shared__ __align__(16) bf16 Ah_s[64][40];
    __shared__ __align__(16) bf16 Al_s[64][40];
    __shared__ __align__(16) bf16 Wh_s[32][72];
    __shared__ __align__(16) bf16 Wl_s[32][72];

    const int tid = threadIdx.x;
    const int bm = blockIdx.x * 64;
    const int lane = tid & 31;
    const int w    = tid >> 5;
    const int wm   = w >> 1;    // 0..3
    const int wn   = w & 1;     // 0..1

    const int arow = tid >> 2;          // 0..63
    const int acol = (tid & 3) * 8;     // 0..24
    const int krow = tid >> 3;          // 0..31
    const int ncol = (tid & 7) * 8;     // 0..56

    const uint32_t aBaseH = smem_u32(&Ah_s[0][0]);
    const uint32_t aBaseL = smem_u32(&Al_s[0][0]);
    const uint32_t wBaseH = smem_u32(&Wh_s[0][0]);
    const uint32_t wBaseL = smem_u32(&Wl_s[0][0]);
    const uint32_t aoff = ((wm*16 + (lane & 15)) * 40 + (lane >> 4) * 8) * 2;
    const uint32_t boff = ((lane & 15) * 72 + wn*32 + (lane >> 4) * 8) * 2;

    const bf16* Agh = Ah + (size_t)(bm + arow) * K + acol;
    const bf16* Agl = Al + (size_t)(bm + arow) * K + acol;
    const bf16* Wgh = Wh + (size_t)krow * Edim + ncol;
    const bf16* Wgl = Wl + (size_t)krow * Edim + ncol;

    float d[4][4];
    #pragma unroll
    for (int nt = 0; nt < 4; nt++)
        #pragma unroll
        for (int q = 0; q < 4; q++) d[nt][q] = 0.f;

    const int nk = K >> 5;

    uint4 aH = *(const uint4*)(Agh);
    uint4 aL = *(const uint4*)(Agl);
    uint4 wH = *(const uint4*)(Wgh);
    uint4 wL = *(const uint4*)(Wgl);
    *(uint4*)&Ah_s[arow][acol] = aH;
    *(uint4*)&Al_s[arow][acol] = aL;
    *(uint4*)&Wh_s[krow][ncol] = wH;
    *(uint4*)&Wl_s[krow][ncol] = wL;
    __syncthreads();

    for (int t = 0; t < nk; t++) {
        const bool has = (t + 1 < nk);
        if (has) {
            const int k0 = (t + 1) * 32;
            aH = *(const uint4*)(Agh + k0);
            aL = *(const uint4*)(Agl + k0);
            wH = *(const uint4*)(Wgh + (size_t)k0 * Edim);
            wL = *(const uint4*)(Wgl + (size_t)k0 * Edim);
        }
        #pragma unroll
        for (int ks = 0; ks < 2; ks++) {
            uint32_t ah[4], al[4];
            {
                const uint32_t o = aoff + (ks * 16) * 2;
                ldmA4(ah, aBaseH + o);
                ldmA4(al, aBaseL + o);
            }
            uint32_t bh[2][4], bl[2][4];
            #pragma unroll
            for (int np = 0; np < 2; np++) {
                const uint32_t o = boff + (ks * 16 * 72 + np * 16) * 2;
                ldmBT4(bh[np], wBaseH + o);
                ldmBT4(bl[np], wBaseL + o);
            }
            #pragma unroll
            for (int p = 0; p < 3; p++) {
                #pragma unroll
                for (int nt = 0; nt < 4; nt++) {
                    const uint32_t* bph = &bh[nt >> 1][(nt & 1) * 2];
                    const uint32_t* bpl = &bl[nt >> 1][(nt & 1) * 2];
                    const uint32_t* aa = (p == 0) ? al : ah;
                    const uint32_t* bb = (p == 1) ? bpl : bph;
                    mma_bf16(d[nt], aa, bb);
                }
            }
        }
        if (has) {
            __syncthreads();
            *(uint4*)&Ah_s[arow][acol] = aH;
            *(uint4*)&Al_s[arow][acol] = aL;
            *(uint4*)&Wh_s[krow][ncol] = wH;
            *(uint4*)&Wl_s[krow][ncol] = wL;
            __syncthreads();
        }
    }

    const int g  = lane >> 2;
    const int tq = lane & 3;
    #pragma unroll
    for (int nt = 0; nt < 4; nt++) {
        #pragma unroll
        for (int half = 0; half < 2; half++) {
            const int rr = bm + wm*16 + g + half*8;
            const int c  = wn*32 + nt*8 + tq*2;
            *(float2*)&out[(size_t)rr * Edim + c] =
                make_float2(d[nt][half*2 + 0], d[nt][half*2 + 1]);
        }
    }
}

// ================= small GEMM: N=64, batched, f32x2; ACT 4 = tanh + row L2norm ====
struct In5 { const float* p[5]; };

template<int ACT>
__global__ __launch_bounds__(128) void gemm_small(
    In5 ins, const float* __restrict__ W, const float* __restrict__ bias,
    float* __restrict__ out, int K, int tilesPer)
{
    __shared__ __align__(16) float As[16][32];
    __shared__ __align__(16) float Bs[16][64];
    const int tid = threadIdx.x;
    const int g  = blockIdx.x / tilesPer;
    const int tb = blockIdx.x % tilesPer;
    const float* A = ins.p[g] + (size_t)tb * 32 * K;
    float* C = out + ((size_t)g * tilesPer * 32 + tb * 32) * 64;

    const int tx = tid & 15;
    const int ty = tid >> 4;
    const int ar = tid >> 2, akc = (tid & 3) * 4;
    const int br = tid >> 4, bc = (tid & 15) * 4;

    ull acc[4][2];
    #pragma unroll
    for (int i = 0; i < 4; i++) { acc[i][0] = 0ull; acc[i][1] = 0ull; }

    for (int k0 = 0; k0 < K; k0 += 16) {
        float4 av  = *(const float4*)(A + (size_t)ar * K + k0 + akc);
        float4 bv0 = *(const float4*)(W + (size_t)(k0 + br) * 64 + bc);
        float4 bv1 = *(const float4*)(W + (size_t)(k0 + br + 8) * 64 + bc);
        __syncthreads();
        As[akc+0][ar] = av.x; As[akc+1][ar] = av.y; As[akc+2][ar] = av.z; As[akc+3][ar] = av.w;
        *(float4*)&Bs[br][bc]   = bv0;
        *(float4*)&Bs[br+8][bc] = bv1;
        __syncthreads();
        #pragma unroll
        for (int kk = 0; kk < 16; kk++) {
            float4 av2 = *(const float4*)&As[kk][ty*4];
            ulonglong2 bp = *(const ulonglong2*)&Bs[kk][tx*4];
            ull a2[4] = {dup2(av2.x), dup2(av2.y), dup2(av2.z), dup2(av2.w)};
            #pragma unroll
            for (int i = 0; i < 4; i++) {
                acc[i][0] = fma2(a2[i], bp.x, acc[i][0]);
                acc[i][1] = fma2(a2[i], bp.y, acc[i][1]);
            }
        }
    }
    if (ACT == 4) {
        float vr[4][4];
        #pragma unroll
        for (int i = 0; i < 4; i++) {
            #pragma unroll
            for (int j = 0; j < 2; j++) {
                float v0, v1; unpack2(acc[i][j], v0, v1);
                const int c = tx * 4 + 2 * j;
                vr[i][2*j]   = tanhf(v0 + bias[c]);
                vr[i][2*j+1] = tanhf(v1 + bias[c+1]);
            }
        }
        #pragma unroll
        for (int i = 0; i < 4; i++) {
            float s = vr[i][0]*vr[i][0] + vr[i][1]*vr[i][1]
                    + vr[i][2]*vr[i][2] + vr[i][3]*vr[i][3];
            #pragma unroll
            for (int o = 8; o > 0; o >>= 1) s += __shfl_xor_sync(0xffffffffu, s, o, 16);
            const float inv = 1.f / fmaxf(sqrtf(s), 1e-12f);
            const int row = ty * 4 + i;
            *(float4*)&C[(size_t)row * 64 + tx * 4] =
                make_float4(vr[i][0]*inv, vr[i][1]*inv, vr[i][2]*inv, vr[i][3]*inv);
        }
    } else {
        #pragma unroll
        for (int i = 0; i < 4; i++) {
            const int row = ty * 4 + i;
            #pragma unroll
            for (int j = 0; j < 2; j++) {
                float v0, v1; unpack2(acc[i][j], v0, v1);
                const int c = tx * 4 + 2 * j;
                if (bias) { v0 += bias[c]; v1 += bias[c+1]; }
                if (ACT == 3) { v0 = tanhf(v0); v1 = tanhf(v1); }
                *(float2*)&C[(size_t)row * 64 + c] = make_float2(v0, v1);
            }
        }
    }
}

// ========== nei SpMM gather (CSR slots 5,6): mean over nnz -> bf16 planes ==========
__global__ __launch_bounds__(256) void spmm2_gather_kernel(
    const float* __restrict__ X0, const float* __restrict__ X1,
    bf16* __restrict__ Y0h, bf16* __restrict__ Y0l,
    bf16* __restrict__ Y1h, bf16* __restrict__ Y1l)
{
    __shared__ int   s_idx[CSR_CAP];
    __shared__ float s_val[CSR_CAP];
    const int row = blockIdx.x;
    const int which = blockIdx.y;
    const int slot = 5 + which;
    const int tid = threadIdx.x;
    const int cnt  = g_csr_cnt[slot * Ndim + row];
    const int full = g_csr_full[slot * Ndim + row];
    const int*   oid = g_csr_idx + ((size_t)slot * Ndim + row) * CSR_CAP;
    const float* ova = g_csr_val + ((size_t)slot * Ndim + row) * CSR_CAP;
    if (tid < cnt) { s_idx[tid] = oid[tid]; s_val[tid] = ova[tid]; }
    __syncthreads();
    const float inv = 1.f / fmaxf((float)full, 1.f);
    const float* X = which ? X1 : X0;
    bf16* Yh = which ? Y1h : Y0h;
    bf16* Yl = which ? Y1l : Y0l;
    const float2* Xp = (const float2*)X + tid;
    float2 acc = make_float2(0.f, 0.f);
    int t = 0;
    for (; t + 4 <= cnt; t += 4) {
        int i0 = s_idx[t], i1 = s_idx[t+1], i2 = s_idx[t+2], i3 = s_idx[t+3];
        float w0 = s_val[t], w1 = s_val[t+1], w2 = s_val[t+2], w3 = s_val[t+3];
        float2 x0 = Xp[(size_t)i0 * 256];
        float2 x1 = Xp[(size_t)i1 * 256];
        float2 x2 = Xp[(size_t)i2 * 256];
        float2 x3 = Xp[(size_t)i3 * 256];
        acc.x += w0*x0.x + w1*x1.x + w2*x2.x + w3*x3.x;
        acc.y += w0*x0.y + w1*x1.y + w2*x2.y + w3*x3.y;
    }
    for (; t < cnt; t++) {
        int i0 = s_idx[t]; float w0 = s_val[t];
        float2 x0 = Xp[(size_t)i0 * 256];
        acc.x += w0 * x0.x; acc.y += w0 * x0.y;
    }
    store_split2(acc.x * inv, acc.y * inv, Yh, Yl, (size_t)row * Hdim + tid * 2);
}

// ========== GCN SpMM gather (CSR slots 0..4) ==========
// planes=1: write relu'd result as bf16 hi/lo planes. planes=0: fp32 (+optional l2norm g>0).
__global__ __launch_bounds__(64) void gcn_gather_kernel(
    const float* __restrict__ Xall, const float* __restrict__ bias,
    float* __restrict__ Yall, bf16* __restrict__ Yh, bf16* __restrict__ Yl,
    int relu, int donorm, int planes)
{
    __shared__ int   s_idx[CSR_CAP];
    __shared__ float s_val[CSR_CAP];
    __shared__ float s_sq[2];
    const int g   = blockIdx.y;       // slot 0..4
    const int row = blockIdx.x;
    const int tid = threadIdx.x;
    const int lane = tid & 31;
    const int wrp  = tid >> 5;
    const float* X = Xall + (size_t)g * Ndim * Edim;
    const int cnt = g_csr_cnt[g * Ndim + row];
    const int*   oid = g_csr_idx + ((size_t)g * Ndim + row) * CSR_CAP;
    const float* ova = g_csr_val + ((size_t)g * Ndim + row) * CSR_CAP;
    for (int i = tid; i < cnt; i += 64) { s_idx[i] = oid[i]; s_val[i] = ova[i]; }
    __syncthreads();
    const int e = tid;
    float v = 0.f;
    int t = 0;
    for (; t + 4 <= cnt; t += 4) {
        int i0 = s_idx[t], i1 = s_idx[t+1], i2 = s_idx[t+2], i3 = s_idx[t+3];
        float w0 = s_val[t], w1 = s_val[t+1], w2 = s_val[t+2], w3 = s_val[t+3];
        v += w0 * X[(size_t)i0 * Edim + e] + w1 * X[(size_t)i1 * Edim + e]
           + w2 * X[(size_t)i2 * Edim + e] + w3 * X[(size_t)i3 * Edim + e];
    }
    for (; t < cnt; t++) v += s_val[t] * X[(size_t)s_idx[t] * Edim + e];
    v += bias[e];
    if (relu) v = fmaxf(v, 0.f);
    const size_t oidx = (size_t)g * Ndim * Edim + (size_t)row * Edim + e;
    if (planes) {
        bf16 h = __float2bfloat16(v);
        Yh[oidx] = h;
        Yl[oidx] = __float2bfloat16(v - __bfloat162float(h));
        return;
    }
    if (donorm && g > 0) {
        float sq = v * v;
        #pragma unroll
        for (int o = 16; o > 0; o >>= 1) sq += __shfl_xor_sync(0xffffffffu, sq, o);
        if (lane == 0) s_sq[wrp] = sq;
        __syncthreads();
        const float nrm = fmaxf(sqrtf(s_sq[0] + s_sq[1]), 1e-12f);
        v /= nrm;
    }
    Yall[oidx] = v;
}

// ---------------- elementwise / tail kernels ----------------
__global__ __launch_bounds__(256) void att_kernel(
    const float* __restrict__ hs, const float* __restrict__ att_w,
    const float* __restrict__ att_b, const float* __restrict__ att_vec,
    float* __restrict__ epart)
{
    __shared__ float w_s[64*64];
    __shared__ float b_s[64];
    __shared__ float v_s[64];
    __shared__ float red[256];
    const int tid = threadIdx.x;
    for (int i = tid; i < 64*64; i += 256) w_s[i] = att_w[i];
    if (tid < 64) { b_s[tid] = att_b[tid]; v_s[tid] = att_vec[tid]; }
    __syncthreads();
    const int v = blockIdx.y;
    const int n = blockIdx.x * 256 + tid;
    const float* row = hs + ((size_t)v * Ndim + n) * 64;
    float r[64];
    #pragma unroll
    for (int f = 0; f < 64; f++) r[f] = row[f];
    float s = 0.f;
    for (int e = 0; e < 64; e++) {
        float acc = b_s[e];
        #pragma unroll
        for (int f = 0; f < 64; f++) acc += r[f] * w_s[f*64 + e];
        s += v_s[e] * tanhf(acc);
    }
    red[tid] = s;
    __syncthreads();
    for (int st = 128; st > 0; st >>= 1) {
        if (tid < st) red[tid] += red[tid + st];
        __syncthreads();
    }
    if (tid == 0) epart[v*4 + blockIdx.x] = red[0];
}

__global__ void beta_kernel(const float* __restrict__ epart, float* __restrict__ beta)
{
    float e[4];
    float m = -1e30f;
    for (int v = 0; v < 4; v++) {
        e[v] = (epart[v*4+0] + epart[v*4+1] + epart[v*4+2] + epart[v*4+3]) / (float)Ndim;
        m = fmaxf(m, e[v]);
    }
    float s = 0.f;
    for (int v = 0; v < 4; v++) { float b = expf(e[v] - m); beta[v] = b; s += b; }
    for (int v = 0; v < 4; v++) beta[v] /= s;
}

__global__ void zfine_kernel(const float* __restrict__ hs, const float* __restrict__ beta,
                             float* __restrict__ zfine, int n)
{
    int i = blockIdx.x * blockDim.x + threadIdx.x;
    if (i < n) {
        float s = beta[0]*hs[i] + beta[1]*hs[(size_t)Ndim*Edim + i]
                + beta[2]*hs[(size_t)2*Ndim*Edim + i] + beta[3]*hs[(size_t)3*Ndim*Edim + i];
        zfine[i] = s;
    }
}

__global__ __launch_bounds__(256) void u_diag_kernel(
    const float* __restrict__ zf, const float* __restrict__ zc,
    const float* __restrict__ mlp1_w, const float* __restrict__ mlp1_b,
    float* __restrict__ Uf, float* __restrict__ Uc, float* __restrict__ diag)
{
    __shared__ float w_s[64*16];
    const int tid = threadIdx.x;
    for (int i = tid; i < 64*16; i += 256) w_s[i] = mlp1_w[i];
    __syncthreads();
    const int n = blockIdx.x * 16 + (tid >> 4);
    const int k = tid & 15;
    const float* zfr = zf + (size_t)n * 64;
    const float* zcr = zc + (size_t)n * 64;
    float af = 0.f, acr = 0.f;
    #pragma unroll
    for (int e = 0; e < 64; e++) {
        float w = w_s[e*16 + k];
        af  += zfr[e] * w;
        acr += zcr[e] * w;
    }
    Uf[(size_t)n*16 + k] = af + mlp1_b[k];
    Uc[(size_t)n*16 + k] = acr;
    float p = 0.f;
    #pragma unroll
    for (int e = 0; e < 4; e++) p += zfr[4*k + e] * zcr[4*k + e];
    #pragma unroll
    for (int o = 8; o > 0; o >>= 1) p += __shfl_down_sync(0xffffffffu, p, o, 16);
    if (k == 0) diag[n] = 2.f * p;
}

__global__ __launch_bounds__(256) void pair_kernel(
    const float* __restrict__ zf, const float* __restrict__ zc,
    const float* __restrict__ Uf, const float* __restrict__ Uc,
    const float* __restrict__ mlp2_w, const float* __restrict__ mlp2_b,
    float* __restrict__ part)
{
    __shared__ float zf_s[16][68];
    __shared__ float zc_s[16][68];
    __shared__ float uc_s[16][17];
    __shared__ float m2_s[16];
    const int tid = threadIdx.x;
    const int bi = blockIdx.y * 16;
    const int bj = blockIdx.x * 16;
    const int lr = tid >> 4, lc = (tid & 15) << 2;
    *(float4*)&zf_s[lr][lc] = *(const float4*)(zf + (size_t)(bi + lr) * 64 + lc);
    *(float4*)&zc_s[lr][lc] = *(const float4*)(zc + (size_t)(bj + lr) * 64 + lc);
    uc_s[tid >> 4][tid & 15] = Uc[(size_t)(bj + (tid >> 4)) * 16 + (tid & 15)];
    if (tid < 16) m2_s[tid] = mlp2_w[tid];
    __syncthreads();
    const int ti = tid >> 4, tj = tid & 15;
    const int i = bi + ti;
    float uf[16];
    #pragma unroll
    for (int k = 0; k < 16; k++) uf[k] = Uf[(size_t)i*16 + k];
    float dot = 0.f;
    #pragma unroll
    for (int e = 0; e < 64; e++) dot += zf_s[ti][e] * zc_s[tj][e];
    float sacc = mlp2_b[0];
    #pragma unroll
    for (int k = 0; k < 16; k++) sacc += m2_s[k] * fast_tanh(uf[k] + uc_s[tj][k]);
    float w = 1.f / (1.f + __expf(-fminf(fmaxf(sacc, -30.f), 30.f)));
    float contrib = __expf(2.f * dot) * w;
    #pragma unroll
    for (int off = 8; off > 0; off >>= 1)
        contrib += __shfl_down_sync(0xffffffffu, contrib, off, 16);
    if (tj == 0) part[(size_t)blockIdx.x * Ndim + i] = contrib;
}

__global__ void loss_kernel(const float* __restrict__ part, const float* __restrict__ diag,
                            float* __restrict__ out)
{
    __shared__ float red[256];
    const int tid = threadIdx.x;
    float s = 0.f;
    for (int i = tid; i < Ndim; i += 256) {
        float d = 0.f;
        for (int b = 0; b < 64; b++) d += part[(size_t)b * Ndim + i];
        s += logf(d) - diag[i];
    }
    red[tid] = s;
    __syncthreads();
    for (int st = 128; st > 0; st >>= 1) {
        if (tid < st) red[tid] += red[tid + st];
        __syncthreads();
    }
    if (tid == 0) out[0] = red[0] / (float)Ndim;
}

// ---------------- host ----------------
static float* devptr(const void* sym) {
    void* p = nullptr;
    cudaGetSymbolAddress(&p, sym);
    return (float*)p;
}
static bf16* devptrb(const void* sym) {
    void* p = nullptr;
    cudaGetSymbolAddress(&p, sym);
    return (bf16*)p;
}

extern "C" void kernel_launch(void* const* d_in, const int* in_sizes, int n_in,
                              void* d_out, int out_size)
{
    const float* feat0     = (const float*)d_in[0];
    const float* feat1     = (const float*)d_in[1];
    const float* feat2     = (const float*)d_in[2];
    const float* mask_feat = (const float*)d_in[3];
    const float* nei0      = (const float*)d_in[4];
    const float* nei1      = (const float*)d_in[5];
    const float* adj0      = (const float*)d_in[6];
    const float* adj1      = (const float*)d_in[7];
    const float* madj0     = (const float*)d_in[8];
    const float* madj1     = (const float*)d_in[9];
    const float* fc0_w     = (const float*)d_in[10];
    const float* fc0_b     = (const float*)d_in[11];
    const float* fc1_w     = (const float*)d_in[12];
    const float* fc1_b     = (const float*)d_in[13];
    const float* fc2_w     = (const float*)d_in[14];
    const float* fc2_b     = (const float*)d_in[15];
    const float* agg0_w    = (const float*)d_in[16];
    const float* agg1_w    = (const float*)d_in[17];
    const float* gcn_w1    = (const float*)d_in[18];
    const float* gcn_b1    = (const float*)d_in[19];
    const float* gcn_w2    = (const float*)d_in[20];
    const float* gcn_b2    = (const float*)d_in[21];
    const float* att_w     = (const float*)d_in[22];
    const float* att_b     = (const float*)d_in[23];
    const float* att_vec   = (const float*)d_in[24];
    const float* proj_w    = (const float*)d_in[25];
    const float* proj_b    = (const float*)d_in[26];
    const float* mlp1_w    = (const float*)d_in[27];
    const float* mlp1_b    = (const float*)d_in[28];
    const float* mlp2_w    = (const float*)d_in[29];
    const float* mlp2_b    = (const float*)d_in[30];

    float* h_tar  = devptr(g_h_tar);
    float* h_mask = devptr(g_h_mask);
    float* h_nei0 = devptr(g_h_nei0);
    float* h_nei1 = devptr(g_h_nei1);
    float* xw_all = devptr(g_xw_all);
    float* hw_all = devptr(g_hw_all);
    float* z_all  = devptr(g_z_all);
    float* epart  = devptr(g_epart);
    float* beta   = devptr(g_beta);
    float* zfine  = devptr(g_zfine);
    float* z2     = devptr(g_z2);
    float* Uf     = devptr(g_Uf);
    float* Uc     = devptr(g_Uc);
    float* diag   = devptr(g_diag);
    float* part   = devptr(g_part);

    bf16 *f0h = devptrb(g_feat0_h), *f0l = devptrb(g_feat0_l);
    bf16 *mkh = devptrb(g_mask_h),  *mkl = devptrb(g_mask_l);
    bf16 *f1h = devptrb(g_feat1_h), *f1l = devptrb(g_feat1_l);
    bf16 *f2h = devptrb(g_feat2_h), *f2l = devptrb(g_feat2_l);
    bf16 *w0h = devptrb(g_fc0w_h),  *w0l = devptrb(g_fc0w_l);
    bf16 *w1h = devptrb(g_fc1w_h),  *w1l = devptrb(g_fc1w_l);
    bf16 *w2h = devptrb(g_fc2w_h),  *w2l = devptrb(g_fc2w_l);
    bf16 *a0h = devptrb(g_ag0w_h),  *a0l = devptrb(g_ag0w_l);
    bf16 *a1h = devptrb(g_ag1w_h),  *a1l = devptrb(g_ag1w_l);
    bf16 *gw1h = devptrb(g_w1_h),   *gw1l = devptrb(g_w1_l);
    bf16 *gw2h = devptrb(g_w2_h),   *gw2l = devptrb(g_w2_l);
    bf16 *g0h = devptrb(g_agg0_h),  *g0l = devptrb(g_agg0_l);
    bf16 *g1h = devptrb(g_agg1_h),  *g1l = devptrb(g_agg1_l);
    bf16 *X5h = devptrb(g_X5h),     *X5l = devptrb(g_X5l);
    bf16 *h1bh = devptrb(g_h1b_h),  *h1bl = devptrb(g_h1b_l);

    const int NE = Ndim * Edim;
    const int NH = Ndim * Hdim;

    // ---- CSR build (all 7 sparse operands, one launch) ----
    csr_build_kernel<<<dim3(Ndim, 7), 128>>>(adj0, adj1, madj0, madj1, nei0, nei1);

    // ---- split all static fp32 operands into bf16 hi/lo planes ----
    {
        SJobs js;
        js.j[0]  = { feat0,     f0h, f0l, (Ndim*D0)/4 };
        js.j[1]  = { mask_feat, mkh, mkl, (Ndim*D0)/4 };
        js.j[2]  = { feat1,     f1h, f1l, (Mdim*D1)/4 };
        js.j[3]  = { feat2,     f2h, f2l, (Mdim*D1)/4 };
        js.j[4]  = { fc0_w,     w0h, w0l, (D0*Hdim)/4 };
        js.j[5]  = { fc1_w,     w1h, w1l, (D1*Hdim)/4 };
        js.j[6]  = { fc2_w,     w2h, w2l, (D1*Hdim)/4 };
        js.j[7]  = { agg0_w,    a0h, a0l, (Hdim*Hdim)/4 };
        js.j[8]  = { agg1_w,    a1h, a1l, (Hdim*Hdim)/4 };
        js.j[9]  = { gcn_w1,    gw1h, gw1l, (Hdim*Edim)/4 };
        js.j[10] = { gcn_w2,    gw2h, gw2l, (Edim*Edim)/4 };
        split_kernel<<<dim3(128, 11), 256>>>(js);
    }

    // ---- encoders via HMMA (MT=2, 640 blocks); seg0 also emits X5 slice0 ----
    {
        SegsH sgs;
        sgs.nseg = 4;
        sgs.s[0] = { f0h, f0l, w0h, w0l, fc0_b, h_tar,  X5h, X5l, nullptr, nullptr, D0, 16  };
        sgs.s[1] = { mkh, mkl, w0h, w0l, fc0_b, h_mask, nullptr, nullptr, nullptr, nullptr, D0, 32 };
        sgs.s[2] = { f1h, f1l, w1h, w1l, fc1_b, h_nei0, nullptr, nullptr, nullptr, nullptr, D1, 96 };
        sgs.s[3] = { f2h, f2l, w2h, w2l, fc2_b, h_nei1, nullptr, nullptr, nullptr, nullptr, D1, 160 };
        hmma_gemm<1,2><<<dim3(Hdim/128, 160), 256>>>(sgs, Hdim, nullptr, nullptr);
    }

    // ---- neighbor mean aggregation (CSR gather, both matrices) ----
    spmm2_gather_kernel<<<dim3(Ndim, 2), 256>>>(h_nei0, h_nei1, g0h, g0l, g1h, g1l);

    // ---- agg GEMMs (HMMA MT=1, 256 blocks): emit views/masks planes into X5 ----
    {
        SegsH sgs;
        sgs.nseg = 2;
        sgs.s[0] = { g0h, g0l, a0h, a0l, nullptr, nullptr,
                     X5h + 1*NH, X5l + 1*NH, X5h + 2*NH, X5l + 2*NH, Hdim, 32 };
        sgs.s[1] = { g1h, g1l, a1h, a1l, nullptr, nullptr,
                     X5h + 3*NH, X5l + 3*NH, X5h + 4*NH, X5l + 4*NH, Hdim, 64 };
        sgs.s[2] = sgs.s[1]; sgs.s[3] = sgs.s[1];
        hmma_gemm<2,1><<<dim3(Hdim/128, 64), 256>>>(sgs, Hdim, h_tar, h_mask);
    }

    // ---- GCN stage A: xw = X5 @ gcn_w1 (stacked HMMA, M=5120, K=512) ----
    hmma_gemm64<<<5*Ndim/64, 256>>>(X5h, X5l, gw1h, gw1l, xw_all, Hdim);

    // ---- GCN stage B: h1 = relu(adj @ xw + b1) -> bf16 planes (CSR gather) ----
    gcn_gather_kernel<<<dim3(Ndim, 5), 64>>>(xw_all, gcn_b1, nullptr, h1bh, h1bl, 1, 0, 1);

    // ---- GCN stage C: hw = h1 @ gcn_w2 (stacked HMMA, M=5120, K=64) ----
    hmma_gemm64<<<5*Ndim/64, 256>>>(h1bh, h1bl, gw2h, gw2l, hw_all, Edim);

    // ---- GCN stage D: z = adj @ hw + b2, fused l2norm for views (CSR gather) ----
    gcn_gather_kernel<<<dim3(Ndim, 5), 64>>>(hw_all, gcn_b2, z_all, nullptr, nullptr, 0, 1, 0);

    // ---- semantic attention over (already normalized) hs, z_fine ----
    float* hs = z_all + NE;
    att_kernel<<<dim3(4,4), 256>>>(hs, att_w, att_b, att_vec, epart);
    beta_kernel<<<1, 1>>>(epart, beta);
    zfine_kernel<<<(NE + 255)/256, 256>>>(hs, beta, zfine, NE);

    // ---- projections with fused tanh + L2 norm ----
    {
        In5 ins = {{ z_all, zfine, zfine, zfine, zfine }};
        gemm_small<4><<<2*32, 128>>>(ins, proj_w, proj_b, z2, Edim, 32);
    }
    float* zc = z2;
    float* zf = z2 + NE;

    // ---- weighted InfoNCE ----
    u_diag_kernel<<<Ndim/16, 256>>>(zf, zc, mlp1_w, mlp1_b, Uf, Uc, diag);
    pair_kernel<<<dim3(64, 64), 256>>>(zf, zc, Uf, Uc, mlp2_w, mlp2_b, part);
    loss_kernel<<<1, 256>>>(part, diag, (float*)d_out);
}